// round 7
// baseline (speedup 1.0000x reference)
#include <cuda_runtime.h>
#include <cstdint>
#include <cstddef>

#define NVN 50000
#define NCN 20000
#define HD  256
#define NLAYER 4
#define EVVN 500000
#define EVCN 300000
#define GN  64

#define ASTRIDE 20
#define BSTRIDE 72
#define NSTAGE 3
#define SMEM_FLOATS (NSTAGE*128*ASTRIDE*2 + NSTAGE*16*BSTRIDE*2)
#define SMEM_BYTES  (SMEM_FLOATS*4)

// ---------------- scratch ----------------
__device__ __align__(128) float g_XV0[NVN * HD];
__device__ __align__(128) float g_XV1[NVN * HD];
__device__ __align__(128) float g_XC0[NCN * HD];
__device__ __align__(128) float g_XC1[NCN * HD];
__device__ __align__(128) float g_XL0[NVN * HD];
__device__ __align__(128) float g_XL1[NVN * HD];
__device__ __align__(128) float g_XL2[NVN * HD];
__device__ __align__(128) float g_XL3[NCN * HD];

__device__ __align__(128) float g_AhV[NVN * HD];
__device__ __align__(128) float g_AlV[NVN * HD];
__device__ __align__(128) float g_AhC[NCN * HD];
__device__ __align__(128) float g_AlC[NCN * HD];
__device__ __align__(128) float g_Wh[16 * HD * HD];
__device__ __align__(128) float g_Wl[16 * HD * HD];

// double-buffered attention scalars: [parity][node]
__device__ float g_AS0[2 * NVN], g_AD0[2 * NVN];
__device__ float g_AS1[2 * NVN], g_AD1[2 * NVN];
__device__ float g_AS2[2 * NVN], g_AD3[2 * NVN];
__device__ float g_AS3[2 * NCN], g_AD2[2 * NCN];

__device__ __align__(128) float g_WS[16 * HD];
__device__ __align__(128) float g_WD[16 * HD];

__device__ int g_RP0[NVN + 1], g_RP1[NVN + 1], g_RP3[NVN + 1], g_RP2[NCN + 1];
__device__ int g_CU0[NVN], g_CU1[NVN], g_CU3[NVN], g_CU2[NCN];
__device__ int g_CS0[EVVN], g_CS1[EVVN], g_CS3[EVCN], g_CS2[EVCN];

__device__ __align__(128) float g_VP[GN * HD];
__device__ __align__(128) float g_CP[GN * HD];
__device__ int   g_CNT[2 * GN];

// ---------------- helpers ----------------
__device__ __forceinline__ void red4(float* p, float4 v) {
    asm volatile("red.global.add.v4.f32 [%0], {%1,%2,%3,%4};"
                 :: "l"(p), "f"(v.x), "f"(v.y), "f"(v.z), "f"(v.w) : "memory");
}
__device__ __forceinline__ void tf32split(float x, float& hi, float& lo) {
    uint32_t hb, lb;
    asm("cvt.rna.tf32.f32 %0, %1;" : "=r"(hb) : "f"(x));
    float hf = __uint_as_float(hb);
    float r = x - hf;
    asm("cvt.rna.tf32.f32 %0, %1;" : "=r"(lb) : "f"(r));
    hi = hf;
    lo = __uint_as_float(lb);
}
__device__ __forceinline__ void ldsm4(uint32_t* r, const float* p) {
    uint32_t addr = (uint32_t)__cvta_generic_to_shared(p);
    asm volatile("ldmatrix.sync.aligned.m8n8.x4.shared.b16 {%0,%1,%2,%3}, [%4];"
                 : "=r"(r[0]), "=r"(r[1]), "=r"(r[2]), "=r"(r[3]) : "r"(addr));
}
__device__ __forceinline__ void mma_tf32(float* c, const uint32_t* a, const uint32_t* b) {
    asm volatile(
        "mma.sync.aligned.m16n8k8.row.col.f32.tf32.tf32.f32 "
        "{%0,%1,%2,%3}, {%4,%5,%6,%7}, {%8,%9}, {%0,%1,%2,%3};"
        : "+f"(c[0]), "+f"(c[1]), "+f"(c[2]), "+f"(c[3])
        : "r"(a[0]), "r"(a[1]), "r"(a[2]), "r"(a[3]), "r"(b[0]), "r"(b[1]));
}
__device__ __forceinline__ void cpa16(float* dst, const float* src, bool valid) {
    uint32_t d = (uint32_t)__cvta_generic_to_shared(dst);
    int sz = valid ? 16 : 0;
    asm volatile("cp.async.ca.shared.global [%0], [%1], 16, %2;"
                 :: "r"(d), "l"(src), "r"(sz));
}
__device__ __forceinline__ float d4(float4 a, float4 b) {
    return a.x * b.x + a.y * b.y + a.z * b.z + a.w * b.w;
}

// ---------------- ws/wd precompute ----------------
__global__ void wsd_kernel(const float* __restrict__ Wsrc, const float* __restrict__ Wdst,
                           const float* __restrict__ as, const float* __restrict__ ad) {
    int b = blockIdx.x;
    int i = threadIdx.x;
    __shared__ float sas[HD], sad[HD];
    sas[i] = as[b * HD + i];
    sad[i] = ad[b * HD + i];
    __syncthreads();
    const float* Ws = Wsrc + (size_t)b * HD * HD + (size_t)i * HD;
    const float* Wd = Wdst + (size_t)b * HD * HD + (size_t)i * HD;
    float s = 0.f, d = 0.f;
    #pragma unroll 8
    for (int j = 0; j < HD; j++) { s += Ws[j] * sas[j]; d += Wd[j] * sad[j]; }
    g_WS[b * HD + i] = s;
    g_WD[b * HD + i] = d;
}

// ---------------- tf32 split (elementwise) ----------------
__global__ void split_kernel(const float* __restrict__ X, float* __restrict__ Xh,
                             float* __restrict__ Xl, int n4) {
    int i = blockIdx.x * blockDim.x + threadIdx.x;
    if (i >= n4) return;
    float4 v = ((const float4*)X)[i];
    float4 h, l;
    tf32split(v.x, h.x, l.x);
    tf32split(v.y, h.y, l.y);
    tf32split(v.z, h.z, l.z);
    tf32split(v.w, h.w, l.w);
    ((float4*)Xh)[i] = h;
    ((float4*)Xl)[i] = l;
}

// ---------------- tf32x3 GEMM, 3-stage cp.async pipeline ----------------
__global__ __launch_bounds__(256) void gemm_split_kernel(
        const float* __restrict__ Ah, const float* __restrict__ Al,
        const float* __restrict__ Whb, const float* __restrict__ Wlb,
        float* __restrict__ C0, float* __restrict__ C1, float* __restrict__ C2,
        int N) {
    extern __shared__ float sm[];
    float* pAh = sm;
    float* pAl = pAh + NSTAGE * 128 * ASTRIDE;
    float* pBh = pAl + NSTAGE * 128 * ASTRIDE;
    float* pBl = pBh + NSTAGE * 16 * BSTRIDE;

    const int tid = threadIdx.x;
    const int lane = tid & 31;
    const int wid = tid >> 5;
    const int wm = (wid & 3) * 32;
    const int wn = (wid >> 2) * 32;
    const int row0 = blockIdx.x * 128;
    const int mat = blockIdx.y >> 2;
    const int col0 = (blockIdx.y & 3) * 64;
    const float* W_h = Whb + (size_t)mat * HD * HD;
    const float* W_l = Wlb + (size_t)mat * HD * HD;
    float* C = (mat == 0) ? C0 : (mat == 1) ? C1 : C2;

    const int arow = tid >> 1;
    const int acol = (tid & 1) * 8;
    const int brow = tid >> 4;
    const int bcol = (tid & 15) * 4;

    float acc[2][4][4];
    #pragma unroll
    for (int i = 0; i < 2; i++)
        #pragma unroll
        for (int j = 0; j < 4; j++)
            #pragma unroll
            for (int q = 0; q < 4; q++) acc[i][j][q] = 0.f;

    const int g = lane >> 2, t4 = lane & 3;
    const int lrow = (lane & 7) + ((lane >> 3) & 1) * 8;
    const int lcol = (lane >> 4) << 2;

    auto load_stage = [&](int s, int k0) {
        bool v = (row0 + arow) < N;
        const float* asrc_h = v ? (Ah + (size_t)(row0 + arow) * HD + k0 + acol) : Ah;
        const float* asrc_l = v ? (Al + (size_t)(row0 + arow) * HD + k0 + acol) : Al;
        float* adst_h = pAh + s * 128 * ASTRIDE + arow * ASTRIDE + acol;
        float* adst_l = pAl + s * 128 * ASTRIDE + arow * ASTRIDE + acol;
        cpa16(adst_h,     asrc_h,     v);
        cpa16(adst_h + 4, asrc_h + 4, v);
        cpa16(adst_l,     asrc_l,     v);
        cpa16(adst_l + 4, asrc_l + 4, v);
        cpa16(pBh + s * 16 * BSTRIDE + brow * BSTRIDE + bcol,
              W_h + (size_t)(k0 + brow) * HD + col0 + bcol, true);
        cpa16(pBl + s * 16 * BSTRIDE + brow * BSTRIDE + bcol,
              W_l + (size_t)(k0 + brow) * HD + col0 + bcol, true);
        asm volatile("cp.async.commit_group;");
    };

    load_stage(0, 0);
    load_stage(1, 16);

    for (int kt = 0; kt < 16; kt++) {
        if (kt + 2 < 16) {
            asm volatile("cp.async.wait_group 1;");
        } else {
            asm volatile("cp.async.wait_group 0;");
        }
        __syncthreads();
        if (kt + 2 < 16) load_stage((kt + 2) % NSTAGE, (kt + 2) * 16);

        const int cur = kt % NSTAGE;
        const float* cAh = pAh + cur * 128 * ASTRIDE;
        const float* cAl = pAl + cur * 128 * ASTRIDE;
        const float* cBh = pBh + cur * 16 * BSTRIDE;
        const float* cBl = pBl + cur * 16 * BSTRIDE;

        #pragma unroll
        for (int kk = 0; kk < 2; kk++) {
            const int kb = kk * 8;
            uint32_t ah[2][4], al[2][4];
            #pragma unroll
            for (int i = 0; i < 2; i++) {
                int base = wm + i * 16;
                ldsm4(ah[i], cAh + (base + lrow) * ASTRIDE + kb + lcol);
                ldsm4(al[i], cAl + (base + lrow) * ASTRIDE + kb + lcol);
            }
            uint32_t bh[4][2], bl[4][2];
            #pragma unroll
            for (int j = 0; j < 4; j++) {
                int n = wn + j * 8 + g;
                bh[j][0] = __float_as_uint(cBh[(kb + t4) * BSTRIDE + n]);
                bh[j][1] = __float_as_uint(cBh[(kb + t4 + 4) * BSTRIDE + n]);
                bl[j][0] = __float_as_uint(cBl[(kb + t4) * BSTRIDE + n]);
                bl[j][1] = __float_as_uint(cBl[(kb + t4 + 4) * BSTRIDE + n]);
            }
            #pragma unroll
            for (int i = 0; i < 2; i++)
                #pragma unroll
                for (int j = 0; j < 4; j++) {
                    mma_tf32(acc[i][j], ah[i], bh[j]);
                    mma_tf32(acc[i][j], ah[i], bl[j]);
                    mma_tf32(acc[i][j], al[i], bh[j]);
                }
        }
    }

    #pragma unroll
    for (int i = 0; i < 2; i++) {
        int r0 = row0 + wm + i * 16 + g;
        #pragma unroll
        for (int j = 0; j < 4; j++) {
            int c = col0 + wn + j * 8 + t4 * 2;
            if (r0 < N)
                *(float2*)(C + (size_t)r0 * HD + c) = make_float2(acc[i][j][0], acc[i][j][1]);
            if (r0 + 8 < N)
                *(float2*)(C + (size_t)(r0 + 8) * HD + c) = make_float2(acc[i][j][2], acc[i][j][3]);
        }
    }
}

// ---------------- standalone attention dots (layer 0 only) ----------------
__global__ void avec_var_kernel(const float* __restrict__ xv) {
    __shared__ float sv[6][HD];
    int t = threadIdx.x;
    sv[0][t] = g_WS[0 * HD + t];
    sv[1][t] = g_WD[0 * HD + t];
    sv[2][t] = g_WS[1 * HD + t];
    sv[3][t] = g_WD[1 * HD + t];
    sv[4][t] = g_WS[2 * HD + t];
    sv[5][t] = g_WD[3 * HD + t];
    __syncthreads();
    int w = (blockIdx.x * blockDim.x + t) >> 5;
    int lane = t & 31;
    if (w >= NVN) return;
    const float* row = xv + (size_t)w * HD;
    float s[6] = {0, 0, 0, 0, 0, 0};
    #pragma unroll
    for (int j0 = 0; j0 < HD; j0 += 32) {
        float x = row[j0 + lane];
        #pragma unroll
        for (int k = 0; k < 6; k++) s[k] += x * sv[k][j0 + lane];
    }
    #pragma unroll
    for (int k = 0; k < 6; k++)
        #pragma unroll
        for (int o = 16; o > 0; o >>= 1) s[k] += __shfl_xor_sync(0xffffffffu, s[k], o);
    if (lane == 0) {
        g_AS0[w] = s[0]; g_AD0[w] = s[1];
        g_AS1[w] = s[2]; g_AD1[w] = s[3];
        g_AS2[w] = s[4]; g_AD3[w] = s[5];
    }
}

__global__ void avec_con_kernel(const float* __restrict__ xc) {
    __shared__ float sv[2][HD];
    int t = threadIdx.x;
    sv[0][t] = g_WD[2 * HD + t];
    sv[1][t] = g_WS[3 * HD + t];
    __syncthreads();
    int w = (blockIdx.x * blockDim.x + t) >> 5;
    int lane = t & 31;
    if (w >= NCN) return;
    const float* row = xc + (size_t)w * HD;
    float s0 = 0.f, s1 = 0.f;
    #pragma unroll
    for (int j0 = 0; j0 < HD; j0 += 32) {
        float x = row[j0 + lane];
        s0 += x * sv[0][j0 + lane];
        s1 += x * sv[1][j0 + lane];
    }
    #pragma unroll
    for (int o = 16; o > 0; o >>= 1) {
        s0 += __shfl_xor_sync(0xffffffffu, s0, o);
        s1 += __shfl_xor_sync(0xffffffffu, s1, o);
    }
    if (lane == 0) { g_AD2[w] = s0; g_AS3[w] = s1; }
}

// ---------------- CSR build ----------------
__global__ void zero_int_kernel(int* __restrict__ p, int n) {
    int i = blockIdx.x * blockDim.x + threadIdx.x;
    if (i < n) p[i] = 0;
}
__global__ void hist_kernel(const int* __restrict__ dst, int* __restrict__ cnt, int E) {
    int i = blockIdx.x * blockDim.x + threadIdx.x;
    if (i < E) atomicAdd(&cnt[dst[i]], 1);
}
__global__ void scan_kernel(int* __restrict__ rp, int* __restrict__ cursor, int n) {
    __shared__ int swarp[32];
    __shared__ int stot;
    int t = threadIdx.x, w = t >> 5, lane = t & 31;
    int carry = 0;
    for (int base = 0; base < n; base += 1024) {
        int idx = base + t;
        int v = (idx < n) ? rp[idx] : 0;
        int x = v;
        #pragma unroll
        for (int o = 1; o < 32; o <<= 1) {
            int y = __shfl_up_sync(0xffffffffu, x, o);
            if (lane >= o) x += y;
        }
        if (lane == 31) swarp[w] = x;
        __syncthreads();
        if (w == 0) {
            int s = swarp[lane];
            int z = s;
            #pragma unroll
            for (int o = 1; o < 32; o <<= 1) {
                int y = __shfl_up_sync(0xffffffffu, z, o);
                if (lane >= o) z += y;
            }
            swarp[lane] = z - s;
            if (lane == 31) stot = z;
        }
        __syncthreads();
        int excl = carry + swarp[w] + (x - v);
        if (idx < n) { rp[idx] = excl; cursor[idx] = excl; }
        carry += stot;
        __syncthreads();
    }
    if (t == 0) rp[n] = carry;
}
__global__ void scatter_kernel(const int* __restrict__ src, const int* __restrict__ dst,
                               int* __restrict__ cursor, int* __restrict__ cs, int E) {
    int i = blockIdx.x * blockDim.x + threadIdx.x;
    if (i >= E) return;
    int pos = atomicAdd(&cursor[dst[i]], 1);
    cs[pos] = src[i];
}

// ---------------- fused GAT ----------------
__device__ __forceinline__ void gat_accum(
        int d, int lane,
        const int* __restrict__ rp, const int* __restrict__ cs,
        const float* __restrict__ AS, const float* __restrict__ AD,
        const float* __restrict__ XL,
        float4& acc0, float4& acc1) {
    int off = rp[d];
    int deg = rp[d + 1] - off;
    if (deg <= 0) return;
    float adv = AD[d];
    float m = -1e30f;
    for (int j = lane; j < deg; j += 32) {
        int s = cs[off + j];
        float e = AS[s] + adv;
        e = (e >= 0.f) ? e : 0.2f * e;
        m = fmaxf(m, e);
    }
    #pragma unroll
    for (int o = 16; o > 0; o >>= 1) m = fmaxf(m, __shfl_xor_sync(0xffffffffu, m, o));
    float den = 0.f;
    for (int j = lane; j < deg; j += 32) {
        int s = cs[off + j];
        float e = AS[s] + adv;
        e = (e >= 0.f) ? e : 0.2f * e;
        den += __expf(e - m);
    }
    #pragma unroll
    for (int o = 16; o > 0; o >>= 1) den += __shfl_xor_sync(0xffffffffu, den, o);
    float invden = 1.f / (den + 1e-16f);
    for (int c = 0; c < deg; c += 32) {
        int j = c + lane;
        int s = 0;
        float wgt = 0.f;
        if (j < deg) {
            s = cs[off + j];
            float e = AS[s] + adv;
            e = (e >= 0.f) ? e : 0.2f * e;
            wgt = __expf(e - m) * invden;
        }
        int cnt = min(32, deg - c);
        for (int jj = 0; jj < cnt; jj++) {
            float wj = __shfl_sync(0xffffffffu, wgt, jj);
            int   sj = __shfl_sync(0xffffffffu, s, jj);
            const float4* xs = (const float4*)(XL + (size_t)sj * HD);
            float4 v0 = xs[lane];
            float4 v1 = xs[32 + lane];
            acc0.x += wj * v0.x; acc0.y += wj * v0.y; acc0.z += wj * v0.z; acc0.w += wj * v0.w;
            acc1.x += wj * v1.x; acc1.y += wj * v1.y; acc1.z += wj * v1.z; acc1.w += wj * v1.w;
        }
    }
}

__device__ __forceinline__ void split_store(float* outh, float* outl, int w, int lane,
                                            float4 acc0, float4 acc1) {
    float4 h0, l0, h1, l1;
    tf32split(acc0.x, h0.x, l0.x); tf32split(acc0.y, h0.y, l0.y);
    tf32split(acc0.z, h0.z, l0.z); tf32split(acc0.w, h0.w, l0.w);
    tf32split(acc1.x, h1.x, l1.x); tf32split(acc1.y, h1.y, l1.y);
    tf32split(acc1.z, h1.z, l1.z); tf32split(acc1.w, h1.w, l1.w);
    float4* oh = (float4*)(outh + (size_t)w * HD);
    float4* ol = (float4*)(outl + (size_t)w * HD);
    oh[lane] = h0; oh[32 + lane] = h1;
    ol[lane] = l0; ol[32 + lane] = l1;
}

__global__ void gat_var_kernel(const float* __restrict__ XL0, const float* __restrict__ XL1,
                               const float* __restrict__ XL3,
                               const float* __restrict__ bias, int l,
                               float* __restrict__ out,
                               float* __restrict__ outh, float* __restrict__ outl,
                               int do_next) {
    int w = (blockIdx.x * blockDim.x + threadIdx.x) >> 5;
    int lane = threadIdx.x & 31;
    if (w >= NVN) return;
    int rv = (l & 1) * NVN, rc = (l & 1) * NCN;
    float4 acc0 = make_float4(0.f, 0.f, 0.f, 0.f);
    float4 acc1 = make_float4(0.f, 0.f, 0.f, 0.f);
    gat_accum(w, lane, g_RP0, g_CS0, g_AS0 + rv, g_AD0 + rv, XL0, acc0, acc1);
    gat_accum(w, lane, g_RP1, g_CS1, g_AS1 + rv, g_AD1 + rv, XL1, acc0, acc1);
    gat_accum(w, lane, g_RP3, g_CS3, g_AS3 + rc, g_AD3 + rv, XL3, acc0, acc1);
    const float4* b0 = (const float4*)(bias + (size_t)(4 * l + 0) * HD);
    const float4* b1 = (const float4*)(bias + (size_t)(4 * l + 1) * HD);
    const float4* b3 = (const float4*)(bias + (size_t)(4 * l + 3) * HD);
    float4 x0 = b0[lane], y0 = b1[lane], z0 = b3[lane];
    float4 x1 = b0[32 + lane], y1 = b1[32 + lane], z1 = b3[32 + lane];
    acc0.x += x0.x + y0.x + z0.x; acc0.y += x0.y + y0.y + z0.y;
    acc0.z += x0.z + y0.z + z0.z; acc0.w += x0.w + y0.w + z0.w;
    acc1.x += x1.x + y1.x + z1.x; acc1.y += x1.y + y1.y + z1.y;
    acc1.z += x1.z + y1.z + z1.z; acc1.w += x1.w + y1.w + z1.w;
    float4* ob = (float4*)(out + (size_t)w * HD);
    ob[lane] = acc0;
    ob[32 + lane] = acc1;
    if (!do_next) return;
    split_store(outh, outl, w, lane, acc0, acc1);
    // next-layer attention dots
    int L = l + 1;
    int wv = ((l + 1) & 1) * NVN;
    float s[6];
    const int vidx[6] = {0, 0, 1, 1, 2, 3};
    #pragma unroll
    for (int k = 0; k < 6; k++) {
        const float* vecb = (k == 1 || k == 3 || k == 5) ? g_WD : g_WS;
        const float4* vp = (const float4*)(vecb + (size_t)(4 * L + vidx[k]) * HD);
        s[k] = d4(acc0, vp[lane]) + d4(acc1, vp[32 + lane]);
    }
    #pragma unroll
    for (int k = 0; k < 6; k++)
        #pragma unroll
        for (int o = 16; o > 0; o >>= 1) s[k] += __shfl_xor_sync(0xffffffffu, s[k], o);
    if (lane == 0) {
        g_AS0[wv + w] = s[0]; g_AD0[wv + w] = s[1];
        g_AS1[wv + w] = s[2]; g_AD1[wv + w] = s[3];
        g_AS2[wv + w] = s[4]; g_AD3[wv + w] = s[5];
    }
}

__global__ void gat_con_kernel(const float* __restrict__ XL2,
                               const float* __restrict__ bias, int l,
                               float* __restrict__ out,
                               float* __restrict__ outh, float* __restrict__ outl,
                               int do_next) {
    int w = (blockIdx.x * blockDim.x + threadIdx.x) >> 5;
    int lane = threadIdx.x & 31;
    if (w >= NCN) return;
    int rc = (l & 1) * NCN;
    float4 acc0 = make_float4(0.f, 0.f, 0.f, 0.f);
    float4 acc1 = make_float4(0.f, 0.f, 0.f, 0.f);
    gat_accum(w, lane, g_RP2, g_CS2, g_AS2 + (l & 1) * NVN, g_AD2 + rc, XL2, acc0, acc1);
    const float4* b2 = (const float4*)(bias + (size_t)(4 * l + 2) * HD);
    float4 x0 = b2[lane], x1 = b2[32 + lane];
    acc0.x += x0.x; acc0.y += x0.y; acc0.z += x0.z; acc0.w += x0.w;
    acc1.x += x1.x; acc1.y += x1.y; acc1.z += x1.z; acc1.w += x1.w;
    float4* ob = (float4*)(out + (size_t)w * HD);
    ob[lane] = acc0;
    ob[32 + lane] = acc1;
    if (!do_next) return;
    split_store(outh, outl, w, lane, acc0, acc1);
    int L = l + 1;
    int wc = ((l + 1) & 1) * NCN;
    const float4* v0 = (const float4*)(g_WD + (size_t)(4 * L + 2) * HD);
    const float4* v1 = (const float4*)(g_WS + (size_t)(4 * L + 3) * HD);
    float s0 = d4(acc0, v0[lane]) + d4(acc1, v0[32 + lane]);
    float s1 = d4(acc0, v1[lane]) + d4(acc1, v1[32 + lane]);
    #pragma unroll
    for (int o = 16; o > 0; o >>= 1) {
        s0 += __shfl_xor_sync(0xffffffffu, s0, o);
        s1 += __shfl_xor_sync(0xffffffffu, s1, o);
    }
    if (lane == 0) { g_AD2[wc + w] = s0; g_AS3[wc + w] = s1; }
}

// ---------------- pooling + head ----------------
__global__ void zero_pool_kernel() {
    int i = blockIdx.x * 256 + threadIdx.x;
    g_VP[i] = 0.f;
    g_CP[i] = 0.f;
    if (i < 2 * GN) g_CNT[i] = 0;
}

__global__ void pool_kernel(const float* __restrict__ X, const int* __restrict__ batch,
                            int N, float* __restrict__ S, int* __restrict__ cnt) {
    int w = (blockIdx.x * blockDim.x + threadIdx.x) >> 5;
    int lane = threadIdx.x & 31;
    if (w >= N) return;
    int g = batch[w];
    if (lane == 0) atomicAdd(&cnt[g], 1);
    const float4* xr = (const float4*)(X + (size_t)w * HD);
    float* sb = S + (size_t)g * HD;
    #pragma unroll
    for (int j = 0; j < 2; j++) {
        int idx = lane + 32 * j;
        red4(sb + 4 * idx, xr[idx]);
    }
}

__global__ void finalize_kernel(const float* __restrict__ Wlin, const float* __restrict__ blin,
                                float* __restrict__ out) {
    int g = blockIdx.x, t = threadIdx.x;
    float cv = (float)max(g_CNT[g], 1);
    float cc = (float)max(g_CNT[GN + g], 1);
    float a = g_VP[g * HD + t] / cv;
    float c = g_CP[g * HD + t] / cc;
    float p0 = a * Wlin[t * 2 + 0] + c * Wlin[(HD + t) * 2 + 0];
    float p1 = a * Wlin[t * 2 + 1] + c * Wlin[(HD + t) * 2 + 1];
    __shared__ float s0[256], s1[256];
    s0[t] = p0; s1[t] = p1;
    __syncthreads();
    for (int o = 128; o > 0; o >>= 1) {
        if (t < o) { s0[t] += s0[t + o]; s1[t] += s1[t + o]; }
        __syncthreads();
    }
    if (t == 0) {
        float z0 = s0[0] + blin[0], z1 = s1[0] + blin[1];
        float m = fmaxf(z0, z1);
        float e0 = expf(z0 - m), e1 = expf(z1 - m);
        float inv = 1.f / (e0 + e1);
        out[2 * g + 0] = e0 * inv;
        out[2 * g + 1] = e1 * inv;
    }
}

// ---------------- host ----------------
extern "C" void kernel_launch(void* const* d_in, const int* in_sizes, int n_in,
                              void* d_out, int out_size) {
    const float* x_var   = (const float*)d_in[0];
    const float* x_con   = (const float*)d_in[1];
    const float* W_src   = (const float*)d_in[2];
    const float* W_dst   = (const float*)d_in[3];
    const float* att_src = (const float*)d_in[4];
    const float* att_dst = (const float*)d_in[5];
    const float* bias    = (const float*)d_in[6];
    const float* W_lin   = (const float*)d_in[7];
    const float* b_lin   = (const float*)d_in[8];
    const int* e_vv      = (const int*)d_in[9];
    const int* e_vv_rev  = (const int*)d_in[10];
    const int* e_vc      = (const int*)d_in[11];
    const int* e_cv      = (const int*)d_in[12];
    const int* batch_var = (const int*)d_in[13];
    const int* batch_con = (const int*)d_in[14];
    float* out = (float*)d_out;

    float *pXV[2], *pXC[2], *pXL0, *pXL1, *pXL2, *pXL3, *pVP, *pCP;
    float *pAhV, *pAlV, *pAhC, *pAlC, *pWh, *pWl;
    int *pRP0, *pRP1, *pRP2, *pRP3, *pCU0, *pCU1, *pCU2, *pCU3;
    int *pCS0, *pCS1, *pCS2, *pCS3, *pCNT;
    cudaGetSymbolAddress((void**)&pXV[0], g_XV0);
    cudaGetSymbolAddress((void**)&pXV[1], g_XV1);
    cudaGetSymbolAddress((void**)&pXC[0], g_XC0);
    cudaGetSymbolAddress((void**)&pXC[1], g_XC1);
    cudaGetSymbolAddress((void**)&pXL0, g_XL0);
    cudaGetSymbolAddress((void**)&pXL1, g_XL1);
    cudaGetSymbolAddress((void**)&pXL2, g_XL2);
    cudaGetSymbolAddress((void**)&pXL3, g_XL3);
    cudaGetSymbolAddress((void**)&pAhV, g_AhV);
    cudaGetSymbolAddress((void**)&pAlV, g_AlV);
    cudaGetSymbolAddress((void**)&pAhC, g_AhC);
    cudaGetSymbolAddress((void**)&pAlC, g_AlC);
    cudaGetSymbolAddress((void**)&pWh, g_Wh);
    cudaGetSymbolAddress((void**)&pWl, g_Wl);
    cudaGetSymbolAddress((void**)&pRP0, g_RP0);
    cudaGetSymbolAddress((void**)&pRP1, g_RP1);
    cudaGetSymbolAddress((void**)&pRP2, g_RP2);
    cudaGetSymbolAddress((void**)&pRP3, g_RP3);
    cudaGetSymbolAddress((void**)&pCU0, g_CU0);
    cudaGetSymbolAddress((void**)&pCU1, g_CU1);
    cudaGetSymbolAddress((void**)&pCU2, g_CU2);
    cudaGetSymbolAddress((void**)&pCU3, g_CU3);
    cudaGetSymbolAddress((void**)&pCS0, g_CS0);
    cudaGetSymbolAddress((void**)&pCS1, g_CS1);
    cudaGetSymbolAddress((void**)&pCS2, g_CS2);
    cudaGetSymbolAddress((void**)&pCS3, g_CS3);
    cudaGetSymbolAddress((void**)&pVP, g_VP);
    cudaGetSymbolAddress((void**)&pCP, g_CP);
    cudaGetSymbolAddress((void**)&pCNT, g_CNT);

    cudaFuncSetAttribute(gemm_split_kernel,
                         cudaFuncAttributeMaxDynamicSharedMemorySize, SMEM_BYTES);

    const int EB = 256;

    wsd_kernel<<<16, 256>>>(W_src, W_dst, att_src, att_dst);
    split_kernel<<<(16 * HD * HD / 4 + EB - 1) / EB, EB>>>(W_src, pWh, pWl, 16 * HD * HD / 4);

    // CSR build (once per call)
    zero_int_kernel<<<(NVN + 1 + EB - 1) / EB, EB>>>(pRP0, NVN + 1);
    zero_int_kernel<<<(NVN + 1 + EB - 1) / EB, EB>>>(pRP1, NVN + 1);
    zero_int_kernel<<<(NVN + 1 + EB - 1) / EB, EB>>>(pRP3, NVN + 1);
    zero_int_kernel<<<(NCN + 1 + EB - 1) / EB, EB>>>(pRP2, NCN + 1);
    hist_kernel<<<(EVVN + EB - 1) / EB, EB>>>(e_vv + EVVN, pRP0, EVVN);
    hist_kernel<<<(EVVN + EB - 1) / EB, EB>>>(e_vv_rev + EVVN, pRP1, EVVN);
    hist_kernel<<<(EVCN + EB - 1) / EB, EB>>>(e_cv + EVCN, pRP3, EVCN);
    hist_kernel<<<(EVCN + EB - 1) / EB, EB>>>(e_vc + EVCN, pRP2, EVCN);
    scan_kernel<<<1, 1024>>>(pRP0, pCU0, NVN);
    scan_kernel<<<1, 1024>>>(pRP1, pCU1, NVN);
    scan_kernel<<<1, 1024>>>(pRP3, pCU3, NVN);
    scan_kernel<<<1, 1024>>>(pRP2, pCU2, NCN);
    scatter_kernel<<<(EVVN + EB - 1) / EB, EB>>>(e_vv, e_vv + EVVN, pCU0, pCS0, EVVN);
    scatter_kernel<<<(EVVN + EB - 1) / EB, EB>>>(e_vv_rev, e_vv_rev + EVVN, pCU1, pCS1, EVVN);
    scatter_kernel<<<(EVCN + EB - 1) / EB, EB>>>(e_cv, e_cv + EVCN, pCU3, pCS3, EVCN);
    scatter_kernel<<<(EVCN + EB - 1) / EB, EB>>>(e_vc, e_vc + EVCN, pCU2, pCS2, EVCN);

    // initial splits + layer-0 attention dots
    split_kernel<<<(NVN * HD / 4 + EB - 1) / EB, EB>>>(x_var, pAhV, pAlV, NVN * HD / 4);
    split_kernel<<<(NCN * HD / 4 + EB - 1) / EB, EB>>>(x_con, pAhC, pAlC, NCN * HD / 4);
    avec_var_kernel<<<(NVN * 32 + EB - 1) / EB, EB>>>(x_var);
    avec_con_kernel<<<(NCN * 32 + EB - 1) / EB, EB>>>(x_con);

    dim3 gemmGridV((NVN + 127) / 128, 12);
    dim3 gemmGridC((NCN + 127) / 128, 4);

    for (int l = 0; l < NLAYER; l++) {
        float* xv_out = pXV[l & 1];
        float* xc_out = pXC[l & 1];
        int do_next = (l + 1 < NLAYER) ? 1 : 0;

        gemm_split_kernel<<<gemmGridV, 256, SMEM_BYTES>>>(
            pAhV, pAlV, pWh + (size_t)(4 * l) * HD * HD, pWl + (size_t)(4 * l) * HD * HD,
            pXL0, pXL1, pXL2, NVN);
        gemm_split_kernel<<<gemmGridC, 256, SMEM_BYTES>>>(
            pAhC, pAlC, pWh + (size_t)(4 * l + 3) * HD * HD, pWl + (size_t)(4 * l + 3) * HD * HD,
            pXL3, pXL3, pXL3, NCN);

        gat_var_kernel<<<(NVN * 32 + EB - 1) / EB, EB>>>(pXL0, pXL1, pXL3, bias, l,
                                                         xv_out, pAhV, pAlV, do_next);
        gat_con_kernel<<<(NCN * 32 + EB - 1) / EB, EB>>>(pXL2, bias, l,
                                                         xc_out, pAhC, pAlC, do_next);
    }

    zero_pool_kernel<<<GN, 256>>>();
    pool_kernel<<<(NVN * 32 + EB - 1) / EB, EB>>>(pXV[(NLAYER - 1) & 1], batch_var, NVN, pVP, pCNT);
    pool_kernel<<<(NCN * 32 + EB - 1) / EB, EB>>>(pXC[(NLAYER - 1) & 1], batch_con, NCN, pCP, pCNT + GN);
    finalize_kernel<<<GN, 256>>>(W_lin, b_lin, out);
}

// round 8
// speedup vs baseline: 1.0150x; 1.0150x over previous
#include <cuda_runtime.h>
#include <cstdint>
#include <cstddef>

#define NVN 50000
#define NCN 20000
#define HD  256
#define NLAYER 4
#define EVVN 500000
#define EVCN 300000
#define GN  64

#define ASTRIDE 20
#define BSTRIDE 72
#define NSTAGE 3
#define SMEM_FLOATS (NSTAGE*128*ASTRIDE*2 + NSTAGE*16*BSTRIDE*2)
#define SMEM_BYTES  (SMEM_FLOATS*4)

// ---------------- scratch ----------------
__device__ __align__(128) float g_XV0[NVN * HD];
__device__ __align__(128) float g_XV1[NVN * HD];
__device__ __align__(128) float g_XC0[NCN * HD];
__device__ __align__(128) float g_XC1[NCN * HD];
__device__ __align__(128) float g_XL0[NVN * HD];
__device__ __align__(128) float g_XL1[NVN * HD];
__device__ __align__(128) float g_XL2[NVN * HD];
__device__ __align__(128) float g_XL3[NCN * HD];

__device__ __align__(128) float g_AhV[NVN * HD];
__device__ __align__(128) float g_AlV[NVN * HD];
__device__ __align__(128) float g_AhC[NCN * HD];
__device__ __align__(128) float g_AlC[NCN * HD];
__device__ __align__(128) float g_Wh[16 * HD * HD];
__device__ __align__(128) float g_Wl[16 * HD * HD];

// double-buffered attention scalars: [parity][node]
__device__ float g_AS0[2 * NVN], g_AD0[2 * NVN];
__device__ float g_AS1[2 * NVN], g_AD1[2 * NVN];
__device__ float g_AS2[2 * NVN], g_AD3[2 * NVN];
__device__ float g_AS3[2 * NCN], g_AD2[2 * NCN];

__device__ __align__(128) float g_WS[16 * HD];
__device__ __align__(128) float g_WD[16 * HD];

__device__ int g_RP0[NVN + 1], g_RP1[NVN + 1], g_RP3[NVN + 1], g_RP2[NCN + 1];
__device__ int g_CU0[NVN], g_CU1[NVN], g_CU3[NVN], g_CU2[NCN];
__device__ int g_CS0[EVVN], g_CS1[EVVN], g_CS3[EVCN], g_CS2[EVCN];

__device__ __align__(128) float g_VP[GN * HD];
__device__ __align__(128) float g_CP[GN * HD];
__device__ int   g_CNT[2 * GN];

// ---------------- helpers ----------------
__device__ __forceinline__ void red4(float* p, float4 v) {
    asm volatile("red.global.add.v4.f32 [%0], {%1,%2,%3,%4};"
                 :: "l"(p), "f"(v.x), "f"(v.y), "f"(v.z), "f"(v.w) : "memory");
}
__device__ __forceinline__ void tf32split(float x, float& hi, float& lo) {
    uint32_t hb, lb;
    asm("cvt.rna.tf32.f32 %0, %1;" : "=r"(hb) : "f"(x));
    float hf = __uint_as_float(hb);
    float r = x - hf;
    asm("cvt.rna.tf32.f32 %0, %1;" : "=r"(lb) : "f"(r));
    hi = hf;
    lo = __uint_as_float(lb);
}
__device__ __forceinline__ void ldsm4(uint32_t* r, const float* p) {
    uint32_t addr = (uint32_t)__cvta_generic_to_shared(p);
    asm volatile("ldmatrix.sync.aligned.m8n8.x4.shared.b16 {%0,%1,%2,%3}, [%4];"
                 : "=r"(r[0]), "=r"(r[1]), "=r"(r[2]), "=r"(r[3]) : "r"(addr));
}
__device__ __forceinline__ void mma_tf32(float* c, const uint32_t* a, const uint32_t* b) {
    asm volatile(
        "mma.sync.aligned.m16n8k8.row.col.f32.tf32.tf32.f32 "
        "{%0,%1,%2,%3}, {%4,%5,%6,%7}, {%8,%9}, {%0,%1,%2,%3};"
        : "+f"(c[0]), "+f"(c[1]), "+f"(c[2]), "+f"(c[3])
        : "r"(a[0]), "r"(a[1]), "r"(a[2]), "r"(a[3]), "r"(b[0]), "r"(b[1]));
}
__device__ __forceinline__ void cpa16(float* dst, const float* src, bool valid) {
    uint32_t d = (uint32_t)__cvta_generic_to_shared(dst);
    int sz = valid ? 16 : 0;
    asm volatile("cp.async.ca.shared.global [%0], [%1], 16, %2;"
                 :: "r"(d), "l"(src), "r"(sz));
}
__device__ __forceinline__ float d4(float4 a, float4 b) {
    return a.x * b.x + a.y * b.y + a.z * b.z + a.w * b.w;
}

// ---------------- ws/wd precompute ----------------
__global__ void wsd_kernel(const float* __restrict__ Wsrc, const float* __restrict__ Wdst,
                           const float* __restrict__ as, const float* __restrict__ ad) {
    int b = blockIdx.x;
    int i = threadIdx.x;
    __shared__ float sas[HD], sad[HD];
    sas[i] = as[b * HD + i];
    sad[i] = ad[b * HD + i];
    __syncthreads();
    const float* Ws = Wsrc + (size_t)b * HD * HD + (size_t)i * HD;
    const float* Wd = Wdst + (size_t)b * HD * HD + (size_t)i * HD;
    float s = 0.f, d = 0.f;
    #pragma unroll 8
    for (int j = 0; j < HD; j++) { s += Ws[j] * sas[j]; d += Wd[j] * sad[j]; }
    g_WS[b * HD + i] = s;
    g_WD[b * HD + i] = d;
}

// ---------------- tf32 split ----------------
__global__ void split_kernel(const float* __restrict__ X, float* __restrict__ Xh,
                             float* __restrict__ Xl, int n4) {
    int i = blockIdx.x * blockDim.x + threadIdx.x;
    if (i >= n4) return;
    float4 v = ((const float4*)X)[i];
    float4 h, l;
    tf32split(v.x, h.x, l.x);
    tf32split(v.y, h.y, l.y);
    tf32split(v.z, h.z, l.z);
    tf32split(v.w, h.w, l.w);
    ((float4*)Xh)[i] = h;
    ((float4*)Xl)[i] = l;
}

// ---------------- tf32x3 GEMM, 3-stage cp.async pipeline ----------------
// grid.y = 16: mats 0..2 -> var GEMMs (A=AhV/AlV, N=NVN), mat 3 -> con GEMM
__global__ __launch_bounds__(256, 2) void gemm_split_kernel(
        const float* __restrict__ AhV, const float* __restrict__ AlV,
        const float* __restrict__ AhC, const float* __restrict__ AlC,
        const float* __restrict__ Whb, const float* __restrict__ Wlb,
        float* __restrict__ C0, float* __restrict__ C1,
        float* __restrict__ C2, float* __restrict__ C3) {
    extern __shared__ float sm[];
    float* pAh = sm;
    float* pAl = pAh + NSTAGE * 128 * ASTRIDE;
    float* pBh = pAl + NSTAGE * 128 * ASTRIDE;
    float* pBl = pBh + NSTAGE * 16 * BSTRIDE;

    const int mat = blockIdx.y >> 2;
    const int N = (mat == 3) ? NCN : NVN;
    const int row0 = blockIdx.x * 128;
    if (row0 >= N) return;
    const float* Ah = (mat == 3) ? AhC : AhV;
    const float* Al = (mat == 3) ? AlC : AlV;
    float* C = (mat == 0) ? C0 : (mat == 1) ? C1 : (mat == 2) ? C2 : C3;

    const int tid = threadIdx.x;
    const int lane = tid & 31;
    const int wid = tid >> 5;
    const int wm = (wid & 3) * 32;
    const int wn = (wid >> 2) * 32;
    const int col0 = (blockIdx.y & 3) * 64;
    const float* W_h = Whb + (size_t)mat * HD * HD;
    const float* W_l = Wlb + (size_t)mat * HD * HD;

    const int arow = tid >> 1;
    const int acol = (tid & 1) * 8;
    const int brow = tid >> 4;
    const int bcol = (tid & 15) * 4;

    float acc[2][4][4];
    #pragma unroll
    for (int i = 0; i < 2; i++)
        #pragma unroll
        for (int j = 0; j < 4; j++)
            #pragma unroll
            for (int q = 0; q < 4; q++) acc[i][j][q] = 0.f;

    const int g = lane >> 2, t4 = lane & 3;
    const int lrow = (lane & 7) + ((lane >> 3) & 1) * 8;
    const int lcol = (lane >> 4) << 2;

    auto load_stage = [&](int s, int k0) {
        bool v = (row0 + arow) < N;
        const float* asrc_h = v ? (Ah + (size_t)(row0 + arow) * HD + k0 + acol) : Ah;
        const float* asrc_l = v ? (Al + (size_t)(row0 + arow) * HD + k0 + acol) : Al;
        float* adst_h = pAh + s * 128 * ASTRIDE + arow * ASTRIDE + acol;
        float* adst_l = pAl + s * 128 * ASTRIDE + arow * ASTRIDE + acol;
        cpa16(adst_h,     asrc_h,     v);
        cpa16(adst_h + 4, asrc_h + 4, v);
        cpa16(adst_l,     asrc_l,     v);
        cpa16(adst_l + 4, asrc_l + 4, v);
        cpa16(pBh + s * 16 * BSTRIDE + brow * BSTRIDE + bcol,
              W_h + (size_t)(k0 + brow) * HD + col0 + bcol, true);
        cpa16(pBl + s * 16 * BSTRIDE + brow * BSTRIDE + bcol,
              W_l + (size_t)(k0 + brow) * HD + col0 + bcol, true);
        asm volatile("cp.async.commit_group;");
    };

    load_stage(0, 0);
    load_stage(1, 16);

    for (int kt = 0; kt < 16; kt++) {
        if (kt + 2 < 16) {
            asm volatile("cp.async.wait_group 1;");
        } else {
            asm volatile("cp.async.wait_group 0;");
        }
        __syncthreads();
        if (kt + 2 < 16) load_stage((kt + 2) % NSTAGE, (kt + 2) * 16);

        const int cur = kt % NSTAGE;
        const float* cAh = pAh + cur * 128 * ASTRIDE;
        const float* cAl = pAl + cur * 128 * ASTRIDE;
        const float* cBh = pBh + cur * 16 * BSTRIDE;
        const float* cBl = pBl + cur * 16 * BSTRIDE;

        #pragma unroll
        for (int kk = 0; kk < 2; kk++) {
            const int kb = kk * 8;
            uint32_t ah[2][4], al[2][4];
            #pragma unroll
            for (int i = 0; i < 2; i++) {
                int base = wm + i * 16;
                ldsm4(ah[i], cAh + (base + lrow) * ASTRIDE + kb + lcol);
                ldsm4(al[i], cAl + (base + lrow) * ASTRIDE + kb + lcol);
            }
            uint32_t bh[4][2], bl[4][2];
            #pragma unroll
            for (int j = 0; j < 4; j++) {
                int n = wn + j * 8 + g;
                bh[j][0] = __float_as_uint(cBh[(kb + t4) * BSTRIDE + n]);
                bh[j][1] = __float_as_uint(cBh[(kb + t4 + 4) * BSTRIDE + n]);
                bl[j][0] = __float_as_uint(cBl[(kb + t4) * BSTRIDE + n]);
                bl[j][1] = __float_as_uint(cBl[(kb + t4 + 4) * BSTRIDE + n]);
            }
            #pragma unroll
            for (int i = 0; i < 2; i++)
                #pragma unroll
                for (int j = 0; j < 4; j++) {
                    mma_tf32(acc[i][j], ah[i], bh[j]);
                    mma_tf32(acc[i][j], ah[i], bl[j]);
                    mma_tf32(acc[i][j], al[i], bh[j]);
                }
        }
    }

    #pragma unroll
    for (int i = 0; i < 2; i++) {
        int r0 = row0 + wm + i * 16 + g;
        #pragma unroll
        for (int j = 0; j < 4; j++) {
            int c = col0 + wn + j * 8 + t4 * 2;
            if (r0 < N)
                *(float2*)(C + (size_t)r0 * HD + c) = make_float2(acc[i][j][0], acc[i][j][1]);
            if (r0 + 8 < N)
                *(float2*)(C + (size_t)(r0 + 8) * HD + c) = make_float2(acc[i][j][2], acc[i][j][3]);
        }
    }
}

// ---------------- standalone attention dots (layer 0 only) ----------------
__global__ void avec_var_kernel(const float* __restrict__ xv) {
    __shared__ float sv[6][HD];
    int t = threadIdx.x;
    sv[0][t] = g_WS[0 * HD + t];
    sv[1][t] = g_WD[0 * HD + t];
    sv[2][t] = g_WS[1 * HD + t];
    sv[3][t] = g_WD[1 * HD + t];
    sv[4][t] = g_WS[2 * HD + t];
    sv[5][t] = g_WD[3 * HD + t];
    __syncthreads();
    int w = (blockIdx.x * blockDim.x + t) >> 5;
    int lane = t & 31;
    if (w >= NVN) return;
    const float* row = xv + (size_t)w * HD;
    float s[6] = {0, 0, 0, 0, 0, 0};
    #pragma unroll
    for (int j0 = 0; j0 < HD; j0 += 32) {
        float x = row[j0 + lane];
        #pragma unroll
        for (int k = 0; k < 6; k++) s[k] += x * sv[k][j0 + lane];
    }
    #pragma unroll
    for (int k = 0; k < 6; k++)
        #pragma unroll
        for (int o = 16; o > 0; o >>= 1) s[k] += __shfl_xor_sync(0xffffffffu, s[k], o);
    if (lane == 0) {
        g_AS0[w] = s[0]; g_AD0[w] = s[1];
        g_AS1[w] = s[2]; g_AD1[w] = s[3];
        g_AS2[w] = s[4]; g_AD3[w] = s[5];
    }
}

__global__ void avec_con_kernel(const float* __restrict__ xc) {
    __shared__ float sv[2][HD];
    int t = threadIdx.x;
    sv[0][t] = g_WD[2 * HD + t];
    sv[1][t] = g_WS[3 * HD + t];
    __syncthreads();
    int w = (blockIdx.x * blockDim.x + t) >> 5;
    int lane = t & 31;
    if (w >= NCN) return;
    const float* row = xc + (size_t)w * HD;
    float s0 = 0.f, s1 = 0.f;
    #pragma unroll
    for (int j0 = 0; j0 < HD; j0 += 32) {
        float x = row[j0 + lane];
        s0 += x * sv[0][j0 + lane];
        s1 += x * sv[1][j0 + lane];
    }
    #pragma unroll
    for (int o = 16; o > 0; o >>= 1) {
        s0 += __shfl_xor_sync(0xffffffffu, s0, o);
        s1 += __shfl_xor_sync(0xffffffffu, s1, o);
    }
    if (lane == 0) { g_AD2[w] = s0; g_AS3[w] = s1; }
}

// ---------------- CSR build ----------------
__global__ void zero_int_kernel(int* __restrict__ p, int n) {
    int i = blockIdx.x * blockDim.x + threadIdx.x;
    if (i < n) p[i] = 0;
}
__global__ void hist_kernel(const int* __restrict__ dst, int* __restrict__ cnt, int E) {
    int i = blockIdx.x * blockDim.x + threadIdx.x;
    if (i < E) atomicAdd(&cnt[dst[i]], 1);
}
__global__ void scan_kernel(int* __restrict__ rp, int* __restrict__ cursor, int n) {
    __shared__ int swarp[32];
    __shared__ int stot;
    int t = threadIdx.x, w = t >> 5, lane = t & 31;
    int carry = 0;
    for (int base = 0; base < n; base += 1024) {
        int idx = base + t;
        int v = (idx < n) ? rp[idx] : 0;
        int x = v;
        #pragma unroll
        for (int o = 1; o < 32; o <<= 1) {
            int y = __shfl_up_sync(0xffffffffu, x, o);
            if (lane >= o) x += y;
        }
        if (lane == 31) swarp[w] = x;
        __syncthreads();
        if (w == 0) {
            int s = swarp[lane];
            int z = s;
            #pragma unroll
            for (int o = 1; o < 32; o <<= 1) {
                int y = __shfl_up_sync(0xffffffffu, z, o);
                if (lane >= o) z += y;
            }
            swarp[lane] = z - s;
            if (lane == 31) stot = z;
        }
        __syncthreads();
        int excl = carry + swarp[w] + (x - v);
        if (idx < n) { rp[idx] = excl; cursor[idx] = excl; }
        carry += stot;
        __syncthreads();
    }
    if (t == 0) rp[n] = carry;
}
__global__ void scatter_kernel(const int* __restrict__ src, const int* __restrict__ dst,
                               int* __restrict__ cursor, int* __restrict__ cs, int E) {
    int i = blockIdx.x * blockDim.x + threadIdx.x;
    if (i >= E) return;
    int pos = atomicAdd(&cursor[dst[i]], 1);
    cs[pos] = src[i];
}

// ---------------- fused GAT ----------------
__device__ __forceinline__ void gat_accum(
        int d, int lane,
        const int* __restrict__ rp, const int* __restrict__ cs,
        const float* __restrict__ AS, const float* __restrict__ AD,
        const float* __restrict__ XL,
        float4& acc0, float4& acc1) {
    int off = rp[d];
    int deg = rp[d + 1] - off;
    if (deg <= 0) return;
    float adv = AD[d];
    float m = -1e30f;
    for (int j = lane; j < deg; j += 32) {
        int s = cs[off + j];
        float e = AS[s] + adv;
        e = (e >= 0.f) ? e : 0.2f * e;
        m = fmaxf(m, e);
    }
    #pragma unroll
    for (int o = 16; o > 0; o >>= 1) m = fmaxf(m, __shfl_xor_sync(0xffffffffu, m, o));
    float den = 0.f;
    for (int j = lane; j < deg; j += 32) {
        int s = cs[off + j];
        float e = AS[s] + adv;
        e = (e >= 0.f) ? e : 0.2f * e;
        den += __expf(e - m);
    }
    #pragma unroll
    for (int o = 16; o > 0; o >>= 1) den += __shfl_xor_sync(0xffffffffu, den, o);
    float invden = 1.f / (den + 1e-16f);
    for (int c = 0; c < deg; c += 32) {
        int j = c + lane;
        int s = 0;
        float wgt = 0.f;
        if (j < deg) {
            s = cs[off + j];
            float e = AS[s] + adv;
            e = (e >= 0.f) ? e : 0.2f * e;
            wgt = __expf(e - m) * invden;
        }
        int cnt = min(32, deg - c);
        for (int jj = 0; jj < cnt; jj++) {
            float wj = __shfl_sync(0xffffffffu, wgt, jj);
            int   sj = __shfl_sync(0xffffffffu, s, jj);
            const float4* xs = (const float4*)(XL + (size_t)sj * HD);
            float4 v0 = xs[lane];
            float4 v1 = xs[32 + lane];
            acc0.x += wj * v0.x; acc0.y += wj * v0.y; acc0.z += wj * v0.z; acc0.w += wj * v0.w;
            acc1.x += wj * v1.x; acc1.y += wj * v1.y; acc1.z += wj * v1.z; acc1.w += wj * v1.w;
        }
    }
}

__device__ __forceinline__ void split_store(float* outh, float* outl, int w, int lane,
                                            float4 acc0, float4 acc1) {
    float4 h0, l0, h1, l1;
    tf32split(acc0.x, h0.x, l0.x); tf32split(acc0.y, h0.y, l0.y);
    tf32split(acc0.z, h0.z, l0.z); tf32split(acc0.w, h0.w, l0.w);
    tf32split(acc1.x, h1.x, l1.x); tf32split(acc1.y, h1.y, l1.y);
    tf32split(acc1.z, h1.z, l1.z); tf32split(acc1.w, h1.w, l1.w);
    float4* oh = (float4*)(outh + (size_t)w * HD);
    float4* ol = (float4*)(outl + (size_t)w * HD);
    oh[lane] = h0; oh[32 + lane] = h1;
    ol[lane] = l0; ol[32 + lane] = l1;
}

// one CSR per pass for L2 locality. mode: 0=first (init with 3 biases),
// 1=middle (accumulate), 2=last (accumulate + epilogue)
__global__ void gat_var_pass_kernel(const float* __restrict__ XL,
                                    const int* __restrict__ rp, const int* __restrict__ cs,
                                    const float* __restrict__ AS, const float* __restrict__ AD,
                                    const float* __restrict__ bias, int l,
                                    float* __restrict__ out,
                                    float* __restrict__ outh, float* __restrict__ outl,
                                    int mode, int do_next) {
    int w = (blockIdx.x * blockDim.x + threadIdx.x) >> 5;
    int lane = threadIdx.x & 31;
    if (w >= NVN) return;
    float4 acc0, acc1;
    float4* ob = (float4*)(out + (size_t)w * HD);
    if (mode == 0) {
        const float4* b0 = (const float4*)(bias + (size_t)(4 * l + 0) * HD);
        const float4* b1 = (const float4*)(bias + (size_t)(4 * l + 1) * HD);
        const float4* b3 = (const float4*)(bias + (size_t)(4 * l + 3) * HD);
        float4 x0 = b0[lane], y0 = b1[lane], z0 = b3[lane];
        float4 x1 = b0[32 + lane], y1 = b1[32 + lane], z1 = b3[32 + lane];
        acc0 = make_float4(x0.x + y0.x + z0.x, x0.y + y0.y + z0.y,
                           x0.z + y0.z + z0.z, x0.w + y0.w + z0.w);
        acc1 = make_float4(x1.x + y1.x + z1.x, x1.y + y1.y + z1.y,
                           x1.z + y1.z + z1.z, x1.w + y1.w + z1.w);
    } else {
        acc0 = ob[lane];
        acc1 = ob[32 + lane];
    }
    gat_accum(w, lane, rp, cs, AS, AD, XL, acc0, acc1);
    ob[lane] = acc0;
    ob[32 + lane] = acc1;
    if (mode != 2 || !do_next) return;
    split_store(outh, outl, w, lane, acc0, acc1);
    int L = l + 1;
    int wv = ((l + 1) & 1) * NVN;
    float s[6];
    const int vidx[6] = {0, 0, 1, 1, 2, 3};
    #pragma unroll
    for (int k = 0; k < 6; k++) {
        const float* vecb = (k == 1 || k == 3 || k == 5) ? g_WD : g_WS;
        const float4* vp = (const float4*)(vecb + (size_t)(4 * L + vidx[k]) * HD);
        s[k] = d4(acc0, vp[lane]) + d4(acc1, vp[32 + lane]);
    }
    #pragma unroll
    for (int k = 0; k < 6; k++)
        #pragma unroll
        for (int o = 16; o > 0; o >>= 1) s[k] += __shfl_xor_sync(0xffffffffu, s[k], o);
    if (lane == 0) {
        g_AS0[wv + w] = s[0]; g_AD0[wv + w] = s[1];
        g_AS1[wv + w] = s[2]; g_AD1[wv + w] = s[3];
        g_AS2[wv + w] = s[4]; g_AD3[wv + w] = s[5];
    }
}

__global__ void gat_con_kernel(const float* __restrict__ XL2,
                               const float* __restrict__ bias, int l,
                               float* __restrict__ out,
                               float* __restrict__ outh, float* __restrict__ outl,
                               int do_next) {
    int w = (blockIdx.x * blockDim.x + threadIdx.x) >> 5;
    int lane = threadIdx.x & 31;
    if (w >= NCN) return;
    int rc = (l & 1) * NCN;
    float4 acc0 = make_float4(0.f, 0.f, 0.f, 0.f);
    float4 acc1 = make_float4(0.f, 0.f, 0.f, 0.f);
    gat_accum(w, lane, g_RP2, g_CS2, g_AS2 + (l & 1) * NVN, g_AD2 + rc, XL2, acc0, acc1);
    const float4* b2 = (const float4*)(bias + (size_t)(4 * l + 2) * HD);
    float4 x0 = b2[lane], x1 = b2[32 + lane];
    acc0.x += x0.x; acc0.y += x0.y; acc0.z += x0.z; acc0.w += x0.w;
    acc1.x += x1.x; acc1.y += x1.y; acc1.z += x1.z; acc1.w += x1.w;
    float4* ob = (float4*)(out + (size_t)w * HD);
    ob[lane] = acc0;
    ob[32 + lane] = acc1;
    if (!do_next) return;
    split_store(outh, outl, w, lane, acc0, acc1);
    int L = l + 1;
    int wc = ((l + 1) & 1) * NCN;
    const float4* v0 = (const float4*)(g_WD + (size_t)(4 * L + 2) * HD);
    const float4* v1 = (const float4*)(g_WS + (size_t)(4 * L + 3) * HD);
    float s0 = d4(acc0, v0[lane]) + d4(acc1, v0[32 + lane]);
    float s1 = d4(acc0, v1[lane]) + d4(acc1, v1[32 + lane]);
    #pragma unroll
    for (int o = 16; o > 0; o >>= 1) {
        s0 += __shfl_xor_sync(0xffffffffu, s0, o);
        s1 += __shfl_xor_sync(0xffffffffu, s1, o);
    }
    if (lane == 0) { g_AD2[wc + w] = s0; g_AS3[wc + w] = s1; }
}

// ---------------- pooling + head ----------------
__global__ void zero_pool_kernel() {
    int i = blockIdx.x * 256 + threadIdx.x;
    g_VP[i] = 0.f;
    g_CP[i] = 0.f;
    if (i < 2 * GN) g_CNT[i] = 0;
}

__global__ void pool_kernel(const float* __restrict__ X, const int* __restrict__ batch,
                            int N, float* __restrict__ S, int* __restrict__ cnt) {
    int w = (blockIdx.x * blockDim.x + threadIdx.x) >> 5;
    int lane = threadIdx.x & 31;
    if (w >= N) return;
    int g = batch[w];
    if (lane == 0) atomicAdd(&cnt[g], 1);
    const float4* xr = (const float4*)(X + (size_t)w * HD);
    float* sb = S + (size_t)g * HD;
    #pragma unroll
    for (int j = 0; j < 2; j++) {
        int idx = lane + 32 * j;
        red4(sb + 4 * idx, xr[idx]);
    }
}

__global__ void finalize_kernel(const float* __restrict__ Wlin, const float* __restrict__ blin,
                                float* __restrict__ out) {
    int g = blockIdx.x, t = threadIdx.x;
    float cv = (float)max(g_CNT[g], 1);
    float cc = (float)max(g_CNT[GN + g], 1);
    float a = g_VP[g * HD + t] / cv;
    float c = g_CP[g * HD + t] / cc;
    float p0 = a * Wlin[t * 2 + 0] + c * Wlin[(HD + t) * 2 + 0];
    float p1 = a * Wlin[t * 2 + 1] + c * Wlin[(HD + t) * 2 + 1];
    __shared__ float s0[256], s1[256];
    s0[t] = p0; s1[t] = p1;
    __syncthreads();
    for (int o = 128; o > 0; o >>= 1) {
        if (t < o) { s0[t] += s0[t + o]; s1[t] += s1[t + o]; }
        __syncthreads();
    }
    if (t == 0) {
        float z0 = s0[0] + blin[0], z1 = s1[0] + blin[1];
        float m = fmaxf(z0, z1);
        float e0 = expf(z0 - m), e1 = expf(z1 - m);
        float inv = 1.f / (e0 + e1);
        out[2 * g + 0] = e0 * inv;
        out[2 * g + 1] = e1 * inv;
    }
}

// ---------------- host ----------------
extern "C" void kernel_launch(void* const* d_in, const int* in_sizes, int n_in,
                              void* d_out, int out_size) {
    const float* x_var   = (const float*)d_in[0];
    const float* x_con   = (const float*)d_in[1];
    const float* W_src   = (const float*)d_in[2];
    const float* W_dst   = (const float*)d_in[3];
    const float* att_src = (const float*)d_in[4];
    const float* att_dst = (const float*)d_in[5];
    const float* bias    = (const float*)d_in[6];
    const float* W_lin   = (const float*)d_in[7];
    const float* b_lin   = (const float*)d_in[8];
    const int* e_vv      = (const int*)d_in[9];
    const int* e_vv_rev  = (const int*)d_in[10];
    const int* e_vc      = (const int*)d_in[11];
    const int* e_cv      = (const int*)d_in[12];
    const int* batch_var = (const int*)d_in[13];
    const int* batch_con = (const int*)d_in[14];
    float* out = (float*)d_out;

    float *pXV[2], *pXC[2], *pXL0, *pXL1, *pXL2, *pXL3, *pVP, *pCP;
    float *pAhV, *pAlV, *pAhC, *pAlC, *pWh, *pWl;
    int *pRP0, *pRP1, *pRP2, *pRP3, *pCU0, *pCU1, *pCU2, *pCU3;
    int *pCS0, *pCS1, *pCS2, *pCS3, *pCNT;
    float *pAS0, *pAD0, *pAS1, *pAD1, *pAS2, *pAD3, *pAS3, *pAD2;
    cudaGetSymbolAddress((void**)&pXV[0], g_XV0);
    cudaGetSymbolAddress((void**)&pXV[1], g_XV1);
    cudaGetSymbolAddress((void**)&pXC[0], g_XC0);
    cudaGetSymbolAddress((void**)&pXC[1], g_XC1);
    cudaGetSymbolAddress((void**)&pXL0, g_XL0);
    cudaGetSymbolAddress((void**)&pXL1, g_XL1);
    cudaGetSymbolAddress((void**)&pXL2, g_XL2);
    cudaGetSymbolAddress((void**)&pXL3, g_XL3);
    cudaGetSymbolAddress((void**)&pAhV, g_AhV);
    cudaGetSymbolAddress((void**)&pAlV, g_AlV);
    cudaGetSymbolAddress((void**)&pAhC, g_AhC);
    cudaGetSymbolAddress((void**)&pAlC, g_AlC);
    cudaGetSymbolAddress((void**)&pWh, g_Wh);
    cudaGetSymbolAddress((void**)&pWl, g_Wl);
    cudaGetSymbolAddress((void**)&pRP0, g_RP0);
    cudaGetSymbolAddress((void**)&pRP1, g_RP1);
    cudaGetSymbolAddress((void**)&pRP2, g_RP2);
    cudaGetSymbolAddress((void**)&pRP3, g_RP3);
    cudaGetSymbolAddress((void**)&pCU0, g_CU0);
    cudaGetSymbolAddress((void**)&pCU1, g_CU1);
    cudaGetSymbolAddress((void**)&pCU2, g_CU2);
    cudaGetSymbolAddress((void**)&pCU3, g_CU3);
    cudaGetSymbolAddress((void**)&pCS0, g_CS0);
    cudaGetSymbolAddress((void**)&pCS1, g_CS1);
    cudaGetSymbolAddress((void**)&pCS2, g_CS2);
    cudaGetSymbolAddress((void**)&pCS3, g_CS3);
    cudaGetSymbolAddress((void**)&pAS0, g_AS0);
    cudaGetSymbolAddress((void**)&pAD0, g_AD0);
    cudaGetSymbolAddress((void**)&pAS1, g_AS1);
    cudaGetSymbolAddress((void**)&pAD1, g_AD1);
    cudaGetSymbolAddress((void**)&pAS2, g_AS2);
    cudaGetSymbolAddress((void**)&pAD3, g_AD3);
    cudaGetSymbolAddress((void**)&pAS3, g_AS3);
    cudaGetSymbolAddress((void**)&pAD2, g_AD2);
    cudaGetSymbolAddress((void**)&pVP, g_VP);
    cudaGetSymbolAddress((void**)&pCP, g_CP);
    cudaGetSymbolAddress((void**)&pCNT, g_CNT);

    cudaFuncSetAttribute(gemm_split_kernel,
                         cudaFuncAttributeMaxDynamicSharedMemorySize, SMEM_BYTES);

    const int EB = 256;
    dim3 gemmGrid((NVN + 127) / 128, 16);   // mats 0-2 var, mat 3 con

    // launches 1-5 (so #6 = first GEMM, inside the ncu -s 5 -c 1 window)
    wsd_kernel<<<16, 256>>>(W_src, W_dst, att_src, att_dst);
    split_kernel<<<(16 * HD * HD / 4 + EB - 1) / EB, EB>>>(W_src, pWh, pWl, 16 * HD * HD / 4);
    split_kernel<<<(NVN * HD / 4 + EB - 1) / EB, EB>>>(x_var, pAhV, pAlV, NVN * HD / 4);
    split_kernel<<<(NCN * HD / 4 + EB - 1) / EB, EB>>>(x_con, pAhC, pAlC, NCN * HD / 4);
    avec_var_kernel<<<(NVN * 32 + EB - 1) / EB, EB>>>(x_var);

    // launch 6: layer-0 fused GEMM (captured by ncu)
    gemm_split_kernel<<<gemmGrid, 256, SMEM_BYTES>>>(
        pAhV, pAlV, pAhC, pAlC, pWh, pWl, pXL0, pXL1, pXL2, pXL3);

    avec_con_kernel<<<(NCN * 32 + EB - 1) / EB, EB>>>(x_con);

    // CSR build (needed before GAT only)
    zero_int_kernel<<<(NVN + 1 + EB - 1) / EB, EB>>>(pRP0, NVN + 1);
    zero_int_kernel<<<(NVN + 1 + EB - 1) / EB, EB>>>(pRP1, NVN + 1);
    zero_int_kernel<<<(NVN + 1 + EB - 1) / EB, EB>>>(pRP3, NVN + 1);
    zero_int_kernel<<<(NCN + 1 + EB - 1) / EB, EB>>>(pRP2, NCN + 1);
    hist_kernel<<<(EVVN + EB - 1) / EB, EB>>>(e_vv + EVVN, pRP0, EVVN);
    hist_kernel<<<(EVVN + EB - 1) / EB, EB>>>(e_vv_rev + EVVN, pRP1, EVVN);
    hist_kernel<<<(EVCN + EB - 1) / EB, EB>>>(e_cv + EVCN, pRP3, EVCN);
    hist_kernel<<<(EVCN + EB - 1) / EB, EB>>>(e_vc + EVCN, pRP2, EVCN);
    scan_kernel<<<1, 1024>>>(pRP0, pCU0, NVN);
    scan_kernel<<<1, 1024>>>(pRP1, pCU1, NVN);
    scan_kernel<<<1, 1024>>>(pRP3, pCU3, NVN);
    scan_kernel<<<1, 1024>>>(pRP2, pCU2, NCN);
    scatter_kernel<<<(EVVN + EB - 1) / EB, EB>>>(e_vv, e_vv + EVVN, pCU0, pCS0, EVVN);
    scatter_kernel<<<(EVVN + EB - 1) / EB, EB>>>(e_vv_rev, e_vv_rev + EVVN, pCU1, pCS1, EVVN);
    scatter_kernel<<<(EVCN + EB - 1) / EB, EB>>>(e_cv, e_cv + EVCN, pCU3, pCS3, EVCN);
    scatter_kernel<<<(EVCN + EB - 1) / EB, EB>>>(e_vc, e_vc + EVCN, pCU2, pCS2, EVCN);

    int gatVB = (NVN * 32 + EB - 1) / EB;
    int gatCB = (NCN * 32 + EB - 1) / EB;

    for (int l = 0; l < NLAYER; l++) {
        float* xv_out = pXV[l & 1];
        float* xc_out = pXC[l & 1];
        int do_next = (l + 1 < NLAYER) ? 1 : 0;
        int rv = (l & 1) * NVN, rc = (l & 1) * NCN;

        if (l > 0) {
            gemm_split_kernel<<<gemmGrid, 256, SMEM_BYTES>>>(
                pAhV, pAlV, pAhC, pAlC,
                pWh + (size_t)(4 * l) * HD * HD, pWl + (size_t)(4 * l) * HD * HD,
                pXL0, pXL1, pXL2, pXL3);
        }

        // var GAT: one CSR per pass (L2 locality)
        gat_var_pass_kernel<<<gatVB, EB>>>(pXL0, pRP0, pCS0, pAS0 + rv, pAD0 + rv,
                                           bias, l, xv_out, pAhV, pAlV, 0, do_next);
        gat_var_pass_kernel<<<gatVB, EB>>>(pXL1, pRP1, pCS1, pAS1 + rv, pAD1 + rv,
                                           bias, l, xv_out, pAhV, pAlV, 1, do_next);
        gat_var_pass_kernel<<<gatVB, EB>>>(pXL3, pRP3, pCS3, pAS3 + rc, pAD3 + rv,
                                           bias, l, xv_out, pAhV, pAlV, 2, do_next);
        gat_con_kernel<<<gatCB, EB>>>(pXL2, bias, l, xc_out, pAhC, pAlC, do_next);
    }

    zero_pool_kernel<<<GN, 256>>>();
    pool_kernel<<<gatVB, EB>>>(pXV[(NLAYER - 1) & 1], batch_var, NVN, pVP, pCNT);
    pool_kernel<<<gatCB, EB>>>(pXC[(NLAYER - 1) & 1], batch_con, NCN, pCP, pCNT + GN);
    finalize_kernel<<<GN, 256>>>(W_lin, b_lin, out);
}

// round 9
// speedup vs baseline: 1.4522x; 1.4307x over previous
#include <cuda_runtime.h>
#include <cuda_fp16.h>
#include <cstdint>
#include <cstddef>

#define NVN 50000
#define NCN 20000
#define HD  256
#define NLAYER 4
#define EVVN 500000
#define EVCN 300000
#define GN  64

#define ASTR 40
#define BSTR 40
#define BK 32
#define NSTAGE 3
// halves: A stages 3*128*40*2(hi,lo) + B stages 3*64*40*2
#define SMEM_HALVES (NSTAGE*128*ASTR*2 + NSTAGE*64*BSTR*2)
#define SMEM_BYTES  (SMEM_HALVES*2)

// ---------------- scratch ----------------
__device__ __align__(128) float g_XV0[NVN * HD];
__device__ __align__(128) float g_XV1[NVN * HD];
__device__ __align__(128) float g_XC0[NCN * HD];
__device__ __align__(128) float g_XC1[NCN * HD];
__device__ __align__(128) float g_XL0[NVN * HD];
__device__ __align__(128) float g_XL1[NVN * HD];
__device__ __align__(128) float g_XL2[NVN * HD];
__device__ __align__(128) float g_XL3[NCN * HD];

// fp16 hi/lo operand buffers
__device__ __align__(128) __half g_AhV[NVN * HD];
__device__ __align__(128) __half g_AlV[NVN * HD];
__device__ __align__(128) __half g_AhC[NCN * HD];
__device__ __align__(128) __half g_AlC[NCN * HD];
__device__ __align__(128) __half g_WhT[16 * HD * HD];  // [mat][n][k]
__device__ __align__(128) __half g_WlT[16 * HD * HD];

// double-buffered attention scalars: [parity][node]
__device__ float g_AS0[2 * NVN], g_AD0[2 * NVN];
__device__ float g_AS1[2 * NVN], g_AD1[2 * NVN];
__device__ float g_AS2[2 * NVN], g_AD3[2 * NVN];
__device__ float g_AS3[2 * NCN], g_AD2[2 * NCN];

__device__ __align__(128) float g_WS[16 * HD];
__device__ __align__(128) float g_WD[16 * HD];

__device__ int g_RP0[NVN + 1], g_RP1[NVN + 1], g_RP3[NVN + 1], g_RP2[NCN + 1];
__device__ int g_CU0[NVN], g_CU1[NVN], g_CU3[NVN], g_CU2[NCN];
__device__ int g_CS0[EVVN], g_CS1[EVVN], g_CS3[EVCN], g_CS2[EVCN];

__device__ __align__(128) float g_VP[GN * HD];
__device__ __align__(128) float g_CP[GN * HD];
__device__ int   g_CNT[2 * GN];

// ---------------- helpers ----------------
__device__ __forceinline__ void red4(float* p, float4 v) {
    asm volatile("red.global.add.v4.f32 [%0], {%1,%2,%3,%4};"
                 :: "l"(p), "f"(v.x), "f"(v.y), "f"(v.z), "f"(v.w) : "memory");
}
__device__ __forceinline__ void h2split(float x, __half& h, __half& l) {
    h = __float2half_rn(x);
    l = __float2half_rn(x - __half2float(h));
}
__device__ __forceinline__ void ldsm4(uint32_t* r, const void* p) {
    uint32_t addr = (uint32_t)__cvta_generic_to_shared(p);
    asm volatile("ldmatrix.sync.aligned.m8n8.x4.shared.b16 {%0,%1,%2,%3}, [%4];"
                 : "=r"(r[0]), "=r"(r[1]), "=r"(r[2]), "=r"(r[3]) : "r"(addr));
}
__device__ __forceinline__ void mma_f16(float* c, const uint32_t* a, const uint32_t* b) {
    asm volatile(
        "mma.sync.aligned.m16n8k16.row.col.f32.f16.f16.f32 "
        "{%0,%1,%2,%3}, {%4,%5,%6,%7}, {%8,%9}, {%0,%1,%2,%3};"
        : "+f"(c[0]), "+f"(c[1]), "+f"(c[2]), "+f"(c[3])
        : "r"(a[0]), "r"(a[1]), "r"(a[2]), "r"(a[3]), "r"(b[0]), "r"(b[1]));
}
__device__ __forceinline__ void cpa16(void* dst, const void* src, bool valid) {
    uint32_t d = (uint32_t)__cvta_generic_to_shared(dst);
    int sz = valid ? 16 : 0;
    asm volatile("cp.async.ca.shared.global [%0], [%1], 16, %2;"
                 :: "r"(d), "l"(src), "r"(sz));
}
__device__ __forceinline__ float d4(float4 a, float4 b) {
    return a.x * b.x + a.y * b.y + a.z * b.z + a.w * b.w;
}

// ---------------- ws/wd precompute ----------------
__global__ void wsd_kernel(const float* __restrict__ Wsrc, const float* __restrict__ Wdst,
                           const float* __restrict__ as, const float* __restrict__ ad) {
    int b = blockIdx.x;
    int i = threadIdx.x;
    __shared__ float sas[HD], sad[HD];
    sas[i] = as[b * HD + i];
    sad[i] = ad[b * HD + i];
    __syncthreads();
    const float* Ws = Wsrc + (size_t)b * HD * HD + (size_t)i * HD;
    const float* Wd = Wdst + (size_t)b * HD * HD + (size_t)i * HD;
    float s = 0.f, d = 0.f;
    #pragma unroll 8
    for (int j = 0; j < HD; j++) { s += Ws[j] * sas[j]; d += Wd[j] * sad[j]; }
    g_WS[b * HD + i] = s;
    g_WD[b * HD + i] = d;
}

// ---------------- activation split: fp32 -> (half hi, half lo) ----------------
__global__ void split_kernel(const float* __restrict__ X, __half* __restrict__ Xh,
                             __half* __restrict__ Xl, int n4) {
    int i = blockIdx.x * blockDim.x + threadIdx.x;
    if (i >= n4) return;
    float4 v = ((const float4*)X)[i];
    __half h0, h1, h2, h3, l0, l1, l2, l3;
    h2split(v.x, h0, l0); h2split(v.y, h1, l1);
    h2split(v.z, h2, l2); h2split(v.w, h3, l3);
    ((__half2*)Xh)[i * 2 + 0] = __halves2half2(h0, h1);
    ((__half2*)Xh)[i * 2 + 1] = __halves2half2(h2, h3);
    ((__half2*)Xl)[i * 2 + 0] = __halves2half2(l0, l1);
    ((__half2*)Xl)[i * 2 + 1] = __halves2half2(l2, l3);
}

// ---------------- W transpose + split: W[mat][k][n] -> WhT/WlT[mat][n][k] -------
__global__ void wsplit_kernel(const float* __restrict__ W) {
    __shared__ float tile[32][33];
    int mat = blockIdx.z;
    int bk = blockIdx.x * 32, bn = blockIdx.y * 32;
    int tx = threadIdx.x, ty = threadIdx.y;   // (32, 8)
    const float* Wm = W + (size_t)mat * HD * HD;
    #pragma unroll
    for (int r = 0; r < 32; r += 8)
        tile[ty + r][tx] = Wm[(size_t)(bk + ty + r) * HD + bn + tx];
    __syncthreads();
    #pragma unroll
    for (int r = 0; r < 32; r += 8) {
        float x = tile[tx][ty + r];
        __half h, l;
        h2split(x, h, l);
        size_t o = (size_t)mat * HD * HD + (size_t)(bn + ty + r) * HD + bk + tx;
        g_WhT[o] = h;
        g_WlT[o] = l;
    }
}

// ---------------- fp16x3 GEMM, 3-stage cp.async, grid.y=16 (mats 0-2 var, 3 con) --
__global__ __launch_bounds__(256, 2) void gemm_fp16_kernel(
        const __half* __restrict__ AhV, const __half* __restrict__ AlV,
        const __half* __restrict__ AhC, const __half* __restrict__ AlC,
        const __half* __restrict__ WhT, const __half* __restrict__ WlT,
        float* __restrict__ C0, float* __restrict__ C1,
        float* __restrict__ C2, float* __restrict__ C3) {
    extern __shared__ __half smh[];
    __half* pAh = smh;
    __half* pAl = pAh + NSTAGE * 128 * ASTR;
    __half* pBh = pAl + NSTAGE * 128 * ASTR;
    __half* pBl = pBh + NSTAGE * 64 * BSTR;

    const int mat = blockIdx.y >> 2;
    const int N = (mat == 3) ? NCN : NVN;
    const int row0 = blockIdx.x * 128;
    if (row0 >= N) return;
    const __half* Ah = (mat == 3) ? AhC : AhV;
    const __half* Al = (mat == 3) ? AlC : AlV;
    float* C = (mat == 0) ? C0 : (mat == 1) ? C1 : (mat == 2) ? C2 : C3;
    const int col0 = (blockIdx.y & 3) * 64;
    const __half* W_h = WhT + (size_t)mat * HD * HD;
    const __half* W_l = WlT + (size_t)mat * HD * HD;

    const int tid = threadIdx.x;
    const int lane = tid & 31;
    const int wid = tid >> 5;
    const int wm = (wid & 3) * 32;
    const int wn = (wid >> 2) * 32;

    const int arow = tid >> 1;            // 0..127
    const int acol = (tid & 1) * 16;      // half-offset 0 or 16
    const int bn = tid >> 2;              // 0..63 (n row)
    const int bk8 = (tid & 3) * 8;        // half-offset 0,8,16,24

    float acc[2][4][4];
    #pragma unroll
    for (int i = 0; i < 2; i++)
        #pragma unroll
        for (int j = 0; j < 4; j++)
            #pragma unroll
            for (int q = 0; q < 4; q++) acc[i][j][q] = 0.f;

    const int g = lane >> 2, t4 = lane & 3;
    const int lr = lane & 15;             // ldmatrix row within 16
    const int lk = (lane >> 4) * 8;       // ldmatrix k-offset (halves)

    auto load_stage = [&](int s, int k0) {
        bool v = (row0 + arow) < N;
        const __half* ah = v ? (Ah + (size_t)(row0 + arow) * HD + k0 + acol) : Ah;
        const __half* al = v ? (Al + (size_t)(row0 + arow) * HD + k0 + acol) : Al;
        __half* dh = pAh + s * 128 * ASTR + arow * ASTR + acol;
        __half* dl = pAl + s * 128 * ASTR + arow * ASTR + acol;
        cpa16(dh,     ah,     v);
        cpa16(dh + 8, ah + 8, v);
        cpa16(dl,     al,     v);
        cpa16(dl + 8, al + 8, v);
        cpa16(pBh + s * 64 * BSTR + bn * BSTR + bk8,
              W_h + (size_t)(col0 + bn) * HD + k0 + bk8, true);
        cpa16(pBl + s * 64 * BSTR + bn * BSTR + bk8,
              W_l + (size_t)(col0 + bn) * HD + k0 + bk8, true);
        asm volatile("cp.async.commit_group;");
    };

    load_stage(0, 0);
    load_stage(1, BK);

    for (int kt = 0; kt < 8; kt++) {
        if (kt + 2 < 8) {
            asm volatile("cp.async.wait_group 1;");
        } else {
            asm volatile("cp.async.wait_group 0;");
        }
        __syncthreads();
        if (kt + 2 < 8) load_stage((kt + 2) % NSTAGE, (kt + 2) * BK);

        const int cur = kt % NSTAGE;
        const __half* cAh = pAh + cur * 128 * ASTR;
        const __half* cAl = pAl + cur * 128 * ASTR;
        const __half* cBh = pBh + cur * 64 * BSTR;
        const __half* cBl = pBl + cur * 64 * BSTR;

        #pragma unroll
        for (int ks = 0; ks < 2; ks++) {
            const int kb = ks * 16;
            uint32_t ah[2][4], al[2][4];
            #pragma unroll
            for (int i = 0; i < 2; i++) {
                const __half* base = cAh + (size_t)(wm + i * 16 + lr) * ASTR + kb + lk;
                ldsm4(ah[i], base);
                const __half* basel = cAl + (size_t)(wm + i * 16 + lr) * ASTR + kb + lk;
                ldsm4(al[i], basel);
            }
            uint32_t bh[4][2], bl[4][2];
            #pragma unroll
            for (int j = 0; j < 4; j++) {
                int n = wn + j * 8 + g;
                bh[j][0] = *(const uint32_t*)(cBh + n * BSTR + kb + 2 * t4);
                bh[j][1] = *(const uint32_t*)(cBh + n * BSTR + kb + 2 * t4 + 8);
                bl[j][0] = *(const uint32_t*)(cBl + n * BSTR + kb + 2 * t4);
                bl[j][1] = *(const uint32_t*)(cBl + n * BSTR + kb + 2 * t4 + 8);
            }
            #pragma unroll
            for (int i = 0; i < 2; i++)
                #pragma unroll
                for (int j = 0; j < 4; j++) {
                    mma_f16(acc[i][j], ah[i], bh[j]);
                    mma_f16(acc[i][j], ah[i], bl[j]);
                    mma_f16(acc[i][j], al[i], bh[j]);
                }
        }
    }

    #pragma unroll
    for (int i = 0; i < 2; i++) {
        int r0 = row0 + wm + i * 16 + g;
        #pragma unroll
        for (int j = 0; j < 4; j++) {
            int c = col0 + wn + j * 8 + t4 * 2;
            if (r0 < N)
                *(float2*)(C + (size_t)r0 * HD + c) = make_float2(acc[i][j][0], acc[i][j][1]);
            if (r0 + 8 < N)
                *(float2*)(C + (size_t)(r0 + 8) * HD + c) = make_float2(acc[i][j][2], acc[i][j][3]);
        }
    }
}

// ---------------- standalone attention dots (layer 0 only) ----------------
__global__ void avec_var_kernel(const float* __restrict__ xv) {
    __shared__ float sv[6][HD];
    int t = threadIdx.x;
    sv[0][t] = g_WS[0 * HD + t];
    sv[1][t] = g_WD[0 * HD + t];
    sv[2][t] = g_WS[1 * HD + t];
    sv[3][t] = g_WD[1 * HD + t];
    sv[4][t] = g_WS[2 * HD + t];
    sv[5][t] = g_WD[3 * HD + t];
    __syncthreads();
    int w = (blockIdx.x * blockDim.x + t) >> 5;
    int lane = t & 31;
    if (w >= NVN) return;
    const float* row = xv + (size_t)w * HD;
    float s[6] = {0, 0, 0, 0, 0, 0};
    #pragma unroll
    for (int j0 = 0; j0 < HD; j0 += 32) {
        float x = row[j0 + lane];
        #pragma unroll
        for (int k = 0; k < 6; k++) s[k] += x * sv[k][j0 + lane];
    }
    #pragma unroll
    for (int k = 0; k < 6; k++)
        #pragma unroll
        for (int o = 16; o > 0; o >>= 1) s[k] += __shfl_xor_sync(0xffffffffu, s[k], o);
    if (lane == 0) {
        g_AS0[w] = s[0]; g_AD0[w] = s[1];
        g_AS1[w] = s[2]; g_AD1[w] = s[3];
        g_AS2[w] = s[4]; g_AD3[w] = s[5];
    }
}

__global__ void avec_con_kernel(const float* __restrict__ xc) {
    __shared__ float sv[2][HD];
    int t = threadIdx.x;
    sv[0][t] = g_WD[2 * HD + t];
    sv[1][t] = g_WS[3 * HD + t];
    __syncthreads();
    int w = (blockIdx.x * blockDim.x + t) >> 5;
    int lane = t & 31;
    if (w >= NCN) return;
    const float* row = xc + (size_t)w * HD;
    float s0 = 0.f, s1 = 0.f;
    #pragma unroll
    for (int j0 = 0; j0 < HD; j0 += 32) {
        float x = row[j0 + lane];
        s0 += x * sv[0][j0 + lane];
        s1 += x * sv[1][j0 + lane];
    }
    #pragma unroll
    for (int o = 16; o > 0; o >>= 1) {
        s0 += __shfl_xor_sync(0xffffffffu, s0, o);
        s1 += __shfl_xor_sync(0xffffffffu, s1, o);
    }
    if (lane == 0) { g_AD2[w] = s0; g_AS3[w] = s1; }
}

// ---------------- CSR build ----------------
__global__ void zero_int_kernel(int* __restrict__ p, int n) {
    int i = blockIdx.x * blockDim.x + threadIdx.x;
    if (i < n) p[i] = 0;
}
__global__ void hist_kernel(const int* __restrict__ dst, int* __restrict__ cnt, int E) {
    int i = blockIdx.x * blockDim.x + threadIdx.x;
    if (i < E) atomicAdd(&cnt[dst[i]], 1);
}
__global__ void scan_kernel(int* __restrict__ rp, int* __restrict__ cursor, int n) {
    __shared__ int swarp[32];
    __shared__ int stot;
    int t = threadIdx.x, w = t >> 5, lane = t & 31;
    int carry = 0;
    for (int base = 0; base < n; base += 1024) {
        int idx = base + t;
        int v = (idx < n) ? rp[idx] : 0;
        int x = v;
        #pragma unroll
        for (int o = 1; o < 32; o <<= 1) {
            int y = __shfl_up_sync(0xffffffffu, x, o);
            if (lane >= o) x += y;
        }
        if (lane == 31) swarp[w] = x;
        __syncthreads();
        if (w == 0) {
            int s = swarp[lane];
            int z = s;
            #pragma unroll
            for (int o = 1; o < 32; o <<= 1) {
                int y = __shfl_up_sync(0xffffffffu, z, o);
                if (lane >= o) z += y;
            }
            swarp[lane] = z - s;
            if (lane == 31) stot = z;
        }
        __syncthreads();
        int excl = carry + swarp[w] + (x - v);
        if (idx < n) { rp[idx] = excl; cursor[idx] = excl; }
        carry += stot;
        __syncthreads();
    }
    if (t == 0) rp[n] = carry;
}
__global__ void scatter_kernel(const int* __restrict__ src, const int* __restrict__ dst,
                               int* __restrict__ cursor, int* __restrict__ cs, int E) {
    int i = blockIdx.x * blockDim.x + threadIdx.x;
    if (i >= E) return;
    int pos = atomicAdd(&cursor[dst[i]], 1);
    cs[pos] = src[i];
}

// ---------------- fused GAT ----------------
__device__ __forceinline__ void gat_accum(
        int d, int lane,
        const int* __restrict__ rp, const int* __restrict__ cs,
        const float* __restrict__ AS, const float* __restrict__ AD,
        const float* __restrict__ XL,
        float4& acc0, float4& acc1) {
    int off = rp[d];
    int deg = rp[d + 1] - off;
    if (deg <= 0) return;
    float adv = AD[d];
    float m = -1e30f;
    for (int j = lane; j < deg; j += 32) {
        int s = cs[off + j];
        float e = AS[s] + adv;
        e = (e >= 0.f) ? e : 0.2f * e;
        m = fmaxf(m, e);
    }
    #pragma unroll
    for (int o = 16; o > 0; o >>= 1) m = fmaxf(m, __shfl_xor_sync(0xffffffffu, m, o));
    float den = 0.f;
    for (int j = lane; j < deg; j += 32) {
        int s = cs[off + j];
        float e = AS[s] + adv;
        e = (e >= 0.f) ? e : 0.2f * e;
        den += __expf(e - m);
    }
    #pragma unroll
    for (int o = 16; o > 0; o >>= 1) den += __shfl_xor_sync(0xffffffffu, den, o);
    float invden = 1.f / (den + 1e-16f);
    // uniform per-neighbor loop: broadcast loads, no shfl, high MLP
    #pragma unroll 4
    for (int j = 0; j < deg; j++) {
        int s = cs[off + j];
        float e = AS[s] + adv;
        e = (e >= 0.f) ? e : 0.2f * e;
        float wgt = __expf(e - m) * invden;
        const float4* xs = (const float4*)(XL + (size_t)s * HD);
        float4 v0 = xs[lane];
        float4 v1 = xs[32 + lane];
        acc0.x += wgt * v0.x; acc0.y += wgt * v0.y; acc0.z += wgt * v0.z; acc0.w += wgt * v0.w;
        acc1.x += wgt * v1.x; acc1.y += wgt * v1.y; acc1.z += wgt * v1.z; acc1.w += wgt * v1.w;
    }
}

__device__ __forceinline__ void split_store(__half* outh, __half* outl, int w, int lane,
                                            float4 acc0, float4 acc1) {
    __half h0, h1, h2, h3, l0, l1, l2, l3;
    __half2* oh = (__half2*)(outh + (size_t)w * HD);
    __half2* ol = (__half2*)(outl + (size_t)w * HD);
    h2split(acc0.x, h0, l0); h2split(acc0.y, h1, l1);
    h2split(acc0.z, h2, l2); h2split(acc0.w, h3, l3);
    oh[lane * 2 + 0] = __halves2half2(h0, h1);
    oh[lane * 2 + 1] = __halves2half2(h2, h3);
    ol[lane * 2 + 0] = __halves2half2(l0, l1);
    ol[lane * 2 + 1] = __halves2half2(l2, l3);
    h2split(acc1.x, h0, l0); h2split(acc1.y, h1, l1);
    h2split(acc1.z, h2, l2); h2split(acc1.w, h3, l3);
    oh[(32 + lane) * 2 + 0] = __halves2half2(h0, h1);
    oh[(32 + lane) * 2 + 1] = __halves2half2(h2, h3);
    ol[(32 + lane) * 2 + 0] = __halves2half2(l0, l1);
    ol[(32 + lane) * 2 + 1] = __halves2half2(l2, l3);
}

// one CSR per pass. mode: 0=first (init with 3 biases), 1=middle, 2=last(+epilogue)
__global__ void gat_var_pass_kernel(const float* __restrict__ XL,
                                    const int* __restrict__ rp, const int* __restrict__ cs,
                                    const float* __restrict__ AS, const float* __restrict__ AD,
                                    const float* __restrict__ bias, int l,
                                    float* __restrict__ out,
                                    __half* __restrict__ outh, __half* __restrict__ outl,
                                    int mode, int do_next) {
    int w = (blockIdx.x * blockDim.x + threadIdx.x) >> 5;
    int lane = threadIdx.x & 31;
    if (w >= NVN) return;
    float4 acc0, acc1;
    float4* ob = (float4*)(out + (size_t)w * HD);
    if (mode == 0) {
        const float4* b0 = (const float4*)(bias + (size_t)(4 * l + 0) * HD);
        const float4* b1 = (const float4*)(bias + (size_t)(4 * l + 1) * HD);
        const float4* b3 = (const float4*)(bias + (size_t)(4 * l + 3) * HD);
        float4 x0 = b0[lane], y0 = b1[lane], z0 = b3[lane];
        float4 x1 = b0[32 + lane], y1 = b1[32 + lane], z1 = b3[32 + lane];
        acc0 = make_float4(x0.x + y0.x + z0.x, x0.y + y0.y + z0.y,
                           x0.z + y0.z + z0.z, x0.w + y0.w + z0.w);
        acc1 = make_float4(x1.x + y1.x + z1.x, x1.y + y1.y + z1.y,
                           x1.z + y1.z + z1.z, x1.w + y1.w + z1.w);
    } else {
        acc0 = ob[lane];
        acc1 = ob[32 + lane];
    }
    gat_accum(w, lane, rp, cs, AS, AD, XL, acc0, acc1);
    ob[lane] = acc0;
    ob[32 + lane] = acc1;
    if (mode != 2 || !do_next) return;
    split_store(outh, outl, w, lane, acc0, acc1);
    int L = l + 1;
    int wv = ((l + 1) & 1) * NVN;
    float s[6];
    const int vidx[6] = {0, 0, 1, 1, 2, 3};
    #pragma unroll
    for (int k = 0; k < 6; k++) {
        const float* vecb = (k == 1 || k == 3 || k == 5) ? g_WD : g_WS;
        const float4* vp = (const float4*)(vecb + (size_t)(4 * L + vidx[k]) * HD);
        s[k] = d4(acc0, vp[lane]) + d4(acc1, vp[32 + lane]);
    }
    #pragma unroll
    for (int k = 0; k < 6; k++)
        #pragma unroll
        for (int o = 16; o > 0; o >>= 1) s[k] += __shfl_xor_sync(0xffffffffu, s[k], o);
    if (lane == 0) {
        g_AS0[wv + w] = s[0]; g_AD0[wv + w] = s[1];
        g_AS1[wv + w] = s[2]; g_AD1[wv + w] = s[3];
        g_AS2[wv + w] = s[4]; g_AD3[wv + w] = s[5];
    }
}

__global__ void gat_con_kernel(const float* __restrict__ XL2,
                               const float* __restrict__ bias, int l,
                               float* __restrict__ out,
                               __half* __restrict__ outh, __half* __restrict__ outl,
                               int do_next) {
    int w = (blockIdx.x * blockDim.x + threadIdx.x) >> 5;
    int lane = threadIdx.x & 31;
    if (w >= NCN) return;
    int rc = (l & 1) * NCN;
    float4 acc0 = make_float4(0.f, 0.f, 0.f, 0.f);
    float4 acc1 = make_float4(0.f, 0.f, 0.f, 0.f);
    gat_accum(w, lane, g_RP2, g_CS2, g_AS2 + (l & 1) * NVN, g_AD2 + rc, XL2, acc0, acc1);
    const float4* b2 = (const float4*)(bias + (size_t)(4 * l + 2) * HD);
    float4 x0 = b2[lane], x1 = b2[32 + lane];
    acc0.x += x0.x; acc0.y += x0.y; acc0.z += x0.z; acc0.w += x0.w;
    acc1.x += x1.x; acc1.y += x1.y; acc1.z += x1.z; acc1.w += x1.w;
    float4* ob = (float4*)(out + (size_t)w * HD);
    ob[lane] = acc0;
    ob[32 + lane] = acc1;
    if (!do_next) return;
    split_store(outh, outl, w, lane, acc0, acc1);
    int L = l + 1;
    int wc = ((l + 1) & 1) * NCN;
    const float4* v0 = (const float4*)(g_WD + (size_t)(4 * L + 2) * HD);
    const float4* v1 = (const float4*)(g_WS + (size_t)(4 * L + 3) * HD);
    float s0 = d4(acc0, v0[lane]) + d4(acc1, v0[32 + lane]);
    float s1 = d4(acc0, v1[lane]) + d4(acc1, v1[32 + lane]);
    #pragma unroll
    for (int o = 16; o > 0; o >>= 1) {
        s0 += __shfl_xor_sync(0xffffffffu, s0, o);
        s1 += __shfl_xor_sync(0xffffffffu, s1, o);
    }
    if (lane == 0) { g_AD2[wc + w] = s0; g_AS3[wc + w] = s1; }
}

// ---------------- pooling + head ----------------
__global__ void zero_pool_kernel() {
    int i = blockIdx.x * 256 + threadIdx.x;
    g_VP[i] = 0.f;
    g_CP[i] = 0.f;
    if (i < 2 * GN) g_CNT[i] = 0;
}

__global__ void pool_kernel(const float* __restrict__ X, const int* __restrict__ batch,
                            int N, float* __restrict__ S, int* __restrict__ cnt) {
    int w = (blockIdx.x * blockDim.x + threadIdx.x) >> 5;
    int lane = threadIdx.x & 31;
    if (w >= N) return;
    int g = batch[w];
    if (lane == 0) atomicAdd(&cnt[g], 1);
    const float4* xr = (const float4*)(X + (size_t)w * HD);
    float* sb = S + (size_t)g * HD;
    #pragma unroll
    for (int j = 0; j < 2; j++) {
        int idx = lane + 32 * j;
        red4(sb + 4 * idx, xr[idx]);
    }
}

__global__ void finalize_kernel(const float* __restrict__ Wlin, const float* __restrict__ blin,
                                float* __restrict__ out) {
    int g = blockIdx.x, t = threadIdx.x;
    float cv = (float)max(g_CNT[g], 1);
    float cc = (float)max(g_CNT[GN + g], 1);
    float a = g_VP[g * HD + t] / cv;
    float c = g_CP[g * HD + t] / cc;
    float p0 = a * Wlin[t * 2 + 0] + c * Wlin[(HD + t) * 2 + 0];
    float p1 = a * Wlin[t * 2 + 1] + c * Wlin[(HD + t) * 2 + 1];
    __shared__ float s0[256], s1[256];
    s0[t] = p0; s1[t] = p1;
    __syncthreads();
    for (int o = 128; o > 0; o >>= 1) {
        if (t < o) { s0[t] += s0[t + o]; s1[t] += s1[t + o]; }
        __syncthreads();
    }
    if (t == 0) {
        float z0 = s0[0] + blin[0], z1 = s1[0] + blin[1];
        float m = fmaxf(z0, z1);
        float e0 = expf(z0 - m), e1 = expf(z1 - m);
        float inv = 1.f / (e0 + e1);
        out[2 * g + 0] = e0 * inv;
        out[2 * g + 1] = e1 * inv;
    }
}

// ---------------- host ----------------
extern "C" void kernel_launch(void* const* d_in, const int* in_sizes, int n_in,
                              void* d_out, int out_size) {
    const float* x_var   = (const float*)d_in[0];
    const float* x_con   = (const float*)d_in[1];
    const float* W_src   = (const float*)d_in[2];
    const float* W_dst   = (const float*)d_in[3];
    const float* att_src = (const float*)d_in[4];
    const float* att_dst = (const float*)d_in[5];
    const float* bias    = (const float*)d_in[6];
    const float* W_lin   = (const float*)d_in[7];
    const float* b_lin   = (const float*)d_in[8];
    const int* e_vv      = (const int*)d_in[9];
    const int* e_vv_rev  = (const int*)d_in[10];
    const int* e_vc      = (const int*)d_in[11];
    const int* e_cv      = (const int*)d_in[12];
    const int* batch_var = (const int*)d_in[13];
    const int* batch_con = (const int*)d_in[14];
    float* out = (float*)d_out;

    float *pXV[2], *pXC[2], *pXL0, *pXL1, *pXL2, *pXL3, *pVP, *pCP;
    __half *pAhV, *pAlV, *pAhC, *pAlC, *pWhT, *pWlT;
    int *pRP0, *pRP1, *pRP2, *pRP3, *pCU0, *pCU1, *pCU2, *pCU3;
    int *pCS0, *pCS1, *pCS2, *pCS3, *pCNT;
    float *pAS0, *pAD0, *pAS1, *pAD1, *pAS2, *pAD3, *pAS3, *pAD2;
    cudaGetSymbolAddress((void**)&pXV[0], g_XV0);
    cudaGetSymbolAddress((void**)&pXV[1], g_XV1);
    cudaGetSymbolAddress((void**)&pXC[0], g_XC0);
    cudaGetSymbolAddress((void**)&pXC[1], g_XC1);
    cudaGetSymbolAddress((void**)&pXL0, g_XL0);
    cudaGetSymbolAddress((void**)&pXL1, g_XL1);
    cudaGetSymbolAddress((void**)&pXL2, g_XL2);
    cudaGetSymbolAddress((void**)&pXL3, g_XL3);
    cudaGetSymbolAddress((void**)&pAhV, g_AhV);
    cudaGetSymbolAddress((void**)&pAlV, g_AlV);
    cudaGetSymbolAddress((void**)&pAhC, g_AhC);
    cudaGetSymbolAddress((void**)&pAlC, g_AlC);
    cudaGetSymbolAddress((void**)&pWhT, g_WhT);
    cudaGetSymbolAddress((void**)&pWlT, g_WlT);
    cudaGetSymbolAddress((void**)&pRP0, g_RP0);
    cudaGetSymbolAddress((void**)&pRP1, g_RP1);
    cudaGetSymbolAddress((void**)&pRP2, g_RP2);
    cudaGetSymbolAddress((void**)&pRP3, g_RP3);
    cudaGetSymbolAddress((void**)&pCU0, g_CU0);
    cudaGetSymbolAddress((void**)&pCU1, g_CU1);
    cudaGetSymbolAddress((void**)&pCU2, g_CU2);
    cudaGetSymbolAddress((void**)&pCU3, g_CU3);
    cudaGetSymbolAddress((void**)&pCS0, g_CS0);
    cudaGetSymbolAddress((void**)&pCS1, g_CS1);
    cudaGetSymbolAddress((void**)&pCS2, g_CS2);
    cudaGetSymbolAddress((void**)&pCS3, g_CS3);
    cudaGetSymbolAddress((void**)&pAS0, g_AS0);
    cudaGetSymbolAddress((void**)&pAD0, g_AD0);
    cudaGetSymbolAddress((void**)&pAS1, g_AS1);
    cudaGetSymbolAddress((void**)&pAD1, g_AD1);
    cudaGetSymbolAddress((void**)&pAS2, g_AS2);
    cudaGetSymbolAddress((void**)&pAD3, g_AD3);
    cudaGetSymbolAddress((void**)&pAS3, g_AS3);
    cudaGetSymbolAddress((void**)&pAD2, g_AD2);
    cudaGetSymbolAddress((void**)&pVP, g_VP);
    cudaGetSymbolAddress((void**)&pCP, g_CP);
    cudaGetSymbolAddress((void**)&pCNT, g_CNT);

    cudaFuncSetAttribute(gemm_fp16_kernel,
                         cudaFuncAttributeMaxDynamicSharedMemorySize, SMEM_BYTES);

    const int EB = 256;
    dim3 gemmGrid((NVN + 127) / 128, 16);

    // launches 1-3, then GEMM at #4 (observed ncu window)
    split_kernel<<<(NVN * HD / 4 + EB - 1) / EB, EB>>>(x_var, pAhV, pAlV, NVN * HD / 4);
    split_kernel<<<(NCN * HD / 4 + EB - 1) / EB, EB>>>(x_con, pAhC, pAlC, NCN * HD / 4);
    wsplit_kernel<<<dim3(8, 8, 16), dim3(32, 8)>>>(W_src);

    gemm_fp16_kernel<<<gemmGrid, 256, SMEM_BYTES>>>(
        pAhV, pAlV, pAhC, pAlC, pWhT, pWlT, pXL0, pXL1, pXL2, pXL3);

    wsd_kernel<<<16, 256>>>(W_src, W_dst, att_src, att_dst);
    avec_var_kernel<<<(NVN * 32 + EB - 1) / EB, EB>>>(x_var);
    avec_con_kernel<<<(NCN * 32 + EB - 1) / EB, EB>>>(x_con);

    // CSR build
    zero_int_kernel<<<(NVN + 1 + EB - 1) / EB, EB>>>(pRP0, NVN + 1);
    zero_int_kernel<<<(NVN + 1 + EB - 1) / EB, EB>>>(pRP1, NVN + 1);
    zero_int_kernel<<<(NVN + 1 + EB - 1) / EB, EB>>>(pRP3, NVN + 1);
    zero_int_kernel<<<(NCN + 1 + EB - 1) / EB, EB>>>(pRP2, NCN + 1);
    hist_kernel<<<(EVVN + EB - 1) / EB, EB>>>(e_vv + EVVN, pRP0, EVVN);
    hist_kernel<<<(EVVN + EB - 1) / EB, EB>>>(e_vv_rev + EVVN, pRP1, EVVN);
    hist_kernel<<<(EVCN + EB - 1) / EB, EB>>>(e_cv + EVCN, pRP3, EVCN);
    hist_kernel<<<(EVCN + EB - 1) / EB, EB>>>(e_vc + EVCN, pRP2, EVCN);
    scan_kernel<<<1, 1024>>>(pRP0, pCU0, NVN);
    scan_kernel<<<1, 1024>>>(pRP1, pCU1, NVN);
    scan_kernel<<<1, 1024>>>(pRP3, pCU3, NVN);
    scan_kernel<<<1, 1024>>>(pRP2, pCU2, NCN);
    scatter_kernel<<<(EVVN + EB - 1) / EB, EB>>>(e_vv, e_vv + EVVN, pCU0, pCS0, EVVN);
    scatter_kernel<<<(EVVN + EB - 1) / EB, EB>>>(e_vv_rev, e_vv_rev + EVVN, pCU1, pCS1, EVVN);
    scatter_kernel<<<(EVCN + EB - 1) / EB, EB>>>(e_cv, e_cv + EVCN, pCU3, pCS3, EVCN);
    scatter_kernel<<<(EVCN + EB - 1) / EB, EB>>>(e_vc, e_vc + EVCN, pCU2, pCS2, EVCN);

    int gatVB = (NVN * 32 + EB - 1) / EB;
    int gatCB = (NCN * 32 + EB - 1) / EB;

    for (int l = 0; l < NLAYER; l++) {
        float* xv_out = pXV[l & 1];
        float* xc_out = pXC[l & 1];
        int do_next = (l + 1 < NLAYER) ? 1 : 0;
        int rv = (l & 1) * NVN, rc = (l & 1) * NCN;

        if (l > 0) {
            gemm_fp16_kernel<<<gemmGrid, 256, SMEM_BYTES>>>(
                pAhV, pAlV, pAhC, pAlC,
                pWhT + (size_t)(4 * l) * HD * HD, pWlT + (size_t)(4 * l) * HD * HD,
                pXL0, pXL1, pXL2, pXL3);
        }

        gat_var_pass_kernel<<<gatVB, EB>>>(pXL0, pRP0, pCS0, pAS0 + rv, pAD0 + rv,
                                           bias, l, xv_out, pAhV, pAlV, 0, do_next);
        gat_var_pass_kernel<<<gatVB, EB>>>(pXL1, pRP1, pCS1, pAS1 + rv, pAD1 + rv,
                                           bias, l, xv_out, pAhV, pAlV, 1, do_next);
        gat_var_pass_kernel<<<gatVB, EB>>>(pXL3, pRP3, pCS3, pAS3 + rc, pAD3 + rv,
                                           bias, l, xv_out, pAhV, pAlV, 2, do_next);
        gat_con_kernel<<<gatCB, EB>>>(pXL2, bias, l, xc_out, pAhC, pAlC, do_next);
    }

    zero_pool_kernel<<<GN, 256>>>();
    pool_kernel<<<gatVB, EB>>>(pXV[(NLAYER - 1) & 1], batch_var, NVN, pVP, pCNT);
    pool_kernel<<<gatCB, EB>>>(pXC[(NLAYER - 1) & 1], batch_con, NCN, pCP, pCNT + GN);
    finalize_kernel<<<GN, 256>>>(W_lin, b_lin, out);
}

// round 10
// speedup vs baseline: 1.6703x; 1.1502x over previous
#include <cuda_runtime.h>
#include <cuda_fp16.h>
#include <cstdint>
#include <cstddef>

#define NVN 50000
#define NCN 20000
#define HD  256
#define NLAYER 4
#define EVVN 500000
#define EVCN 300000
#define GN  64

#define ASTR 40
#define BK 32
#define NSTAGE 2
// halves: A stages 2*128*40*(h,l) + B stages 2*128*40*(h,l)
#define SMEM_HALVES (NSTAGE*128*ASTR*2 + NSTAGE*128*ASTR*2)
#define SMEM_BYTES  (SMEM_HALVES*2)

// ---------------- scratch ----------------
__device__ __align__(128) float g_XV0[NVN * HD];
__device__ __align__(128) float g_XV1[NVN * HD];
__device__ __align__(128) float g_XC0[NCN * HD];
__device__ __align__(128) float g_XC1[NCN * HD];
__device__ __align__(128) float g_XL0[NVN * HD];
__device__ __align__(128) float g_XL1[NVN * HD];
__device__ __align__(128) float g_XL2[NVN * HD];
__device__ __align__(128) float g_XL3[NCN * HD];

// fp16 hi/lo operand buffers
__device__ __align__(128) __half g_AhV[NVN * HD];
__device__ __align__(128) __half g_AlV[NVN * HD];
__device__ __align__(128) __half g_AhC[NCN * HD];
__device__ __align__(128) __half g_AlC[NCN * HD];
__device__ __align__(128) __half g_WhT[16 * HD * HD];  // [mat][n][k]
__device__ __align__(128) __half g_WlT[16 * HD * HD];

// double-buffered attention scalars: [parity][node]
__device__ float g_AS0[2 * NVN], g_AD0[2 * NVN];
__device__ float g_AS1[2 * NVN], g_AD1[2 * NVN];
__device__ float g_AS2[2 * NVN], g_AD3[2 * NVN];
__device__ float g_AS3[2 * NCN], g_AD2[2 * NCN];

__device__ __align__(128) float g_WS[16 * HD];
__device__ __align__(128) float g_WD[16 * HD];

__device__ int g_RP0[NVN + 1], g_RP1[NVN + 1], g_RP3[NVN + 1], g_RP2[NCN + 1];
__device__ int g_CU0[NVN], g_CU1[NVN], g_CU3[NVN], g_CU2[NCN];
__device__ int g_CS0[EVVN], g_CS1[EVVN], g_CS3[EVCN], g_CS2[EVCN];

__device__ __align__(128) float g_VP[GN * HD];
__device__ __align__(128) float g_CP[GN * HD];
__device__ int   g_CNT[2 * GN];

// ---------------- helpers ----------------
__device__ __forceinline__ void red4(float* p, float4 v) {
    asm volatile("red.global.add.v4.f32 [%0], {%1,%2,%3,%4};"
                 :: "l"(p), "f"(v.x), "f"(v.y), "f"(v.z), "f"(v.w) : "memory");
}
__device__ __forceinline__ void h2split(float x, __half& h, __half& l) {
    h = __float2half_rn(x);
    l = __float2half_rn(x - __half2float(h));
}
__device__ __forceinline__ void ldsm4(uint32_t* r, const void* p) {
    uint32_t addr = (uint32_t)__cvta_generic_to_shared(p);
    asm volatile("ldmatrix.sync.aligned.m8n8.x4.shared.b16 {%0,%1,%2,%3}, [%4];"
                 : "=r"(r[0]), "=r"(r[1]), "=r"(r[2]), "=r"(r[3]) : "r"(addr));
}
__device__ __forceinline__ void ldsm2(uint32_t* r, const void* p) {
    uint32_t addr = (uint32_t)__cvta_generic_to_shared(p);
    asm volatile("ldmatrix.sync.aligned.m8n8.x2.shared.b16 {%0,%1}, [%2];"
                 : "=r"(r[0]), "=r"(r[1]) : "r"(addr));
}
__device__ __forceinline__ void mma_f16(float* c, const uint32_t* a, const uint32_t* b) {
    asm volatile(
        "mma.sync.aligned.m16n8k16.row.col.f32.f16.f16.f32 "
        "{%0,%1,%2,%3}, {%4,%5,%6,%7}, {%8,%9}, {%0,%1,%2,%3};"
        : "+f"(c[0]), "+f"(c[1]), "+f"(c[2]), "+f"(c[3])
        : "r"(a[0]), "r"(a[1]), "r"(a[2]), "r"(a[3]), "r"(b[0]), "r"(b[1]));
}
__device__ __forceinline__ void cpa16(void* dst, const void* src, bool valid) {
    uint32_t d = (uint32_t)__cvta_generic_to_shared(dst);
    int sz = valid ? 16 : 0;
    asm volatile("cp.async.ca.shared.global [%0], [%1], 16, %2;"
                 :: "r"(d), "l"(src), "r"(sz));
}
__device__ __forceinline__ float d4(float4 a, float4 b) {
    return a.x * b.x + a.y * b.y + a.z * b.z + a.w * b.w;
}

// ---------------- ws/wd precompute ----------------
__global__ void wsd_kernel(const float* __restrict__ Wsrc, const float* __restrict__ Wdst,
                           const float* __restrict__ as, const float* __restrict__ ad) {
    int b = blockIdx.x;
    int i = threadIdx.x;
    __shared__ float sas[HD], sad[HD];
    sas[i] = as[b * HD + i];
    sad[i] = ad[b * HD + i];
    __syncthreads();
    const float* Ws = Wsrc + (size_t)b * HD * HD + (size_t)i * HD;
    const float* Wd = Wdst + (size_t)b * HD * HD + (size_t)i * HD;
    float s = 0.f, d = 0.f;
    #pragma unroll 8
    for (int j = 0; j < HD; j++) { s += Ws[j] * sas[j]; d += Wd[j] * sad[j]; }
    g_WS[b * HD + i] = s;
    g_WD[b * HD + i] = d;
}

// ---------------- activation split: fp32 -> (half hi, half lo) ----------------
__global__ void split_kernel(const float* __restrict__ X, __half* __restrict__ Xh,
                             __half* __restrict__ Xl, int n4) {
    int i = blockIdx.x * blockDim.x + threadIdx.x;
    if (i >= n4) return;
    float4 v = ((const float4*)X)[i];
    __half h0, h1, h2, h3, l0, l1, l2, l3;
    h2split(v.x, h0, l0); h2split(v.y, h1, l1);
    h2split(v.z, h2, l2); h2split(v.w, h3, l3);
    ((__half2*)Xh)[i * 2 + 0] = __halves2half2(h0, h1);
    ((__half2*)Xh)[i * 2 + 1] = __halves2half2(h2, h3);
    ((__half2*)Xl)[i * 2 + 0] = __halves2half2(l0, l1);
    ((__half2*)Xl)[i * 2 + 1] = __halves2half2(l2, l3);
}

// ---------------- W transpose + split: W[mat][k][n] -> WhT/WlT[mat][n][k] -------
__global__ void wsplit_kernel(const float* __restrict__ W) {
    __shared__ float tile[32][33];
    int mat = blockIdx.z;
    int bk = blockIdx.x * 32, bn = blockIdx.y * 32;
    int tx = threadIdx.x, ty = threadIdx.y;   // (32, 8)
    const float* Wm = W + (size_t)mat * HD * HD;
    #pragma unroll
    for (int r = 0; r < 32; r += 8)
        tile[ty + r][tx] = Wm[(size_t)(bk + ty + r) * HD + bn + tx];
    __syncthreads();
    #pragma unroll
    for (int r = 0; r < 32; r += 8) {
        float x = tile[tx][ty + r];
        __half h, l;
        h2split(x, h, l);
        size_t o = (size_t)mat * HD * HD + (size_t)(bn + ty + r) * HD + bk + tx;
        g_WhT[o] = h;
        g_WlT[o] = l;
    }
}

// ---------------- fp16x3 GEMM, 128x128 tile, 2-stage, B via ldmatrix ----------
// grid.y = 8: mat = y>>1 (0-2 var, 3 con), col0 = (y&1)*128
__global__ __launch_bounds__(256, 2) void gemm_fp16_kernel(
        const __half* __restrict__ AhV, const __half* __restrict__ AlV,
        const __half* __restrict__ AhC, const __half* __restrict__ AlC,
        const __half* __restrict__ WhT, const __half* __restrict__ WlT,
        float* __restrict__ C0, float* __restrict__ C1,
        float* __restrict__ C2, float* __restrict__ C3) {
    extern __shared__ __half smh[];
    __half* pAh = smh;
    __half* pAl = pAh + NSTAGE * 128 * ASTR;
    __half* pBh = pAl + NSTAGE * 128 * ASTR;
    __half* pBl = pBh + NSTAGE * 128 * ASTR;

    const int mat = blockIdx.y >> 1;
    const int N = (mat == 3) ? NCN : NVN;
    const int row0 = blockIdx.x * 128;
    if (row0 >= N) return;
    const __half* Ah = (mat == 3) ? AhC : AhV;
    const __half* Al = (mat == 3) ? AlC : AlV;
    float* C = (mat == 0) ? C0 : (mat == 1) ? C1 : (mat == 2) ? C2 : C3;
    const int col0 = (blockIdx.y & 1) * 128;
    const __half* W_h = WhT + (size_t)mat * HD * HD;
    const __half* W_l = WlT + (size_t)mat * HD * HD;

    const int tid = threadIdx.x;
    const int lane = tid & 31;
    const int wid = tid >> 5;
    const int wm = (wid & 3) * 32;     // 4 m-warps
    const int wn = (wid >> 2) * 64;    // 2 n-warps, 64-wide tiles

    const int arow = tid >> 1;         // 0..127
    const int acol = (tid & 1) * 16;   // half-offset 0 or 16

    float acc[2][8][4];
    #pragma unroll
    for (int i = 0; i < 2; i++)
        #pragma unroll
        for (int j = 0; j < 8; j++)
            #pragma unroll
            for (int q = 0; q < 4; q++) acc[i][j][q] = 0.f;

    const int g = lane >> 2, t4 = lane & 3;
    const int lr = lane & 15;
    const int lk = (lane >> 4) * 8;
    const int br = lane & 7;                 // B ldmatrix row within tile
    const int bko = ((lane >> 3) & 1) * 8;   // B tile1 k offset

    auto load_stage = [&](int s, int k0) {
        bool v = (row0 + arow) < N;
        const __half* ah = v ? (Ah + (size_t)(row0 + arow) * HD + k0 + acol) : Ah;
        const __half* al = v ? (Al + (size_t)(row0 + arow) * HD + k0 + acol) : Al;
        __half* dh = pAh + s * 128 * ASTR + arow * ASTR + acol;
        __half* dl = pAl + s * 128 * ASTR + arow * ASTR + acol;
        cpa16(dh,     ah,     v);
        cpa16(dh + 8, ah + 8, v);
        cpa16(dl,     al,     v);
        cpa16(dl + 8, al + 8, v);
        // B: 128 n rows x 32 k halves
        __half* eh = pBh + s * 128 * ASTR + arow * ASTR + acol;
        __half* el = pBl + s * 128 * ASTR + arow * ASTR + acol;
        const __half* wh = W_h + (size_t)(col0 + arow) * HD + k0 + acol;
        const __half* wl = W_l + (size_t)(col0 + arow) * HD + k0 + acol;
        cpa16(eh,     wh,     true);
        cpa16(eh + 8, wh + 8, true);
        cpa16(el,     wl,     true);
        cpa16(el + 8, wl + 8, true);
        asm volatile("cp.async.commit_group;");
    };

    load_stage(0, 0);

    for (int kt = 0; kt < 8; kt++) {
        asm volatile("cp.async.wait_group 0;");
        __syncthreads();
        if (kt + 1 < 8) load_stage((kt + 1) & 1, (kt + 1) * BK);

        const int cur = kt & 1;
        const __half* cAh = pAh + cur * 128 * ASTR;
        const __half* cAl = pAl + cur * 128 * ASTR;
        const __half* cBh = pBh + cur * 128 * ASTR;
        const __half* cBl = pBl + cur * 128 * ASTR;

        #pragma unroll
        for (int ks = 0; ks < 2; ks++) {
            const int kb = ks * 16;
            uint32_t ah[2][4], al[2][4];
            #pragma unroll
            for (int i = 0; i < 2; i++) {
                ldsm4(ah[i], cAh + (size_t)(wm + i * 16 + lr) * ASTR + kb + lk);
                ldsm4(al[i], cAl + (size_t)(wm + i * 16 + lr) * ASTR + kb + lk);
            }
            #pragma unroll
            for (int j = 0; j < 8; j++) {
                uint32_t bh[2], bl[2];
                const __half* bp = cBh + (size_t)(wn + j * 8 + br) * ASTR + kb + bko;
                ldsm2(bh, bp);
                const __half* bq = cBl + (size_t)(wn + j * 8 + br) * ASTR + kb + bko;
                ldsm2(bl, bq);
                #pragma unroll
                for (int i = 0; i < 2; i++) {
                    mma_f16(acc[i][j], ah[i], bh);
                    mma_f16(acc[i][j], ah[i], bl);
                    mma_f16(acc[i][j], al[i], bh);
                }
            }
        }
    }

    #pragma unroll
    for (int i = 0; i < 2; i++) {
        int r0 = row0 + wm + i * 16 + g;
        #pragma unroll
        for (int j = 0; j < 8; j++) {
            int c = col0 + wn + j * 8 + t4 * 2;
            if (r0 < N)
                *(float2*)(C + (size_t)r0 * HD + c) = make_float2(acc[i][j][0], acc[i][j][1]);
            if (r0 + 8 < N)
                *(float2*)(C + (size_t)(r0 + 8) * HD + c) = make_float2(acc[i][j][2], acc[i][j][3]);
        }
    }
}

// ---------------- standalone attention dots (layer 0 only) ----------------
__global__ void avec_var_kernel(const float* __restrict__ xv) {
    __shared__ float sv[6][HD];
    int t = threadIdx.x;
    sv[0][t] = g_WS[0 * HD + t];
    sv[1][t] = g_WD[0 * HD + t];
    sv[2][t] = g_WS[1 * HD + t];
    sv[3][t] = g_WD[1 * HD + t];
    sv[4][t] = g_WS[2 * HD + t];
    sv[5][t] = g_WD[3 * HD + t];
    __syncthreads();
    int w = (blockIdx.x * blockDim.x + t) >> 5;
    int lane = t & 31;
    if (w >= NVN) return;
    const float* row = xv + (size_t)w * HD;
    float s[6] = {0, 0, 0, 0, 0, 0};
    #pragma unroll
    for (int j0 = 0; j0 < HD; j0 += 32) {
        float x = row[j0 + lane];
        #pragma unroll
        for (int k = 0; k < 6; k++) s[k] += x * sv[k][j0 + lane];
    }
    #pragma unroll
    for (int k = 0; k < 6; k++)
        #pragma unroll
        for (int o = 16; o > 0; o >>= 1) s[k] += __shfl_xor_sync(0xffffffffu, s[k], o);
    if (lane == 0) {
        g_AS0[w] = s[0]; g_AD0[w] = s[1];
        g_AS1[w] = s[2]; g_AD1[w] = s[3];
        g_AS2[w] = s[4]; g_AD3[w] = s[5];
    }
}

__global__ void avec_con_kernel(const float* __restrict__ xc) {
    __shared__ float sv[2][HD];
    int t = threadIdx.x;
    sv[0][t] = g_WD[2 * HD + t];
    sv[1][t] = g_WS[3 * HD + t];
    __syncthreads();
    int w = (blockIdx.x * blockDim.x + t) >> 5;
    int lane = t & 31;
    if (w >= NCN) return;
    const float* row = xc + (size_t)w * HD;
    float s0 = 0.f, s1 = 0.f;
    #pragma unroll
    for (int j0 = 0; j0 < HD; j0 += 32) {
        float x = row[j0 + lane];
        s0 += x * sv[0][j0 + lane];
        s1 += x * sv[1][j0 + lane];
    }
    #pragma unroll
    for (int o = 16; o > 0; o >>= 1) {
        s0 += __shfl_xor_sync(0xffffffffu, s0, o);
        s1 += __shfl_xor_sync(0xffffffffu, s1, o);
    }
    if (lane == 0) { g_AD2[w] = s0; g_AS3[w] = s1; }
}

// ---------------- CSR build ----------------
__global__ void zero_int_kernel(int* __restrict__ p, int n) {
    int i = blockIdx.x * blockDim.x + threadIdx.x;
    if (i < n) p[i] = 0;
}
__global__ void hist_kernel(const int* __restrict__ dst, int* __restrict__ cnt, int E) {
    int i = blockIdx.x * blockDim.x + threadIdx.x;
    if (i < E) atomicAdd(&cnt[dst[i]], 1);
}
__global__ void scan_kernel(int* __restrict__ rp, int* __restrict__ cursor, int n) {
    __shared__ int swarp[32];
    __shared__ int stot;
    int t = threadIdx.x, w = t >> 5, lane = t & 31;
    int carry = 0;
    for (int base = 0; base < n; base += 1024) {
        int idx = base + t;
        int v = (idx < n) ? rp[idx] : 0;
        int x = v;
        #pragma unroll
        for (int o = 1; o < 32; o <<= 1) {
            int y = __shfl_up_sync(0xffffffffu, x, o);
            if (lane >= o) x += y;
        }
        if (lane == 31) swarp[w] = x;
        __syncthreads();
        if (w == 0) {
            int s = swarp[lane];
            int z = s;
            #pragma unroll
            for (int o = 1; o < 32; o <<= 1) {
                int y = __shfl_up_sync(0xffffffffu, z, o);
                if (lane >= o) z += y;
            }
            swarp[lane] = z - s;
            if (lane == 31) stot = z;
        }
        __syncthreads();
        int excl = carry + swarp[w] + (x - v);
        if (idx < n) { rp[idx] = excl; cursor[idx] = excl; }
        carry += stot;
        __syncthreads();
    }
    if (t == 0) rp[n] = carry;
}
__global__ void scatter_kernel(const int* __restrict__ src, const int* __restrict__ dst,
                               int* __restrict__ cursor, int* __restrict__ cs, int E) {
    int i = blockIdx.x * blockDim.x + threadIdx.x;
    if (i >= E) return;
    int pos = atomicAdd(&cursor[dst[i]], 1);
    cs[pos] = src[i];
}

// ---------------- fused GAT ----------------
__device__ __forceinline__ void gat_accum(
        int d, int lane,
        const int* __restrict__ rp, const int* __restrict__ cs,
        const float* __restrict__ AS, const float* __restrict__ AD,
        const float* __restrict__ XL,
        float4& acc0, float4& acc1) {
    int off = rp[d];
    int deg = rp[d + 1] - off;
    if (deg <= 0) return;
    float adv = AD[d];
    float m = -1e30f;
    for (int j = lane; j < deg; j += 32) {
        int s = cs[off + j];
        float e = AS[s] + adv;
        e = (e >= 0.f) ? e : 0.2f * e;
        m = fmaxf(m, e);
    }
    #pragma unroll
    for (int o = 16; o > 0; o >>= 1) m = fmaxf(m, __shfl_xor_sync(0xffffffffu, m, o));
    float den = 0.f;
    for (int j = lane; j < deg; j += 32) {
        int s = cs[off + j];
        float e = AS[s] + adv;
        e = (e >= 0.f) ? e : 0.2f * e;
        den += __expf(e - m);
    }
    #pragma unroll
    for (int o = 16; o > 0; o >>= 1) den += __shfl_xor_sync(0xffffffffu, den, o);
    float invden = 1.f / (den + 1e-16f);
    #pragma unroll 4
    for (int j = 0; j < deg; j++) {
        int s = cs[off + j];
        float e = AS[s] + adv;
        e = (e >= 0.f) ? e : 0.2f * e;
        float wgt = __expf(e - m) * invden;
        const float4* xs = (const float4*)(XL + (size_t)s * HD);
        float4 v0 = xs[lane];
        float4 v1 = xs[32 + lane];
        acc0.x += wgt * v0.x; acc0.y += wgt * v0.y; acc0.z += wgt * v0.z; acc0.w += wgt * v0.w;
        acc1.x += wgt * v1.x; acc1.y += wgt * v1.y; acc1.z += wgt * v1.z; acc1.w += wgt * v1.w;
    }
}

__device__ __forceinline__ void split_store(__half* outh, __half* outl, int w, int lane,
                                            float4 acc0, float4 acc1) {
    __half h0, h1, h2, h3, l0, l1, l2, l3;
    __half2* oh = (__half2*)(outh + (size_t)w * HD);
    __half2* ol = (__half2*)(outl + (size_t)w * HD);
    h2split(acc0.x, h0, l0); h2split(acc0.y, h1, l1);
    h2split(acc0.z, h2, l2); h2split(acc0.w, h3, l3);
    oh[lane * 2 + 0] = __halves2half2(h0, h1);
    oh[lane * 2 + 1] = __halves2half2(h2, h3);
    ol[lane * 2 + 0] = __halves2half2(l0, l1);
    ol[lane * 2 + 1] = __halves2half2(l2, l3);
    h2split(acc1.x, h0, l0); h2split(acc1.y, h1, l1);
    h2split(acc1.z, h2, l2); h2split(acc1.w, h3, l3);
    oh[(32 + lane) * 2 + 0] = __halves2half2(h0, h1);
    oh[(32 + lane) * 2 + 1] = __halves2half2(h2, h3);
    ol[(32 + lane) * 2 + 0] = __halves2half2(l0, l1);
    ol[(32 + lane) * 2 + 1] = __halves2half2(l2, l3);
}

// one CSR per pass. mode: 0=first (init with 3 biases), 1=middle, 2=last(+epilogue)
__global__ void gat_var_pass_kernel(const float* __restrict__ XL,
                                    const int* __restrict__ rp, const int* __restrict__ cs,
                                    const float* __restrict__ AS, const float* __restrict__ AD,
                                    const float* __restrict__ bias, int l,
                                    float* __restrict__ out,
                                    __half* __restrict__ outh, __half* __restrict__ outl,
                                    int mode, int do_next) {
    int w = (blockIdx.x * blockDim.x + threadIdx.x) >> 5;
    int lane = threadIdx.x & 31;
    if (w >= NVN) return;
    float4 acc0, acc1;
    float4* ob = (float4*)(out + (size_t)w * HD);
    if (mode == 0) {
        const float4* b0 = (const float4*)(bias + (size_t)(4 * l + 0) * HD);
        const float4* b1 = (const float4*)(bias + (size_t)(4 * l + 1) * HD);
        const float4* b3 = (const float4*)(bias + (size_t)(4 * l + 3) * HD);
        float4 x0 = b0[lane], y0 = b1[lane], z0 = b3[lane];
        float4 x1 = b0[32 + lane], y1 = b1[32 + lane], z1 = b3[32 + lane];
        acc0 = make_float4(x0.x + y0.x + z0.x, x0.y + y0.y + z0.y,
                           x0.z + y0.z + z0.z, x0.w + y0.w + z0.w);
        acc1 = make_float4(x1.x + y1.x + z1.x, x1.y + y1.y + z1.y,
                           x1.z + y1.z + z1.z, x1.w + y1.w + z1.w);
    } else {
        acc0 = ob[lane];
        acc1 = ob[32 + lane];
    }
    gat_accum(w, lane, rp, cs, AS, AD, XL, acc0, acc1);
    ob[lane] = acc0;
    ob[32 + lane] = acc1;
    if (mode != 2 || !do_next) return;
    split_store(outh, outl, w, lane, acc0, acc1);
    int L = l + 1;
    int wv = ((l + 1) & 1) * NVN;
    float s[6];
    const int vidx[6] = {0, 0, 1, 1, 2, 3};
    #pragma unroll
    for (int k = 0; k < 6; k++) {
        const float* vecb = (k == 1 || k == 3 || k == 5) ? g_WD : g_WS;
        const float4* vp = (const float4*)(vecb + (size_t)(4 * L + vidx[k]) * HD);
        s[k] = d4(acc0, vp[lane]) + d4(acc1, vp[32 + lane]);
    }
    #pragma unroll
    for (int k = 0; k < 6; k++)
        #pragma unroll
        for (int o = 16; o > 0; o >>= 1) s[k] += __shfl_xor_sync(0xffffffffu, s[k], o);
    if (lane == 0) {
        g_AS0[wv + w] = s[0]; g_AD0[wv + w] = s[1];
        g_AS1[wv + w] = s[2]; g_AD1[wv + w] = s[3];
        g_AS2[wv + w] = s[4]; g_AD3[wv + w] = s[5];
    }
}

__global__ void gat_con_kernel(const float* __restrict__ XL2,
                               const float* __restrict__ bias, int l,
                               float* __restrict__ out,
                               __half* __restrict__ outh, __half* __restrict__ outl,
                               int do_next) {
    int w = (blockIdx.x * blockDim.x + threadIdx.x) >> 5;
    int lane = threadIdx.x & 31;
    if (w >= NCN) return;
    int rc = (l & 1) * NCN;
    float4 acc0 = make_float4(0.f, 0.f, 0.f, 0.f);
    float4 acc1 = make_float4(0.f, 0.f, 0.f, 0.f);
    gat_accum(w, lane, g_RP2, g_CS2, g_AS2 + (l & 1) * NVN, g_AD2 + rc, XL2, acc0, acc1);
    const float4* b2 = (const float4*)(bias + (size_t)(4 * l + 2) * HD);
    float4 x0 = b2[lane], x1 = b2[32 + lane];
    acc0.x += x0.x; acc0.y += x0.y; acc0.z += x0.z; acc0.w += x0.w;
    acc1.x += x1.x; acc1.y += x1.y; acc1.z += x1.z; acc1.w += x1.w;
    float4* ob = (float4*)(out + (size_t)w * HD);
    ob[lane] = acc0;
    ob[32 + lane] = acc1;
    if (!do_next) return;
    split_store(outh, outl, w, lane, acc0, acc1);
    int L = l + 1;
    int wc = ((l + 1) & 1) * NCN;
    const float4* v0 = (const float4*)(g_WD + (size_t)(4 * L + 2) * HD);
    const float4* v1 = (const float4*)(g_WS + (size_t)(4 * L + 3) * HD);
    float s0 = d4(acc0, v0[lane]) + d4(acc1, v0[32 + lane]);
    float s1 = d4(acc0, v1[lane]) + d4(acc1, v1[32 + lane]);
    #pragma unroll
    for (int o = 16; o > 0; o >>= 1) {
        s0 += __shfl_xor_sync(0xffffffffu, s0, o);
        s1 += __shfl_xor_sync(0xffffffffu, s1, o);
    }
    if (lane == 0) { g_AD2[wc + w] = s0; g_AS3[wc + w] = s1; }
}

// ---------------- pooling + head ----------------
__global__ void zero_pool_kernel() {
    int i = blockIdx.x * 256 + threadIdx.x;
    g_VP[i] = 0.f;
    g_CP[i] = 0.f;
    if (i < 2 * GN) g_CNT[i] = 0;
}

__global__ void pool_kernel(const float* __restrict__ X, const int* __restrict__ batch,
                            int N, float* __restrict__ S, int* __restrict__ cnt) {
    int w = (blockIdx.x * blockDim.x + threadIdx.x) >> 5;
    int lane = threadIdx.x & 31;
    if (w >= N) return;
    int g = batch[w];
    if (lane == 0) atomicAdd(&cnt[g], 1);
    const float4* xr = (const float4*)(X + (size_t)w * HD);
    float* sb = S + (size_t)g * HD;
    #pragma unroll
    for (int j = 0; j < 2; j++) {
        int idx = lane + 32 * j;
        red4(sb + 4 * idx, xr[idx]);
    }
}

__global__ void finalize_kernel(const float* __restrict__ Wlin, const float* __restrict__ blin,
                                float* __restrict__ out) {
    int g = blockIdx.x, t = threadIdx.x;
    float cv = (float)max(g_CNT[g], 1);
    float cc = (float)max(g_CNT[GN + g], 1);
    float a = g_VP[g * HD + t] / cv;
    float c = g_CP[g * HD + t] / cc;
    float p0 = a * Wlin[t * 2 + 0] + c * Wlin[(HD + t) * 2 + 0];
    float p1 = a * Wlin[t * 2 + 1] + c * Wlin[(HD + t) * 2 + 1];
    __shared__ float s0[256], s1[256];
    s0[t] = p0; s1[t] = p1;
    __syncthreads();
    for (int o = 128; o > 0; o >>= 1) {
        if (t < o) { s0[t] += s0[t + o]; s1[t] += s1[t + o]; }
        __syncthreads();
    }
    if (t == 0) {
        float z0 = s0[0] + blin[0], z1 = s1[0] + blin[1];
        float m = fmaxf(z0, z1);
        float e0 = expf(z0 - m), e1 = expf(z1 - m);
        float inv = 1.f / (e0 + e1);
        out[2 * g + 0] = e0 * inv;
        out[2 * g + 1] = e1 * inv;
    }
}

// ---------------- host ----------------
extern "C" void kernel_launch(void* const* d_in, const int* in_sizes, int n_in,
                              void* d_out, int out_size) {
    const float* x_var   = (const float*)d_in[0];
    const float* x_con   = (const float*)d_in[1];
    const float* W_src   = (const float*)d_in[2];
    const float* W_dst   = (const float*)d_in[3];
    const float* att_src = (const float*)d_in[4];
    const float* att_dst = (const float*)d_in[5];
    const float* bias    = (const float*)d_in[6];
    const float* W_lin   = (const float*)d_in[7];
    const float* b_lin   = (const float*)d_in[8];
    const int* e_vv      = (const int*)d_in[9];
    const int* e_vv_rev  = (const int*)d_in[10];
    const int* e_vc      = (const int*)d_in[11];
    const int* e_cv      = (const int*)d_in[12];
    const int* batch_var = (const int*)d_in[13];
    const int* batch_con = (const int*)d_in[14];
    float* out = (float*)d_out;

    float *pXV[2], *pXC[2], *pXL0, *pXL1, *pXL2, *pXL3, *pVP, *pCP;
    __half *pAhV, *pAlV, *pAhC, *pAlC, *pWhT, *pWlT;
    int *pRP0, *pRP1, *pRP2, *pRP3, *pCU0, *pCU1, *pCU2, *pCU3;
    int *pCS0, *pCS1, *pCS2, *pCS3, *pCNT;
    float *pAS0, *pAD0, *pAS1, *pAD1, *pAS2, *pAD3, *pAS3, *pAD2;
    cudaGetSymbolAddress((void**)&pXV[0], g_XV0);
    cudaGetSymbolAddress((void**)&pXV[1], g_XV1);
    cudaGetSymbolAddress((void**)&pXC[0], g_XC0);
    cudaGetSymbolAddress((void**)&pXC[1], g_XC1);
    cudaGetSymbolAddress((void**)&pXL0, g_XL0);
    cudaGetSymbolAddress((void**)&pXL1, g_XL1);
    cudaGetSymbolAddress((void**)&pXL2, g_XL2);
    cudaGetSymbolAddress((void**)&pXL3, g_XL3);
    cudaGetSymbolAddress((void**)&pAhV, g_AhV);
    cudaGetSymbolAddress((void**)&pAlV, g_AlV);
    cudaGetSymbolAddress((void**)&pAhC, g_AhC);
    cudaGetSymbolAddress((void**)&pAlC, g_AlC);
    cudaGetSymbolAddress((void**)&pWhT, g_WhT);
    cudaGetSymbolAddress((void**)&pWlT, g_WlT);
    cudaGetSymbolAddress((void**)&pRP0, g_RP0);
    cudaGetSymbolAddress((void**)&pRP1, g_RP1);
    cudaGetSymbolAddress((void**)&pRP2, g_RP2);
    cudaGetSymbolAddress((void**)&pRP3, g_RP3);
    cudaGetSymbolAddress((void**)&pCU0, g_CU0);
    cudaGetSymbolAddress((void**)&pCU1, g_CU1);
    cudaGetSymbolAddress((void**)&pCU2, g_CU2);
    cudaGetSymbolAddress((void**)&pCU3, g_CU3);
    cudaGetSymbolAddress((void**)&pCS0, g_CS0);
    cudaGetSymbolAddress((void**)&pCS1, g_CS1);
    cudaGetSymbolAddress((void**)&pCS2, g_CS2);
    cudaGetSymbolAddress((void**)&pCS3, g_CS3);
    cudaGetSymbolAddress((void**)&pAS0, g_AS0);
    cudaGetSymbolAddress((void**)&pAD0, g_AD0);
    cudaGetSymbolAddress((void**)&pAS1, g_AS1);
    cudaGetSymbolAddress((void**)&pAD1, g_AD1);
    cudaGetSymbolAddress((void**)&pAS2, g_AS2);
    cudaGetSymbolAddress((void**)&pAD3, g_AD3);
    cudaGetSymbolAddress((void**)&pAS3, g_AS3);
    cudaGetSymbolAddress((void**)&pAD2, g_AD2);
    cudaGetSymbolAddress((void**)&pVP, g_VP);
    cudaGetSymbolAddress((void**)&pCP, g_CP);
    cudaGetSymbolAddress((void**)&pCNT, g_CNT);

    cudaFuncSetAttribute(gemm_fp16_kernel,
                         cudaFuncAttributeMaxDynamicSharedMemorySize, SMEM_BYTES);

    const int EB = 256;
    dim3 gemmGrid((NVN + 127) / 128, 8);   // mat = y>>1, col block = y&1

    // launches 1-3, then GEMM at #4 (observed ncu window)
    split_kernel<<<(NVN * HD / 4 + EB - 1) / EB, EB>>>(x_var, pAhV, pAlV, NVN * HD / 4);
    split_kernel<<<(NCN * HD / 4 + EB - 1) / EB, EB>>>(x_con, pAhC, pAlC, NCN * HD / 4);
    wsplit_kernel<<<dim3(8, 8, 16), dim3(32, 8)>>>(W_src);

    gemm_fp16_kernel<<<gemmGrid, 256, SMEM_BYTES>>>(
        pAhV, pAlV, pAhC, pAlC, pWhT, pWlT, pXL0, pXL1, pXL2, pXL3);

    wsd_kernel<<<16, 256>>>(W_src, W_dst, att_src, att_dst);
    avec_var_kernel<<<(NVN * 32 + EB - 1) / EB, EB>>>(x_var);
    avec_con_kernel<<<(NCN * 32 + EB - 1) / EB, EB>>>(x_con);

    // CSR build
    zero_int_kernel<<<(NVN + 1 + EB - 1) / EB, EB>>>(pRP0, NVN + 1);
    zero_int_kernel<<<(NVN + 1 + EB - 1) / EB, EB>>>(pRP1, NVN + 1);
    zero_int_kernel<<<(NVN + 1 + EB - 1) / EB, EB>>>(pRP3, NVN + 1);
    zero_int_kernel<<<(NCN + 1 + EB - 1) / EB, EB>>>(pRP2, NCN + 1);
    hist_kernel<<<(EVVN + EB - 1) / EB, EB>>>(e_vv + EVVN, pRP0, EVVN);
    hist_kernel<<<(EVVN + EB - 1) / EB, EB>>>(e_vv_rev + EVVN, pRP1, EVVN);
    hist_kernel<<<(EVCN + EB - 1) / EB, EB>>>(e_cv + EVCN, pRP3, EVCN);
    hist_kernel<<<(EVCN + EB - 1) / EB, EB>>>(e_vc + EVCN, pRP2, EVCN);
    scan_kernel<<<1, 1024>>>(pRP0, pCU0, NVN);
    scan_kernel<<<1, 1024>>>(pRP1, pCU1, NVN);
    scan_kernel<<<1, 1024>>>(pRP3, pCU3, NVN);
    scan_kernel<<<1, 1024>>>(pRP2, pCU2, NCN);
    scatter_kernel<<<(EVVN + EB - 1) / EB, EB>>>(e_vv, e_vv + EVVN, pCU0, pCS0, EVVN);
    scatter_kernel<<<(EVVN + EB - 1) / EB, EB>>>(e_vv_rev, e_vv_rev + EVVN, pCU1, pCS1, EVVN);
    scatter_kernel<<<(EVCN + EB - 1) / EB, EB>>>(e_cv, e_cv + EVCN, pCU3, pCS3, EVCN);
    scatter_kernel<<<(EVCN + EB - 1) / EB, EB>>>(e_vc, e_vc + EVCN, pCU2, pCS2, EVCN);

    int gatVB = (NVN * 32 + EB - 1) / EB;
    int gatCB = (NCN * 32 + EB - 1) / EB;

    for (int l = 0; l < NLAYER; l++) {
        float* xv_out = pXV[l & 1];
        float* xc_out = pXC[l & 1];
        int do_next = (l + 1 < NLAYER) ? 1 : 0;
        int rv = (l & 1) * NVN, rc = (l & 1) * NCN;

        if (l > 0) {
            gemm_fp16_kernel<<<gemmGrid, 256, SMEM_BYTES>>>(
                pAhV, pAlV, pAhC, pAlC,
                pWhT + (size_t)(4 * l) * HD * HD, pWlT + (size_t)(4 * l) * HD * HD,
                pXL0, pXL1, pXL2, pXL3);
        }

        gat_var_pass_kernel<<<gatVB, EB>>>(pXL0, pRP0, pCS0, pAS0 + rv, pAD0 + rv,
                                           bias, l, xv_out, pAhV, pAlV, 0, do_next);
        gat_var_pass_kernel<<<gatVB, EB>>>(pXL1, pRP1, pCS1, pAS1 + rv, pAD1 + rv,
                                           bias, l, xv_out, pAhV, pAlV, 1, do_next);
        gat_var_pass_kernel<<<gatVB, EB>>>(pXL3, pRP3, pCS3, pAS3 + rc, pAD3 + rv,
                                           bias, l, xv_out, pAhV, pAlV, 2, do_next);
        gat_con_kernel<<<gatCB, EB>>>(pXL2, bias, l, xc_out, pAhC, pAlC, do_next);
    }

    zero_pool_kernel<<<GN, 256>>>();
    pool_kernel<<<gatVB, EB>>>(pXV[(NLAYER - 1) & 1], batch_var, NVN, pVP, pCNT);
    pool_kernel<<<gatCB, EB>>>(pXC[(NLAYER - 1) & 1], batch_con, NCN, pCP, pCNT + GN);
    finalize_kernel<<<GN, 256>>>(W_lin, b_lin, out);
}

// round 11
// speedup vs baseline: 1.7544x; 1.0503x over previous
#include <cuda_runtime.h>
#include <cuda_fp16.h>
#include <cstdint>
#include <cstddef>

#define NVN 50000
#define NCN 20000
#define HD  256
#define NLAYER 4
#define EVVN 500000
#define EVCN 300000
#define GN  64

#define ASTR 40
#define BK 32
#define NSTAGE 2
#define SMEM_HALVES (NSTAGE*128*ASTR*2 + NSTAGE*128*ASTR*2)
#define SMEM_BYTES  (SMEM_HALVES*2)

// ---------------- scratch ----------------
__device__ __align__(128) float g_XV0[NVN * HD];
__device__ __align__(128) float g_XV1[NVN * HD];
__device__ __align__(128) float g_XC0[NCN * HD];
__device__ __align__(128) float g_XC1[NCN * HD];
// XL now fp16 (gather payload halved)
__device__ __align__(128) __half g_XL0[NVN * HD];
__device__ __align__(128) __half g_XL1[NVN * HD];
__device__ __align__(128) __half g_XL2[NVN * HD];
__device__ __align__(128) __half g_XL3[NCN * HD];

// fp16 hi/lo operand buffers
__device__ __align__(128) __half g_AhV[NVN * HD];
__device__ __align__(128) __half g_AlV[NVN * HD];
__device__ __align__(128) __half g_AhC[NCN * HD];
__device__ __align__(128) __half g_AlC[NCN * HD];
__device__ __align__(128) __half g_WhT[16 * HD * HD];  // [mat][n][k]
__device__ __align__(128) __half g_WlT[16 * HD * HD];

// double-buffered attention scalars: [parity][node]
__device__ float g_AS0[2 * NVN], g_AD0[2 * NVN];
__device__ float g_AS1[2 * NVN], g_AD1[2 * NVN];
__device__ float g_AS2[2 * NVN], g_AD3[2 * NVN];
__device__ float g_AS3[2 * NCN], g_AD2[2 * NCN];

__device__ __align__(128) float g_WS[16 * HD];
__device__ __align__(128) float g_WD[16 * HD];

__device__ int g_RP0[NVN + 1], g_RP1[NVN + 1], g_RP3[NVN + 1], g_RP2[NCN + 1];
__device__ int g_CU0[NVN], g_CU1[NVN], g_CU3[NVN], g_CU2[NCN];
__device__ int g_CS0[EVVN], g_CS1[EVVN], g_CS3[EVCN], g_CS2[EVCN];

__device__ __align__(128) float g_VP[GN * HD];
__device__ __align__(128) float g_CP[GN * HD];
__device__ int   g_CNT[2 * GN];

// ---------------- helpers ----------------
__device__ __forceinline__ void red4(float* p, float4 v) {
    asm volatile("red.global.add.v4.f32 [%0], {%1,%2,%3,%4};"
                 :: "l"(p), "f"(v.x), "f"(v.y), "f"(v.z), "f"(v.w) : "memory");
}
__device__ __forceinline__ void h2split(float x, __half& h, __half& l) {
    h = __float2half_rn(x);
    l = __float2half_rn(x - __half2float(h));
}
__device__ __forceinline__ void ldsm4(uint32_t* r, const void* p) {
    uint32_t addr = (uint32_t)__cvta_generic_to_shared(p);
    asm volatile("ldmatrix.sync.aligned.m8n8.x4.shared.b16 {%0,%1,%2,%3}, [%4];"
                 : "=r"(r[0]), "=r"(r[1]), "=r"(r[2]), "=r"(r[3]) : "r"(addr));
}
__device__ __forceinline__ void ldsm2(uint32_t* r, const void* p) {
    uint32_t addr = (uint32_t)__cvta_generic_to_shared(p);
    asm volatile("ldmatrix.sync.aligned.m8n8.x2.shared.b16 {%0,%1}, [%2];"
                 : "=r"(r[0]), "=r"(r[1]) : "r"(addr));
}
__device__ __forceinline__ void mma_f16(float* c, const uint32_t* a, const uint32_t* b) {
    asm volatile(
        "mma.sync.aligned.m16n8k16.row.col.f32.f16.f16.f32 "
        "{%0,%1,%2,%3}, {%4,%5,%6,%7}, {%8,%9}, {%0,%1,%2,%3};"
        : "+f"(c[0]), "+f"(c[1]), "+f"(c[2]), "+f"(c[3])
        : "r"(a[0]), "r"(a[1]), "r"(a[2]), "r"(a[3]), "r"(b[0]), "r"(b[1]));
}
__device__ __forceinline__ void cpa16(void* dst, const void* src, bool valid) {
    uint32_t d = (uint32_t)__cvta_generic_to_shared(dst);
    int sz = valid ? 16 : 0;
    asm volatile("cp.async.ca.shared.global [%0], [%1], 16, %2;"
                 :: "r"(d), "l"(src), "r"(sz));
}
__device__ __forceinline__ float d4(float4 a, float4 b) {
    return a.x * b.x + a.y * b.y + a.z * b.z + a.w * b.w;
}

// ---------------- ws/wd precompute ----------------
__global__ void wsd_kernel(const float* __restrict__ Wsrc, const float* __restrict__ Wdst,
                           const float* __restrict__ as, const float* __restrict__ ad) {
    int b = blockIdx.x;
    int i = threadIdx.x;
    __shared__ float sas[HD], sad[HD];
    sas[i] = as[b * HD + i];
    sad[i] = ad[b * HD + i];
    __syncthreads();
    const float* Ws = Wsrc + (size_t)b * HD * HD + (size_t)i * HD;
    const float* Wd = Wdst + (size_t)b * HD * HD + (size_t)i * HD;
    float s = 0.f, d = 0.f;
    #pragma unroll 8
    for (int j = 0; j < HD; j++) { s += Ws[j] * sas[j]; d += Wd[j] * sad[j]; }
    g_WS[b * HD + i] = s;
    g_WD[b * HD + i] = d;
}

// ---------------- activation split: fp32 -> (half hi, half lo) ----------------
__global__ void split_kernel(const float* __restrict__ X, __half* __restrict__ Xh,
                             __half* __restrict__ Xl, int n4) {
    int i = blockIdx.x * blockDim.x + threadIdx.x;
    if (i >= n4) return;
    float4 v = ((const float4*)X)[i];
    __half h0, h1, h2, h3, l0, l1, l2, l3;
    h2split(v.x, h0, l0); h2split(v.y, h1, l1);
    h2split(v.z, h2, l2); h2split(v.w, h3, l3);
    ((__half2*)Xh)[i * 2 + 0] = __halves2half2(h0, h1);
    ((__half2*)Xh)[i * 2 + 1] = __halves2half2(h2, h3);
    ((__half2*)Xl)[i * 2 + 0] = __halves2half2(l0, l1);
    ((__half2*)Xl)[i * 2 + 1] = __halves2half2(l2, l3);
}

// ---------------- W transpose + split ----------------
__global__ void wsplit_kernel(const float* __restrict__ W) {
    __shared__ float tile[32][33];
    int mat = blockIdx.z;
    int bk = blockIdx.x * 32, bn = blockIdx.y * 32;
    int tx = threadIdx.x, ty = threadIdx.y;   // (32, 8)
    const float* Wm = W + (size_t)mat * HD * HD;
    #pragma unroll
    for (int r = 0; r < 32; r += 8)
        tile[ty + r][tx] = Wm[(size_t)(bk + ty + r) * HD + bn + tx];
    __syncthreads();
    #pragma unroll
    for (int r = 0; r < 32; r += 8) {
        float x = tile[tx][ty + r];
        __half h, l;
        h2split(x, h, l);
        size_t o = (size_t)mat * HD * HD + (size_t)(bn + ty + r) * HD + bk + tx;
        g_WhT[o] = h;
        g_WlT[o] = l;
    }
}

// ---------------- fp16x3 GEMM, 128x128 tile, 2-stage, fp16 output ----------
__global__ __launch_bounds__(256, 2) void gemm_fp16_kernel(
        const __half* __restrict__ AhV, const __half* __restrict__ AlV,
        const __half* __restrict__ AhC, const __half* __restrict__ AlC,
        const __half* __restrict__ WhT, const __half* __restrict__ WlT,
        __half* __restrict__ C0, __half* __restrict__ C1,
        __half* __restrict__ C2, __half* __restrict__ C3) {
    extern __shared__ __half smh[];
    __half* pAh = smh;
    __half* pAl = pAh + NSTAGE * 128 * ASTR;
    __half* pBh = pAl + NSTAGE * 128 * ASTR;
    __half* pBl = pBh + NSTAGE * 128 * ASTR;

    const int mat = blockIdx.y >> 1;
    const int N = (mat == 3) ? NCN : NVN;
    const int row0 = blockIdx.x * 128;
    if (row0 >= N) return;
    const __half* Ah = (mat == 3) ? AhC : AhV;
    const __half* Al = (mat == 3) ? AlC : AlV;
    __half* C = (mat == 0) ? C0 : (mat == 1) ? C1 : (mat == 2) ? C2 : C3;
    const int col0 = (blockIdx.y & 1) * 128;
    const __half* W_h = WhT + (size_t)mat * HD * HD;
    const __half* W_l = WlT + (size_t)mat * HD * HD;

    const int tid = threadIdx.x;
    const int lane = tid & 31;
    const int wid = tid >> 5;
    const int wm = (wid & 3) * 32;
    const int wn = (wid >> 2) * 64;

    const int arow = tid >> 1;
    const int acol = (tid & 1) * 16;

    float acc[2][8][4];
    #pragma unroll
    for (int i = 0; i < 2; i++)
        #pragma unroll
        for (int j = 0; j < 8; j++)
            #pragma unroll
            for (int q = 0; q < 4; q++) acc[i][j][q] = 0.f;

    const int g = lane >> 2, t4 = lane & 3;
    const int lr = lane & 15;
    const int lk = (lane >> 4) * 8;
    const int br = lane & 7;
    const int bko = ((lane >> 3) & 1) * 8;

    auto load_stage = [&](int s, int k0) {
        bool v = (row0 + arow) < N;
        const __half* ah = v ? (Ah + (size_t)(row0 + arow) * HD + k0 + acol) : Ah;
        const __half* al = v ? (Al + (size_t)(row0 + arow) * HD + k0 + acol) : Al;
        __half* dh = pAh + s * 128 * ASTR + arow * ASTR + acol;
        __half* dl = pAl + s * 128 * ASTR + arow * ASTR + acol;
        cpa16(dh,     ah,     v);
        cpa16(dh + 8, ah + 8, v);
        cpa16(dl,     al,     v);
        cpa16(dl + 8, al + 8, v);
        __half* eh = pBh + s * 128 * ASTR + arow * ASTR + acol;
        __half* el = pBl + s * 128 * ASTR + arow * ASTR + acol;
        const __half* wh = W_h + (size_t)(col0 + arow) * HD + k0 + acol;
        const __half* wl = W_l + (size_t)(col0 + arow) * HD + k0 + acol;
        cpa16(eh,     wh,     true);
        cpa16(eh + 8, wh + 8, true);
        cpa16(el,     wl,     true);
        cpa16(el + 8, wl + 8, true);
        asm volatile("cp.async.commit_group;");
    };

    load_stage(0, 0);

    for (int kt = 0; kt < 8; kt++) {
        asm volatile("cp.async.wait_group 0;");
        __syncthreads();
        if (kt + 1 < 8) load_stage((kt + 1) & 1, (kt + 1) * BK);

        const int cur = kt & 1;
        const __half* cAh = pAh + cur * 128 * ASTR;
        const __half* cAl = pAl + cur * 128 * ASTR;
        const __half* cBh = pBh + cur * 128 * ASTR;
        const __half* cBl = pBl + cur * 128 * ASTR;

        #pragma unroll
        for (int ks = 0; ks < 2; ks++) {
            const int kb = ks * 16;
            uint32_t ah[2][4], al[2][4];
            #pragma unroll
            for (int i = 0; i < 2; i++) {
                ldsm4(ah[i], cAh + (size_t)(wm + i * 16 + lr) * ASTR + kb + lk);
                ldsm4(al[i], cAl + (size_t)(wm + i * 16 + lr) * ASTR + kb + lk);
            }
            #pragma unroll
            for (int j = 0; j < 8; j++) {
                uint32_t bh[2], bl[2];
                ldsm2(bh, cBh + (size_t)(wn + j * 8 + br) * ASTR + kb + bko);
                ldsm2(bl, cBl + (size_t)(wn + j * 8 + br) * ASTR + kb + bko);
                #pragma unroll
                for (int i = 0; i < 2; i++) {
                    mma_f16(acc[i][j], ah[i], bh);
                    mma_f16(acc[i][j], ah[i], bl);
                    mma_f16(acc[i][j], al[i], bh);
                }
            }
        }
    }

    #pragma unroll
    for (int i = 0; i < 2; i++) {
        int r0 = row0 + wm + i * 16 + g;
        #pragma unroll
        for (int j = 0; j < 8; j++) {
            int c = col0 + wn + j * 8 + t4 * 2;
            if (r0 < N)
                *(__half2*)(C + (size_t)r0 * HD + c) =
                    __floats2half2_rn(acc[i][j][0], acc[i][j][1]);
            if (r0 + 8 < N)
                *(__half2*)(C + (size_t)(r0 + 8) * HD + c) =
                    __floats2half2_rn(acc[i][j][2], acc[i][j][3]);
        }
    }
}

// ---------------- standalone attention dots (layer 0 only) ----------------
__global__ void avec_var_kernel(const float* __restrict__ xv) {
    __shared__ float sv[6][HD];
    int t = threadIdx.x;
    sv[0][t] = g_WS[0 * HD + t];
    sv[1][t] = g_WD[0 * HD + t];
    sv[2][t] = g_WS[1 * HD + t];
    sv[3][t] = g_WD[1 * HD + t];
    sv[4][t] = g_WS[2 * HD + t];
    sv[5][t] = g_WD[3 * HD + t];
    __syncthreads();
    int w = (blockIdx.x * blockDim.x + t) >> 5;
    int lane = t & 31;
    if (w >= NVN) return;
    const float* row = xv + (size_t)w * HD;
    float s[6] = {0, 0, 0, 0, 0, 0};
    #pragma unroll
    for (int j0 = 0; j0 < HD; j0 += 32) {
        float x = row[j0 + lane];
        #pragma unroll
        for (int k = 0; k < 6; k++) s[k] += x * sv[k][j0 + lane];
    }
    #pragma unroll
    for (int k = 0; k < 6; k++)
        #pragma unroll
        for (int o = 16; o > 0; o >>= 1) s[k] += __shfl_xor_sync(0xffffffffu, s[k], o);
    if (lane == 0) {
        g_AS0[w] = s[0]; g_AD0[w] = s[1];
        g_AS1[w] = s[2]; g_AD1[w] = s[3];
        g_AS2[w] = s[4]; g_AD3[w] = s[5];
    }
}

__global__ void avec_con_kernel(const float* __restrict__ xc) {
    __shared__ float sv[2][HD];
    int t = threadIdx.x;
    sv[0][t] = g_WD[2 * HD + t];
    sv[1][t] = g_WS[3 * HD + t];
    __syncthreads();
    int w = (blockIdx.x * blockDim.x + t) >> 5;
    int lane = t & 31;
    if (w >= NCN) return;
    const float* row = xc + (size_t)w * HD;
    float s0 = 0.f, s1 = 0.f;
    #pragma unroll
    for (int j0 = 0; j0 < HD; j0 += 32) {
        float x = row[j0 + lane];
        s0 += x * sv[0][j0 + lane];
        s1 += x * sv[1][j0 + lane];
    }
    #pragma unroll
    for (int o = 16; o > 0; o >>= 1) {
        s0 += __shfl_xor_sync(0xffffffffu, s0, o);
        s1 += __shfl_xor_sync(0xffffffffu, s1, o);
    }
    if (lane == 0) { g_AD2[w] = s0; g_AS3[w] = s1; }
}

// ---------------- CSR build ----------------
__global__ void zero_int_kernel(int* __restrict__ p, int n) {
    int i = blockIdx.x * blockDim.x + threadIdx.x;
    if (i < n) p[i] = 0;
}
__global__ void hist_kernel(const int* __restrict__ dst, int* __restrict__ cnt, int E) {
    int i = blockIdx.x * blockDim.x + threadIdx.x;
    if (i < E) atomicAdd(&cnt[dst[i]], 1);
}
__global__ void scan_kernel(int* __restrict__ rp, int* __restrict__ cursor, int n) {
    __shared__ int swarp[32];
    __shared__ int stot;
    int t = threadIdx.x, w = t >> 5, lane = t & 31;
    int carry = 0;
    for (int base = 0; base < n; base += 1024) {
        int idx = base + t;
        int v = (idx < n) ? rp[idx] : 0;
        int x = v;
        #pragma unroll
        for (int o = 1; o < 32; o <<= 1) {
            int y = __shfl_up_sync(0xffffffffu, x, o);
            if (lane >= o) x += y;
        }
        if (lane == 31) swarp[w] = x;
        __syncthreads();
        if (w == 0) {
            int s = swarp[lane];
            int z = s;
            #pragma unroll
            for (int o = 1; o < 32; o <<= 1) {
                int y = __shfl_up_sync(0xffffffffu, z, o);
                if (lane >= o) z += y;
            }
            swarp[lane] = z - s;
            if (lane == 31) stot = z;
        }
        __syncthreads();
        int excl = carry + swarp[w] + (x - v);
        if (idx < n) { rp[idx] = excl; cursor[idx] = excl; }
        carry += stot;
        __syncthreads();
    }
    if (t == 0) rp[n] = carry;
}
__global__ void scatter_kernel(const int* __restrict__ src, const int* __restrict__ dst,
                               int* __restrict__ cursor, int* __restrict__ cs, int E) {
    int i = blockIdx.x * blockDim.x + threadIdx.x;
    if (i >= E) return;
    int pos = atomicAdd(&cursor[dst[i]], 1);
    cs[pos] = src[i];
}

// ---------------- fused GAT (fp16 XL, lane owns 8 contiguous elems) ----------
__device__ __forceinline__ void gat_accum(
        int d, int lane,
        const int* __restrict__ rp, const int* __restrict__ cs,
        const float* __restrict__ AS, const float* __restrict__ AD,
        const __half* __restrict__ XL,
        float4& acc0, float4& acc1) {
    int off = rp[d];
    int deg = rp[d + 1] - off;
    if (deg <= 0) return;
    float adv = AD[d];
    float m = -1e30f;
    for (int j = lane; j < deg; j += 32) {
        int s = cs[off + j];
        float e = AS[s] + adv;
        e = (e >= 0.f) ? e : 0.2f * e;
        m = fmaxf(m, e);
    }
    #pragma unroll
    for (int o = 16; o > 0; o >>= 1) m = fmaxf(m, __shfl_xor_sync(0xffffffffu, m, o));
    float den = 0.f;
    for (int j = lane; j < deg; j += 32) {
        int s = cs[off + j];
        float e = AS[s] + adv;
        e = (e >= 0.f) ? e : 0.2f * e;
        den += __expf(e - m);
    }
    #pragma unroll
    for (int o = 16; o > 0; o >>= 1) den += __shfl_xor_sync(0xffffffffu, den, o);
    float invden = 1.f / (den + 1e-16f);
    #pragma unroll 4
    for (int j = 0; j < deg; j++) {
        int s = cs[off + j];
        float e = AS[s] + adv;
        e = (e >= 0.f) ? e : 0.2f * e;
        float wgt = __expf(e - m) * invden;
        // lane owns halves [8*lane, 8*lane+8): one 16B load
        const uint4 raw = ((const uint4*)(XL + (size_t)s * HD))[lane];
        __half2 p0 = *(const __half2*)&raw.x;
        __half2 p1 = *(const __half2*)&raw.y;
        __half2 p2 = *(const __half2*)&raw.z;
        __half2 p3 = *(const __half2*)&raw.w;
        float2 f0 = __half22float2(p0), f1 = __half22float2(p1);
        float2 f2 = __half22float2(p2), f3 = __half22float2(p3);
        acc0.x += wgt * f0.x; acc0.y += wgt * f0.y;
        acc0.z += wgt * f1.x; acc0.w += wgt * f1.y;
        acc1.x += wgt * f2.x; acc1.y += wgt * f2.y;
        acc1.z += wgt * f3.x; acc1.w += wgt * f3.y;
    }
}

__device__ __forceinline__ void split_store(__half* outh, __half* outl, int w, int lane,
                                            float4 acc0, float4 acc1) {
    // lane owns elements [8*lane, 8*lane+8)
    __half h0, h1, h2, h3, l0, l1, l2, l3;
    __half2* oh = (__half2*)(outh + (size_t)w * HD) + lane * 4;
    __half2* ol = (__half2*)(outl + (size_t)w * HD) + lane * 4;
    h2split(acc0.x, h0, l0); h2split(acc0.y, h1, l1);
    h2split(acc0.z, h2, l2); h2split(acc0.w, h3, l3);
    oh[0] = __halves2half2(h0, h1);
    oh[1] = __halves2half2(h2, h3);
    ol[0] = __halves2half2(l0, l1);
    ol[1] = __halves2half2(l2, l3);
    h2split(acc1.x, h0, l0); h2split(acc1.y, h1, l1);
    h2split(acc1.z, h2, l2); h2split(acc1.w, h3, l3);
    oh[2] = __halves2half2(h0, h1);
    oh[3] = __halves2half2(h2, h3);
    ol[2] = __halves2half2(l0, l1);
    ol[3] = __halves2half2(l2, l3);
}

// one CSR per pass. mode: 0=first (init with 3 biases), 1=middle, 2=last(+epilogue)
__global__ void gat_var_pass_kernel(const __half* __restrict__ XL,
                                    const int* __restrict__ rp, const int* __restrict__ cs,
                                    const float* __restrict__ AS, const float* __restrict__ AD,
                                    const float* __restrict__ bias, int l,
                                    float* __restrict__ out,
                                    __half* __restrict__ outh, __half* __restrict__ outl,
                                    int mode, int do_next) {
    int w = (blockIdx.x * blockDim.x + threadIdx.x) >> 5;
    int lane = threadIdx.x & 31;
    if (w >= NVN) return;
    float4 acc0, acc1;
    float4* ob = (float4*)(out + (size_t)w * HD) + lane * 2;
    if (mode == 0) {
        const float4* b0 = (const float4*)(bias + (size_t)(4 * l + 0) * HD) + lane * 2;
        const float4* b1 = (const float4*)(bias + (size_t)(4 * l + 1) * HD) + lane * 2;
        const float4* b3 = (const float4*)(bias + (size_t)(4 * l + 3) * HD) + lane * 2;
        float4 x0 = b0[0], y0 = b1[0], z0 = b3[0];
        float4 x1 = b0[1], y1 = b1[1], z1 = b3[1];
        acc0 = make_float4(x0.x + y0.x + z0.x, x0.y + y0.y + z0.y,
                           x0.z + y0.z + z0.z, x0.w + y0.w + z0.w);
        acc1 = make_float4(x1.x + y1.x + z1.x, x1.y + y1.y + z1.y,
                           x1.z + y1.z + z1.z, x1.w + y1.w + z1.w);
    } else {
        acc0 = ob[0];
        acc1 = ob[1];
    }
    gat_accum(w, lane, rp, cs, AS, AD, XL, acc0, acc1);
    ob[0] = acc0;
    ob[1] = acc1;
    if (mode != 2 || !do_next) return;
    split_store(outh, outl, w, lane, acc0, acc1);
    int L = l + 1;
    int wv = ((l + 1) & 1) * NVN;
    float s[6];
    const int vidx[6] = {0, 0, 1, 1, 2, 3};
    #pragma unroll
    for (int k = 0; k < 6; k++) {
        const float* vecb = (k == 1 || k == 3 || k == 5) ? g_WD : g_WS;
        const float4* vp = (const float4*)(vecb + (size_t)(4 * L + vidx[k]) * HD) + lane * 2;
        s[k] = d4(acc0, vp[0]) + d4(acc1, vp[1]);
    }
    #pragma unroll
    for (int k = 0; k < 6; k++)
        #pragma unroll
        for (int o = 16; o > 0; o >>= 1) s[k] += __shfl_xor_sync(0xffffffffu, s[k], o);
    if (lane == 0) {
        g_AS0[wv + w] = s[0]; g_AD0[wv + w] = s[1];
        g_AS1[wv + w] = s[2]; g_AD1[wv + w] = s[3];
        g_AS2[wv + w] = s[4]; g_AD3[wv + w] = s[5];
    }
}

__global__ void gat_con_kernel(const __half* __restrict__ XL2,
                               const float* __restrict__ bias, int l,
                               float* __restrict__ out,
                               __half* __restrict__ outh, __half* __restrict__ outl,
                               int do_next) {
    int w = (blockIdx.x * blockDim.x + threadIdx.x) >> 5;
    int lane = threadIdx.x & 31;
    if (w >= NCN) return;
    int rc = (l & 1) * NCN;
    float4 acc0, acc1;
    const float4* b2 = (const float4*)(bias + (size_t)(4 * l + 2) * HD) + lane * 2;
    acc0 = b2[0];
    acc1 = b2[1];
    gat_accum(w, lane, g_RP2, g_CS2, g_AS2 + (l & 1) * NVN, g_AD2 + rc, XL2, acc0, acc1);
    float4* ob = (float4*)(out + (size_t)w * HD) + lane * 2;
    ob[0] = acc0;
    ob[1] = acc1;
    if (!do_next) return;
    split_store(outh, outl, w, lane, acc0, acc1);
    int L = l + 1;
    int wc = ((l + 1) & 1) * NCN;
    const float4* v0 = (const float4*)(g_WD + (size_t)(4 * L + 2) * HD) + lane * 2;
    const float4* v1 = (const float4*)(g_WS + (size_t)(4 * L + 3) * HD) + lane * 2;
    float s0 = d4(acc0, v0[0]) + d4(acc1, v0[1]);
    float s1 = d4(acc0, v1[0]) + d4(acc1, v1[1]);
    #pragma unroll
    for (int o = 16; o > 0; o >>= 1) {
        s0 += __shfl_xor_sync(0xffffffffu, s0, o);
        s1 += __shfl_xor_sync(0xffffffffu, s1, o);
    }
    if (lane == 0) { g_AD2[wc + w] = s0; g_AS3[wc + w] = s1; }
}

// ---------------- pooling + head ----------------
__global__ void zero_pool_kernel() {
    int i = blockIdx.x * 256 + threadIdx.x;
    g_VP[i] = 0.f;
    g_CP[i] = 0.f;
    if (i < 2 * GN) g_CNT[i] = 0;
}

__global__ void pool_kernel(const float* __restrict__ X, const int* __restrict__ batch,
                            int N, float* __restrict__ S, int* __restrict__ cnt) {
    int w = (blockIdx.x * blockDim.x + threadIdx.x) >> 5;
    int lane = threadIdx.x & 31;
    if (w >= N) return;
    int g = batch[w];
    if (lane == 0) atomicAdd(&cnt[g], 1);
    const float4* xr = (const float4*)(X + (size_t)w * HD);
    float* sb = S + (size_t)g * HD;
    #pragma unroll
    for (int j = 0; j < 2; j++) {
        int idx = lane + 32 * j;
        red4(sb + 4 * idx, xr[idx]);
    }
}

__global__ void finalize_kernel(const float* __restrict__ Wlin, const float* __restrict__ blin,
                                float* __restrict__ out) {
    int g = blockIdx.x, t = threadIdx.x;
    float cv = (float)max(g_CNT[g], 1);
    float cc = (float)max(g_CNT[GN + g], 1);
    float a = g_VP[g * HD + t] / cv;
    float c = g_CP[g * HD + t] / cc;
    float p0 = a * Wlin[t * 2 + 0] + c * Wlin[(HD + t) * 2 + 0];
    float p1 = a * Wlin[t * 2 + 1] + c * Wlin[(HD + t) * 2 + 1];
    __shared__ float s0[256], s1[256];
    s0[t] = p0; s1[t] = p1;
    __syncthreads();
    for (int o = 128; o > 0; o >>= 1) {
        if (t < o) { s0[t] += s0[t + o]; s1[t] += s1[t + o]; }
        __syncthreads();
    }
    if (t == 0) {
        float z0 = s0[0] + blin[0], z1 = s1[0] + blin[1];
        float m = fmaxf(z0, z1);
        float e0 = expf(z0 - m), e1 = expf(z1 - m);
        float inv = 1.f / (e0 + e1);
        out[2 * g + 0] = e0 * inv;
        out[2 * g + 1] = e1 * inv;
    }
}

// ---------------- host ----------------
extern "C" void kernel_launch(void* const* d_in, const int* in_sizes, int n_in,
                              void* d_out, int out_size) {
    const float* x_var   = (const float*)d_in[0];
    const float* x_con   = (const float*)d_in[1];
    const float* W_src   = (const float*)d_in[2];
    const float* W_dst   = (const float*)d_in[3];
    const float* att_src = (const float*)d_in[4];
    const float* att_dst = (const float*)d_in[5];
    const float* bias    = (const float*)d_in[6];
    const float* W_lin   = (const float*)d_in[7];
    const float* b_lin   = (const float*)d_in[8];
    const int* e_vv      = (const int*)d_in[9];
    const int* e_vv_rev  = (const int*)d_in[10];
    const int* e_vc      = (const int*)d_in[11];
    const int* e_cv      = (const int*)d_in[12];
    const int* batch_var = (const int*)d_in[13];
    const int* batch_con = (const int*)d_in[14];
    float* out = (float*)d_out;

    float *pXV[2], *pXC[2], *pVP, *pCP;
    __half *pXL0, *pXL1, *pXL2, *pXL3;
    __half *pAhV, *pAlV, *pAhC, *pAlC, *pWhT, *pWlT;
    int *pRP0, *pRP1, *pRP2, *pRP3, *pCU0, *pCU1, *pCU2, *pCU3;
    int *pCS0, *pCS1, *pCS2, *pCS3, *pCNT;
    float *pAS0, *pAD0, *pAS1, *pAD1, *pAS2, *pAD3, *pAS3, *pAD2;
    cudaGetSymbolAddress((void**)&pXV[0], g_XV0);
    cudaGetSymbolAddress((void**)&pXV[1], g_XV1);
    cudaGetSymbolAddress((void**)&pXC[0], g_XC0);
    cudaGetSymbolAddress((void**)&pXC[1], g_XC1);
    cudaGetSymbolAddress((void**)&pXL0, g_XL0);
    cudaGetSymbolAddress((void**)&pXL1, g_XL1);
    cudaGetSymbolAddress((void**)&pXL2, g_XL2);
    cudaGetSymbolAddress((void**)&pXL3, g_XL3);
    cudaGetSymbolAddress((void**)&pAhV, g_AhV);
    cudaGetSymbolAddress((void**)&pAlV, g_AlV);
    cudaGetSymbolAddress((void**)&pAhC, g_AhC);
    cudaGetSymbolAddress((void**)&pAlC, g_AlC);
    cudaGetSymbolAddress((void**)&pWhT, g_WhT);
    cudaGetSymbolAddress((void**)&pWlT, g_WlT);
    cudaGetSymbolAddress((void**)&pRP0, g_RP0);
    cudaGetSymbolAddress((void**)&pRP1, g_RP1);
    cudaGetSymbolAddress((void**)&pRP2, g_RP2);
    cudaGetSymbolAddress((void**)&pRP3, g_RP3);
    cudaGetSymbolAddress((void**)&pCU0, g_CU0);
    cudaGetSymbolAddress((void**)&pCU1, g_CU1);
    cudaGetSymbolAddress((void**)&pCU2, g_CU2);
    cudaGetSymbolAddress((void**)&pCU3, g_CU3);
    cudaGetSymbolAddress((void**)&pCS0, g_CS0);
    cudaGetSymbolAddress((void**)&pCS1, g_CS1);
    cudaGetSymbolAddress((void**)&pCS2, g_CS2);
    cudaGetSymbolAddress((void**)&pCS3, g_CS3);
    cudaGetSymbolAddress((void**)&pAS0, g_AS0);
    cudaGetSymbolAddress((void**)&pAD0, g_AD0);
    cudaGetSymbolAddress((void**)&pAS1, g_AS1);
    cudaGetSymbolAddress((void**)&pAD1, g_AD1);
    cudaGetSymbolAddress((void**)&pAS2, g_AS2);
    cudaGetSymbolAddress((void**)&pAD3, g_AD3);
    cudaGetSymbolAddress((void**)&pAS3, g_AS3);
    cudaGetSymbolAddress((void**)&pAD2, g_AD2);
    cudaGetSymbolAddress((void**)&pVP, g_VP);
    cudaGetSymbolAddress((void**)&pCP, g_CP);
    cudaGetSymbolAddress((void**)&pCNT, g_CNT);

    cudaFuncSetAttribute(gemm_fp16_kernel,
                         cudaFuncAttributeMaxDynamicSharedMemorySize, SMEM_BYTES);

    const int EB = 256;
    dim3 gemmGrid((NVN + 127) / 128, 8);

    split_kernel<<<(NVN * HD / 4 + EB - 1) / EB, EB>>>(x_var, pAhV, pAlV, NVN * HD / 4);
    split_kernel<<<(NCN * HD / 4 + EB - 1) / EB, EB>>>(x_con, pAhC, pAlC, NCN * HD / 4);
    wsplit_kernel<<<dim3(8, 8, 16), dim3(32, 8)>>>(W_src);

    gemm_fp16_kernel<<<gemmGrid, 256, SMEM_BYTES>>>(
        pAhV, pAlV, pAhC, pAlC, pWhT, pWlT, pXL0, pXL1, pXL2, pXL3);

    wsd_kernel<<<16, 256>>>(W_src, W_dst, att_src, att_dst);
    avec_var_kernel<<<(NVN * 32 + EB - 1) / EB, EB>>>(x_var);
    avec_con_kernel<<<(NCN * 32 + EB - 1) / EB, EB>>>(x_con);

    zero_int_kernel<<<(NVN + 1 + EB - 1) / EB, EB>>>(pRP0, NVN + 1);
    zero_int_kernel<<<(NVN + 1 + EB - 1) / EB, EB>>>(pRP1, NVN + 1);
    zero_int_kernel<<<(NVN + 1 + EB - 1) / EB, EB>>>(pRP3, NVN + 1);
    zero_int_kernel<<<(NCN + 1 + EB - 1) / EB, EB>>>(pRP2, NCN + 1);
    hist_kernel<<<(EVVN + EB - 1) / EB, EB>>>(e_vv + EVVN, pRP0, EVVN);
    hist_kernel<<<(EVVN + EB - 1) / EB, EB>>>(e_vv_rev + EVVN, pRP1, EVVN);
    hist_kernel<<<(EVCN + EB - 1) / EB, EB>>>(e_cv + EVCN, pRP3, EVCN);
    hist_kernel<<<(EVCN + EB - 1) / EB, EB>>>(e_vc + EVCN, pRP2, EVCN);
    scan_kernel<<<1, 1024>>>(pRP0, pCU0, NVN);
    scan_kernel<<<1, 1024>>>(pRP1, pCU1, NVN);
    scan_kernel<<<1, 1024>>>(pRP3, pCU3, NVN);
    scan_kernel<<<1, 1024>>>(pRP2, pCU2, NCN);
    scatter_kernel<<<(EVVN + EB - 1) / EB, EB>>>(e_vv, e_vv + EVVN, pCU0, pCS0, EVVN);
    scatter_kernel<<<(EVVN + EB - 1) / EB, EB>>>(e_vv_rev, e_vv_rev + EVVN, pCU1, pCS1, EVVN);
    scatter_kernel<<<(EVCN + EB - 1) / EB, EB>>>(e_cv, e_cv + EVCN, pCU3, pCS3, EVCN);
    scatter_kernel<<<(EVCN + EB - 1) / EB, EB>>>(e_vc, e_vc + EVCN, pCU2, pCS2, EVCN);

    int gatVB = (NVN * 32 + EB - 1) / EB;
    int gatCB = (NCN * 32 + EB - 1) / EB;

    for (int l = 0; l < NLAYER; l++) {
        float* xv_out = pXV[l & 1];
        float* xc_out = pXC[l & 1];
        int do_next = (l + 1 < NLAYER) ? 1 : 0;
        int rv = (l & 1) * NVN, rc = (l & 1) * NCN;

        if (l > 0) {
            gemm_fp16_kernel<<<gemmGrid, 256, SMEM_BYTES>>>(
                pAhV, pAlV, pAhC, pAlC,
                pWhT + (size_t)(4 * l) * HD * HD, pWlT + (size_t)(4 * l) * HD * HD,
                pXL0, pXL1, pXL2, pXL3);
        }

        gat_var_pass_kernel<<<gatVB, EB>>>(pXL0, pRP0, pCS0, pAS0 + rv, pAD0 + rv,
                                           bias, l, xv_out, pAhV, pAlV, 0, do_next);
        gat_var_pass_kernel<<<gatVB, EB>>>(pXL1, pRP1, pCS1, pAS1 + rv, pAD1 + rv,
                                           bias, l, xv_out, pAhV, pAlV, 1, do_next);
        gat_var_pass_kernel<<<gatVB, EB>>>(pXL3, pRP3, pCS3, pAS3 + rc, pAD3 + rv,
                                           bias, l, xv_out, pAhV, pAlV, 2, do_next);
        gat_con_kernel<<<gatCB, EB>>>(pXL2, bias, l, xc_out, pAhC, pAlC, do_next);
    }

    zero_pool_kernel<<<GN, 256>>>();
    pool_kernel<<<gatVB, EB>>>(pXV[(NLAYER - 1) & 1], batch_var, NVN, pVP, pCNT);
    pool_kernel<<<gatCB, EB>>>(pXC[(NLAYER - 1) & 1], batch_con, NCN, pCP, pCNT + GN);
    finalize_kernel<<<GN, 256>>>(W_lin, b_lin, out);
}

// round 13
// speedup vs baseline: 1.9222x; 1.0957x over previous
#include <cuda_runtime.h>
#include <cuda_fp16.h>
#include <cstdint>
#include <cstddef>

#define NVN 50000
#define NCN 20000
#define HD  256
#define NLAYER 4
#define EVVN 500000
#define EVCN 300000
#define GN  64

#define ASTR 40
#define BK 32
#define NSTAGE 2
#define SMEM_HALVES (NSTAGE*128*ASTR*2 + NSTAGE*128*ASTR*2)
#define SMEM_BYTES  (SMEM_HALVES*2)

// ---------------- scratch ----------------
__device__ __align__(128) float g_XV0[NVN * HD];
__device__ __align__(128) float g_XC0[NCN * HD];
// XL fp16
__device__ __align__(128) __half g_XL0[NVN * HD];
__device__ __align__(128) __half g_XL1[NVN * HD];
__device__ __align__(128) __half g_XL2[NVN * HD];
__device__ __align__(128) __half g_XL3[NCN * HD];

// fp16 hi/lo operand buffers
__device__ __align__(128) __half g_AhV[NVN * HD];
__device__ __align__(128) __half g_AlV[NVN * HD];
__device__ __align__(128) __half g_AhC[NCN * HD];
__device__ __align__(128) __half g_AlC[NCN * HD];
__device__ __align__(128) __half g_WhT[16 * HD * HD];  // [mat][n][k]
__device__ __align__(128) __half g_WlT[16 * HD * HD];

// double-buffered attention scalars: [parity][node]
__device__ float g_AS0[2 * NVN], g_AD0[2 * NVN];
__device__ float g_AS1[2 * NVN], g_AD1[2 * NVN];
__device__ float g_AS2[2 * NVN], g_AD3[2 * NVN];
__device__ float g_AS3[2 * NCN], g_AD2[2 * NCN];

__device__ __align__(128) float g_WS[16 * HD];
__device__ __align__(128) float g_WD[16 * HD];

__device__ int g_RP0[NVN + 1], g_RP1[NVN + 1], g_RP3[NVN + 1], g_RP2[NCN + 1];
__device__ int g_CU0[NVN], g_CU1[NVN], g_CU3[NVN], g_CU2[NCN];
__device__ int g_CS0[EVVN], g_CS1[EVVN], g_CS3[EVCN], g_CS2[EVCN];

__device__ __align__(128) float g_VP[GN * HD];
__device__ __align__(128) float g_CP[GN * HD];
__device__ int   g_CNT[2 * GN];

// ---------------- helpers ----------------
__device__ __forceinline__ void red4(float* p, float4 v) {
    asm volatile("red.global.add.v4.f32 [%0], {%1,%2,%3,%4};"
                 :: "l"(p), "f"(v.x), "f"(v.y), "f"(v.z), "f"(v.w) : "memory");
}
__device__ __forceinline__ void h2split(float x, __half& h, __half& l) {
    h = __float2half_rn(x);
    l = __float2half_rn(x - __half2float(h));
}
__device__ __forceinline__ void ldsm4(uint32_t* r, const void* p) {
    uint32_t addr = (uint32_t)__cvta_generic_to_shared(p);
    asm volatile("ldmatrix.sync.aligned.m8n8.x4.shared.b16 {%0,%1,%2,%3}, [%4];"
                 : "=r"(r[0]), "=r"(r[1]), "=r"(r[2]), "=r"(r[3]) : "r"(addr));
}
__device__ __forceinline__ void ldsm2(uint32_t* r, const void* p) {
    uint32_t addr = (uint32_t)__cvta_generic_to_shared(p);
    asm volatile("ldmatrix.sync.aligned.m8n8.x2.shared.b16 {%0,%1}, [%2];"
                 : "=r"(r[0]), "=r"(r[1]) : "r"(addr));
}
__device__ __forceinline__ void mma_f16(float* c, const uint32_t* a, const uint32_t* b) {
    asm volatile(
        "mma.sync.aligned.m16n8k16.row.col.f32.f16.f16.f32 "
        "{%0,%1,%2,%3}, {%4,%5,%6,%7}, {%8,%9}, {%0,%1,%2,%3};"
        : "+f"(c[0]), "+f"(c[1]), "+f"(c[2]), "+f"(c[3])
        : "r"(a[0]), "r"(a[1]), "r"(a[2]), "r"(a[3]), "r"(b[0]), "r"(b[1]));
}
__device__ __forceinline__ void cpa16(void* dst, const void* src, bool valid) {
    uint32_t d = (uint32_t)__cvta_generic_to_shared(dst);
    int sz = valid ? 16 : 0;
    asm volatile("cp.async.ca.shared.global [%0], [%1], 16, %2;"
                 :: "r"(d), "l"(src), "r"(sz));
}
__device__ __forceinline__ float d4(float4 a, float4 b) {
    return a.x * b.x + a.y * b.y + a.z * b.z + a.w * b.w;
}

// ---------------- ws/wd precompute ----------------
__global__ void wsd_kernel(const float* __restrict__ Wsrc, const float* __restrict__ Wdst,
                           const float* __restrict__ as, const float* __restrict__ ad) {
    int b = blockIdx.x;
    int i = threadIdx.x;
    __shared__ float sas[HD], sad[HD];
    sas[i] = as[b * HD + i];
    sad[i] = ad[b * HD + i];
    __syncthreads();
    const float* Ws = Wsrc + (size_t)b * HD * HD + (size_t)i * HD;
    const float* Wd = Wdst + (size_t)b * HD * HD + (size_t)i * HD;
    float s = 0.f, d = 0.f;
    #pragma unroll 8
    for (int j = 0; j < HD; j++) { s += Ws[j] * sas[j]; d += Wd[j] * sad[j]; }
    g_WS[b * HD + i] = s;
    g_WD[b * HD + i] = d;
}

// ---------------- activation split ----------------
__global__ void split_kernel(const float* __restrict__ X, __half* __restrict__ Xh,
                             __half* __restrict__ Xl, int n4) {
    int i = blockIdx.x * blockDim.x + threadIdx.x;
    if (i >= n4) return;
    float4 v = ((const float4*)X)[i];
    __half h0, h1, h2, h3, l0, l1, l2, l3;
    h2split(v.x, h0, l0); h2split(v.y, h1, l1);
    h2split(v.z, h2, l2); h2split(v.w, h3, l3);
    ((__half2*)Xh)[i * 2 + 0] = __halves2half2(h0, h1);
    ((__half2*)Xh)[i * 2 + 1] = __halves2half2(h2, h3);
    ((__half2*)Xl)[i * 2 + 0] = __halves2half2(l0, l1);
    ((__half2*)Xl)[i * 2 + 1] = __halves2half2(l2, l3);
}

// ---------------- W transpose + split ----------------
__global__ void wsplit_kernel(const float* __restrict__ W) {
    __shared__ float tile[32][33];
    int mat = blockIdx.z;
    int bk = blockIdx.x * 32, bn = blockIdx.y * 32;
    int tx = threadIdx.x, ty = threadIdx.y;
    const float* Wm = W + (size_t)mat * HD * HD;
    #pragma unroll
    for (int r = 0; r < 32; r += 8)
        tile[ty + r][tx] = Wm[(size_t)(bk + ty + r) * HD + bn + tx];
    __syncthreads();
    #pragma unroll
    for (int r = 0; r < 32; r += 8) {
        float x = tile[tx][ty + r];
        __half h, l;
        h2split(x, h, l);
        size_t o = (size_t)mat * HD * HD + (size_t)(bn + ty + r) * HD + bk + tx;
        g_WhT[o] = h;
        g_WlT[o] = l;
    }
}

// ---------------- fp16x3 GEMM, 128x128 tile, 2-stage, fp16 output ----------
__global__ __launch_bounds__(256, 2) void gemm_fp16_kernel(
        const __half* __restrict__ AhV, const __half* __restrict__ AlV,
        const __half* __restrict__ AhC, const __half* __restrict__ AlC,
        const __half* __restrict__ WhT, const __half* __restrict__ WlT,
        __half* __restrict__ C0, __half* __restrict__ C1,
        __half* __restrict__ C2, __half* __restrict__ C3) {
    extern __shared__ __half smh[];
    __half* pAh = smh;
    __half* pAl = pAh + NSTAGE * 128 * ASTR;
    __half* pBh = pAl + NSTAGE * 128 * ASTR;
    __half* pBl = pBh + NSTAGE * 128 * ASTR;

    const int mat = blockIdx.y >> 1;
    const int N = (mat == 3) ? NCN : NVN;
    const int row0 = blockIdx.x * 128;
    if (row0 >= N) return;
    const __half* Ah = (mat == 3) ? AhC : AhV;
    const __half* Al = (mat == 3) ? AlC : AlV;
    __half* C = (mat == 0) ? C0 : (mat == 1) ? C1 : (mat == 2) ? C2 : C3;
    const int col0 = (blockIdx.y & 1) * 128;
    const __half* W_h = WhT + (size_t)mat * HD * HD;
    const __half* W_l = WlT + (size_t)mat * HD * HD;

    const int tid = threadIdx.x;
    const int lane = tid & 31;
    const int wid = tid >> 5;
    const int wm = (wid & 3) * 32;
    const int wn = (wid >> 2) * 64;

    const int arow = tid >> 1;
    const int acol = (tid & 1) * 16;

    float acc[2][8][4];
    #pragma unroll
    for (int i = 0; i < 2; i++)
        #pragma unroll
        for (int j = 0; j < 8; j++)
            #pragma unroll
            for (int q = 0; q < 4; q++) acc[i][j][q] = 0.f;

    const int g = lane >> 2, t4 = lane & 3;
    const int lr = lane & 15;
    const int lk = (lane >> 4) * 8;
    const int br = lane & 7;
    const int bko = ((lane >> 3) & 1) * 8;

    auto load_stage = [&](int s, int k0) {
        bool v = (row0 + arow) < N;
        const __half* ah = v ? (Ah + (size_t)(row0 + arow) * HD + k0 + acol) : Ah;
        const __half* al = v ? (Al + (size_t)(row0 + arow) * HD + k0 + acol) : Al;
        __half* dh = pAh + s * 128 * ASTR + arow * ASTR + acol;
        __half* dl = pAl + s * 128 * ASTR + arow * ASTR + acol;
        cpa16(dh,     ah,     v);
        cpa16(dh + 8, ah + 8, v);
        cpa16(dl,     al,     v);
        cpa16(dl + 8, al + 8, v);
        __half* eh = pBh + s * 128 * ASTR + arow * ASTR + acol;
        __half* el = pBl + s * 128 * ASTR + arow * ASTR + acol;
        const __half* wh = W_h + (size_t)(col0 + arow) * HD + k0 + acol;
        const __half* wl = W_l + (size_t)(col0 + arow) * HD + k0 + acol;
        cpa16(eh,     wh,     true);
        cpa16(eh + 8, wh + 8, true);
        cpa16(el,     wl,     true);
        cpa16(el + 8, wl + 8, true);
        asm volatile("cp.async.commit_group;");
    };

    load_stage(0, 0);

    for (int kt = 0; kt < 8; kt++) {
        asm volatile("cp.async.wait_group 0;");
        __syncthreads();
        if (kt + 1 < 8) load_stage((kt + 1) & 1, (kt + 1) * BK);

        const int cur = kt & 1;
        const __half* cAh = pAh + cur * 128 * ASTR;
        const __half* cAl = pAl + cur * 128 * ASTR;
        const __half* cBh = pBh + cur * 128 * ASTR;
        const __half* cBl = pBl + cur * 128 * ASTR;

        #pragma unroll
        for (int ks = 0; ks < 2; ks++) {
            const int kb = ks * 16;
            uint32_t ah[2][4], al[2][4];
            #pragma unroll
            for (int i = 0; i < 2; i++) {
                ldsm4(ah[i], cAh + (size_t)(wm + i * 16 + lr) * ASTR + kb + lk);
                ldsm4(al[i], cAl + (size_t)(wm + i * 16 + lr) * ASTR + kb + lk);
            }
            #pragma unroll
            for (int j = 0; j < 8; j++) {
                uint32_t bh[2], bl[2];
                ldsm2(bh, cBh + (size_t)(wn + j * 8 + br) * ASTR + kb + bko);
                ldsm2(bl, cBl + (size_t)(wn + j * 8 + br) * ASTR + kb + bko);
                #pragma unroll
                for (int i = 0; i < 2; i++) {
                    mma_f16(acc[i][j], ah[i], bh);
                    mma_f16(acc[i][j], ah[i], bl);
                    mma_f16(acc[i][j], al[i], bh);
                }
            }
        }
    }

    #pragma unroll
    for (int i = 0; i < 2; i++) {
        int r0 = row0 + wm + i * 16 + g;
        #pragma unroll
        for (int j = 0; j < 8; j++) {
            int c = col0 + wn + j * 8 + t4 * 2;
            if (r0 < N)
                *(__half2*)(C + (size_t)r0 * HD + c) =
                    __floats2half2_rn(acc[i][j][0], acc[i][j][1]);
            if (r0 + 8 < N)
                *(__half2*)(C + (size_t)(r0 + 8) * HD + c) =
                    __floats2half2_rn(acc[i][j][2], acc[i][j][3]);
        }
    }
}

// ---------------- standalone attention dots (layer 0 only) ----------------
__global__ void avec_var_kernel(const float* __restrict__ xv) {
    __shared__ float sv[6][HD];
    int t = threadIdx.x;
    sv[0][t] = g_WS[0 * HD + t];
    sv[1][t] = g_WD[0 * HD + t];
    sv[2][t] = g_WS[1 * HD + t];
    sv[3][t] = g_WD[1 * HD + t];
    sv[4][t] = g_WS[2 * HD + t];
    sv[5][t] = g_WD[3 * HD + t];
    __syncthreads();
    int w = (blockIdx.x * blockDim.x + t) >> 5;
    int lane = t & 31;
    if (w >= NVN) return;
    const float* row = xv + (size_t)w * HD;
    float s[6] = {0, 0, 0, 0, 0, 0};
    #pragma unroll
    for (int j0 = 0; j0 < HD; j0 += 32) {
        float x = row[j0 + lane];
        #pragma unroll
        for (int k = 0; k < 6; k++) s[k] += x * sv[k][j0 + lane];
    }
    #pragma unroll
    for (int k = 0; k < 6; k++)
        #pragma unroll
        for (int o = 16; o > 0; o >>= 1) s[k] += __shfl_xor_sync(0xffffffffu, s[k], o);
    if (lane == 0) {
        g_AS0[w] = s[0]; g_AD0[w] = s[1];
        g_AS1[w] = s[2]; g_AD1[w] = s[3];
        g_AS2[w] = s[4]; g_AD3[w] = s[5];
    }
}

__global__ void avec_con_kernel(const float* __restrict__ xc) {
    __shared__ float sv[2][HD];
    int t = threadIdx.x;
    sv[0][t] = g_WD[2 * HD + t];
    sv[1][t] = g_WS[3 * HD + t];
    __syncthreads();
    int w = (blockIdx.x * blockDim.x + t) >> 5;
    int lane = t & 31;
    if (w >= NCN) return;
    const float* row = xc + (size_t)w * HD;
    float s0 = 0.f, s1 = 0.f;
    #pragma unroll
    for (int j0 = 0; j0 < HD; j0 += 32) {
        float x = row[j0 + lane];
        s0 += x * sv[0][j0 + lane];
        s1 += x * sv[1][j0 + lane];
    }
    #pragma unroll
    for (int o = 16; o > 0; o >>= 1) {
        s0 += __shfl_xor_sync(0xffffffffu, s0, o);
        s1 += __shfl_xor_sync(0xffffffffu, s1, o);
    }
    if (lane == 0) { g_AD2[w] = s0; g_AS3[w] = s1; }
}

// ---------------- CSR build ----------------
__global__ void zero_int_kernel(int* __restrict__ p, int n) {
    int i = blockIdx.x * blockDim.x + threadIdx.x;
    if (i < n) p[i] = 0;
}
__global__ void hist_kernel(const int* __restrict__ dst, int* __restrict__ cnt, int E) {
    int i = blockIdx.x * blockDim.x + threadIdx.x;
    if (i < E) atomicAdd(&cnt[dst[i]], 1);
}
__global__ void scan_kernel(int* __restrict__ rp, int* __restrict__ cursor, int n) {
    __shared__ int swarp[32];
    __shared__ int stot;
    int t = threadIdx.x, w = t >> 5, lane = t & 31;
    int carry = 0;
    for (int base = 0; base < n; base += 1024) {
        int idx = base + t;
        int v = (idx < n) ? rp[idx] : 0;
        int x = v;
        #pragma unroll
        for (int o = 1; o < 32; o <<= 1) {
            int y = __shfl_up_sync(0xffffffffu, x, o);
            if (lane >= o) x += y;
        }
        if (lane == 31) swarp[w] = x;
        __syncthreads();
        if (w == 0) {
            int s = swarp[lane];
            int z = s;
            #pragma unroll
            for (int o = 1; o < 32; o <<= 1) {
                int y = __shfl_up_sync(0xffffffffu, z, o);
                if (lane >= o) z += y;
            }
            swarp[lane] = z - s;
            if (lane == 31) stot = z;
        }
        __syncthreads();
        int excl = carry + swarp[w] + (x - v);
        if (idx < n) { rp[idx] = excl; cursor[idx] = excl; }
        carry += stot;
        __syncthreads();
    }
    if (t == 0) rp[n] = carry;
}
__global__ void scatter_kernel(const int* __restrict__ src, const int* __restrict__ dst,
                               int* __restrict__ cursor, int* __restrict__ cs, int E) {
    int i = blockIdx.x * blockDim.x + threadIdx.x;
    if (i >= E) return;
    int pos = atomicAdd(&cursor[dst[i]], 1);
    cs[pos] = src[i];
}

// ---------------- fused GAT (fp16 XL, lane owns 8 contiguous elems) ----------
__device__ __forceinline__ void gat_accum(
        int d, int lane,
        const int* __restrict__ rp, const int* __restrict__ cs,
        const float* __restrict__ AS, const float* __restrict__ AD,
        const __half* __restrict__ XL,
        float4& acc0, float4& acc1) {
    int off = rp[d];
    int deg = rp[d + 1] - off;
    if (deg <= 0) return;
    float adv = AD[d];
    float m = -1e30f;
    for (int j = lane; j < deg; j += 32) {
        int s = cs[off + j];
        float e = AS[s] + adv;
        e = (e >= 0.f) ? e : 0.2f * e;
        m = fmaxf(m, e);
    }
    #pragma unroll
    for (int o = 16; o > 0; o >>= 1) m = fmaxf(m, __shfl_xor_sync(0xffffffffu, m, o));
    float den = 0.f;
    for (int j = lane; j < deg; j += 32) {
        int s = cs[off + j];
        float e = AS[s] + adv;
        e = (e >= 0.f) ? e : 0.2f * e;
        den += __expf(e - m);
    }
    #pragma unroll
    for (int o = 16; o > 0; o >>= 1) den += __shfl_xor_sync(0xffffffffu, den, o);
    float invden = 1.f / (den + 1e-16f);
    #pragma unroll 4
    for (int j = 0; j < deg; j++) {
        int s = cs[off + j];
        float e = AS[s] + adv;
        e = (e >= 0.f) ? e : 0.2f * e;
        float wgt = __expf(e - m) * invden;
        const uint4 raw = ((const uint4*)(XL + (size_t)s * HD))[lane];
        __half2 p0 = *(const __half2*)&raw.x;
        __half2 p1 = *(const __half2*)&raw.y;
        __half2 p2 = *(const __half2*)&raw.z;
        __half2 p3 = *(const __half2*)&raw.w;
        float2 f0 = __half22float2(p0), f1 = __half22float2(p1);
        float2 f2 = __half22float2(p2), f3 = __half22float2(p3);
        acc0.x += wgt * f0.x; acc0.y += wgt * f0.y;
        acc0.z += wgt * f1.x; acc0.w += wgt * f1.y;
        acc1.x += wgt * f2.x; acc1.y += wgt * f2.y;
        acc1.z += wgt * f3.x; acc1.w += wgt * f3.y;
    }
}

__device__ __forceinline__ void split_store(__half* outh, __half* outl, int w, int lane,
                                            float4 acc0, float4 acc1) {
    __half h0, h1, h2, h3, l0, l1, l2, l3;
    __half2* oh = (__half2*)(outh + (size_t)w * HD) + lane * 4;
    __half2* ol = (__half2*)(outl + (size_t)w * HD) + lane * 4;
    h2split(acc0.x, h0, l0); h2split(acc0.y, h1, l1);
    h2split(acc0.z, h2, l2); h2split(acc0.w, h3, l3);
    oh[0] = __halves2half2(h0, h1);
    oh[1] = __halves2half2(h2, h3);
    ol[0] = __halves2half2(l0, l1);
    ol[1] = __halves2half2(l2, l3);
    h2split(acc1.x, h0, l0); h2split(acc1.y, h1, l1);
    h2split(acc1.z, h2, l2); h2split(acc1.w, h3, l3);
    oh[2] = __halves2half2(h0, h1);
    oh[3] = __halves2half2(h2, h3);
    ol[2] = __halves2half2(l0, l1);
    ol[3] = __halves2half2(l2, l3);
}

// merged var GAT: all 3 CSRs in registers; fp32 out only at last layer
__global__ void gat_var_kernel(const __half* __restrict__ XL0, const __half* __restrict__ XL1,
                               const __half* __restrict__ XL3,
                               const float* __restrict__ bias, int l,
                               float* __restrict__ out,
                               __half* __restrict__ outh, __half* __restrict__ outl,
                               int do_next) {
    int w = (blockIdx.x * blockDim.x + threadIdx.x) >> 5;
    int lane = threadIdx.x & 31;
    if (w >= NVN) return;
    int rv = (l & 1) * NVN, rc = (l & 1) * NCN;
    float4 acc0, acc1;
    {
        const float4* b0 = (const float4*)(bias + (size_t)(4 * l + 0) * HD) + lane * 2;
        const float4* b1 = (const float4*)(bias + (size_t)(4 * l + 1) * HD) + lane * 2;
        const float4* b3 = (const float4*)(bias + (size_t)(4 * l + 3) * HD) + lane * 2;
        float4 x0 = b0[0], y0 = b1[0], z0 = b3[0];
        float4 x1 = b0[1], y1 = b1[1], z1 = b3[1];
        acc0 = make_float4(x0.x + y0.x + z0.x, x0.y + y0.y + z0.y,
                           x0.z + y0.z + z0.z, x0.w + y0.w + z0.w);
        acc1 = make_float4(x1.x + y1.x + z1.x, x1.y + y1.y + z1.y,
                           x1.z + y1.z + z1.z, x1.w + y1.w + z1.w);
    }
    gat_accum(w, lane, g_RP0, g_CS0, g_AS0 + rv, g_AD0 + rv, XL0, acc0, acc1);
    gat_accum(w, lane, g_RP1, g_CS1, g_AS1 + rv, g_AD1 + rv, XL1, acc0, acc1);
    gat_accum(w, lane, g_RP3, g_CS3, g_AS3 + rc, g_AD3 + rv, XL3, acc0, acc1);
    if (!do_next) {
        float4* ob = (float4*)(out + (size_t)w * HD) + lane * 2;
        ob[0] = acc0;
        ob[1] = acc1;
        return;
    }
    split_store(outh, outl, w, lane, acc0, acc1);
    int L = l + 1;
    int wv = ((l + 1) & 1) * NVN;
    float s[6];
    const int vidx[6] = {0, 0, 1, 1, 2, 3};
    #pragma unroll
    for (int k = 0; k < 6; k++) {
        const float* vecb = (k == 1 || k == 3 || k == 5) ? g_WD : g_WS;
        const float4* vp = (const float4*)(vecb + (size_t)(4 * L + vidx[k]) * HD) + lane * 2;
        s[k] = d4(acc0, vp[0]) + d4(acc1, vp[1]);
    }
    #pragma unroll
    for (int k = 0; k < 6; k++)
        #pragma unroll
        for (int o = 16; o > 0; o >>= 1) s[k] += __shfl_xor_sync(0xffffffffu, s[k], o);
    if (lane == 0) {
        g_AS0[wv + w] = s[0]; g_AD0[wv + w] = s[1];
        g_AS1[wv + w] = s[2]; g_AD1[wv + w] = s[3];
        g_AS2[wv + w] = s[4]; g_AD3[wv + w] = s[5];
    }
}

__global__ void gat_con_kernel(const __half* __restrict__ XL2,
                               const float* __restrict__ bias, int l,
                               float* __restrict__ out,
                               __half* __restrict__ outh, __half* __restrict__ outl,
                               int do_next) {
    int w = (blockIdx.x * blockDim.x + threadIdx.x) >> 5;
    int lane = threadIdx.x & 31;
    if (w >= NCN) return;
    int rc = (l & 1) * NCN;
    float4 acc0, acc1;
    const float4* b2 = (const float4*)(bias + (size_t)(4 * l + 2) * HD) + lane * 2;
    acc0 = b2[0];
    acc1 = b2[1];
    gat_accum(w, lane, g_RP2, g_CS2, g_AS2 + (l & 1) * NVN, g_AD2 + rc, XL2, acc0, acc1);
    if (!do_next) {
        float4* ob = (float4*)(out + (size_t)w * HD) + lane * 2;
        ob[0] = acc0;
        ob[1] = acc1;
        return;
    }
    split_store(outh, outl, w, lane, acc0, acc1);
    int L = l + 1;
    int wc = ((l + 1) & 1) * NCN;
    const float4* v0 = (const float4*)(g_WD + (size_t)(4 * L + 2) * HD) + lane * 2;
    const float4* v1 = (const float4*)(g_WS + (size_t)(4 * L + 3) * HD) + lane * 2;
    float s0 = d4(acc0, v0[0]) + d4(acc1, v0[1]);
    float s1 = d4(acc0, v1[0]) + d4(acc1, v1[1]);
    #pragma unroll
    for (int o = 16; o > 0; o >>= 1) {
        s0 += __shfl_xor_sync(0xffffffffu, s0, o);
        s1 += __shfl_xor_sync(0xffffffffu, s1, o);
    }
    if (lane == 0) { g_AD2[wc + w] = s0; g_AS3[wc + w] = s1; }
}

// ---------------- pooling + head ----------------
__global__ void zero_pool_kernel() {
    int i = blockIdx.x * 256 + threadIdx.x;
    g_VP[i] = 0.f;
    g_CP[i] = 0.f;
    if (i < 2 * GN) g_CNT[i] = 0;
}

__global__ void pool_kernel(const float* __restrict__ X, const int* __restrict__ batch,
                            int N, float* __restrict__ S, int* __restrict__ cnt) {
    int w = (blockIdx.x * blockDim.x + threadIdx.x) >> 5;
    int lane = threadIdx.x & 31;
    if (w >= N) return;
    int g = batch[w];
    if (lane == 0) atomicAdd(&cnt[g], 1);
    const float4* xr = (const float4*)(X + (size_t)w * HD);
    float* sb = S + (size_t)g * HD;
    #pragma unroll
    for (int j = 0; j < 2; j++) {
        int idx = lane + 32 * j;
        red4(sb + 4 * idx, xr[idx]);
    }
}

__global__ void finalize_kernel(const float* __restrict__ Wlin, const float* __restrict__ blin,
                                float* __restrict__ out) {
    int g = blockIdx.x, t = threadIdx.x;
    float cv = (float)max(g_CNT[g], 1);
    float cc = (float)max(g_CNT[GN + g], 1);
    float a = g_VP[g * HD + t] / cv;
    float c = g_CP[g * HD + t] / cc;
    float p0 = a * Wlin[t * 2 + 0] + c * Wlin[(HD + t) * 2 + 0];
    float p1 = a * Wlin[t * 2 + 1] + c * Wlin[(HD + t) * 2 + 1];
    __shared__ float s0[256], s1[256];
    s0[t] = p0; s1[t] = p1;
    __syncthreads();
    for (int o = 128; o > 0; o >>= 1) {
        if (t < o) { s0[t] += s0[t + o]; s1[t] += s1[t + o]; }
        __syncthreads();
    }
    if (t == 0) {
        float z0 = s0[0] + blin[0], z1 = s1[0] + blin[1];
        float m = fmaxf(z0, z1);
        float e0 = expf(z0 - m), e1 = expf(z1 - m);
        float inv = 1.f / (e0 + e1);
        out[2 * g + 0] = e0 * inv;
        out[2 * g + 1] = e1 * inv;
    }
}

// ---------------- host ----------------
extern "C" void kernel_launch(void* const* d_in, const int* in_sizes, int n_in,
                              void* d_out, int out_size) {
    const float* x_var   = (const float*)d_in[0];
    const float* x_con   = (const float*)d_in[1];
    const float* W_src   = (const float*)d_in[2];
    const float* W_dst   = (const float*)d_in[3];
    const float* att_src = (const float*)d_in[4];
    const float* att_dst = (const float*)d_in[5];
    const float* bias    = (const float*)d_in[6];
    const float* W_lin   = (const float*)d_in[7];
    const float* b_lin   = (const float*)d_in[8];
    const int* e_vv      = (const int*)d_in[9];
    const int* e_vv_rev  = (const int*)d_in[10];
    const int* e_vc      = (const int*)d_in[11];
    const int* e_cv      = (const int*)d_in[12];
    const int* batch_var = (const int*)d_in[13];
    const int* batch_con = (const int*)d_in[14];
    float* out = (float*)d_out;

    float *pXV, *pXC, *pVP, *pCP;
    __half *pXL0, *pXL1, *pXL2, *pXL3;
    __half *pAhV, *pAlV, *pAhC, *pAlC, *pWhT, *pWlT;
    int *pRP0, *pRP1, *pRP2, *pRP3, *pCU0, *pCU1, *pCU2, *pCU3;
    int *pCS0, *pCS1, *pCS2, *pCS3, *pCNT;
    cudaGetSymbolAddress((void**)&pXV, g_XV0);
    cudaGetSymbolAddress((void**)&pXC, g_XC0);
    cudaGetSymbolAddress((void**)&pXL0, g_XL0);
    cudaGetSymbolAddress((void**)&pXL1, g_XL1);
    cudaGetSymbolAddress((void**)&pXL2, g_XL2);
    cudaGetSymbolAddress((void**)&pXL3, g_XL3);
    cudaGetSymbolAddress((void**)&pAhV, g_AhV);
    cudaGetSymbolAddress((void**)&pAlV, g_AlV);
    cudaGetSymbolAddress((void**)&pAhC, g_AhC);
    cudaGetSymbolAddress((void**)&pAlC, g_AlC);
    cudaGetSymbolAddress((void**)&pWhT, g_WhT);
    cudaGetSymbolAddress((void**)&pWlT, g_WlT);
    cudaGetSymbolAddress((void**)&pRP0, g_RP0);
    cudaGetSymbolAddress((void**)&pRP1, g_RP1);
    cudaGetSymbolAddress((void**)&pRP2, g_RP2);
    cudaGetSymbolAddress((void**)&pRP3, g_RP3);
    cudaGetSymbolAddress((void**)&pCU0, g_CU0);
    cudaGetSymbolAddress((void**)&pCU1, g_CU1);
    cudaGetSymbolAddress((void**)&pCU2, g_CU2);
    cudaGetSymbolAddress((void**)&pCU3, g_CU3);
    cudaGetSymbolAddress((void**)&pCS0, g_CS0);
    cudaGetSymbolAddress((void**)&pCS1, g_CS1);
    cudaGetSymbolAddress((void**)&pCS2, g_CS2);
    cudaGetSymbolAddress((void**)&pCS3, g_CS3);
    cudaGetSymbolAddress((void**)&pVP, g_VP);
    cudaGetSymbolAddress((void**)&pCP, g_CP);
    cudaGetSymbolAddress((void**)&pCNT, g_CNT);

    cudaFuncSetAttribute(gemm_fp16_kernel,
                         cudaFuncAttributeMaxDynamicSharedMemorySize, SMEM_BYTES);

    const int EB = 256;
    dim3 gemmGrid((NVN + 127) / 128, 8);

    split_kernel<<<(NVN * HD / 4 + EB - 1) / EB, EB>>>(x_var, pAhV, pAlV, NVN * HD / 4);
    split_kernel<<<(NCN * HD / 4 + EB - 1) / EB, EB>>>(x_con, pAhC, pAlC, NCN * HD / 4);
    wsplit_kernel<<<dim3(8, 8, 16), dim3(32, 8)>>>(W_src);

    gemm_fp16_kernel<<<gemmGrid, 256, SMEM_BYTES>>>(
        pAhV, pAlV, pAhC, pAlC, pWhT, pWlT, pXL0, pXL1, pXL2, pXL3);

    wsd_kernel<<<16, 256>>>(W_src, W_dst, att_src, att_dst);
    avec_var_kernel<<<(NVN * 32 + EB - 1) / EB, EB>>>(x_var);
    avec_con_kernel<<<(NCN * 32 + EB - 1) / EB, EB>>>(x_con);

    zero_int_kernel<<<(NVN + 1 + EB - 1) / EB, EB>>>(pRP0, NVN + 1);
    zero_int_kernel<<<(NVN + 1 + EB - 1) / EB, EB>>>(pRP1, NVN + 1);
    zero_int_kernel<<<(NVN + 1 + EB - 1) / EB, EB>>>(pRP3, NVN + 1);
    zero_int_kernel<<<(NCN + 1 + EB - 1) / EB, EB>>>(pRP2, NCN + 1);
    hist_kernel<<<(EVVN + EB - 1) / EB, EB>>>(e_vv + EVVN, pRP0, EVVN);
    hist_kernel<<<(EVVN + EB - 1) / EB, EB>>>(e_vv_rev + EVVN, pRP1, EVVN);
    hist_kernel<<<(EVCN + EB - 1) / EB, EB>>>(e_cv + EVCN, pRP3, EVCN);
    hist_kernel<<<(EVCN + EB - 1) / EB, EB>>>(e_vc + EVCN, pRP2, EVCN);
    scan_kernel<<<1, 1024>>>(pRP0, pCU0, NVN);
    scan_kernel<<<1, 1024>>>(pRP1, pCU1, NVN);
    scan_kernel<<<1, 1024>>>(pRP3, pCU3, NVN);
    scan_kernel<<<1, 1024>>>(pRP2, pCU2, NCN);
    scatter_kernel<<<(EVVN + EB - 1) / EB, EB>>>(e_vv, e_vv + EVVN, pCU0, pCS0, EVVN);
    scatter_kernel<<<(EVVN + EB - 1) / EB, EB>>>(e_vv_rev, e_vv_rev + EVVN, pCU1, pCS1, EVVN);
    scatter_kernel<<<(EVCN + EB - 1) / EB, EB>>>(e_cv, e_cv + EVCN, pCU3, pCS3, EVCN);
    scatter_kernel<<<(EVCN + EB - 1) / EB, EB>>>(e_vc, e_vc + EVCN, pCU2, pCS2, EVCN);

    int gatVB = (NVN * 32 + EB - 1) / EB;
    int gatCB = (NCN * 32 + EB - 1) / EB;

    for (int l = 0; l < NLAYER; l++) {
        int do_next = (l + 1 < NLAYER) ? 1 : 0;

        if (l > 0) {
            gemm_fp16_kernel<<<gemmGrid, 256, SMEM_BYTES>>>(
                pAhV, pAlV, pAhC, pAlC,
                pWhT + (size_t)(4 * l) * HD * HD, pWlT + (size_t)(4 * l) * HD * HD,
                pXL0, pXL1, pXL2, pXL3);
        }

        gat_var_kernel<<<gatVB, EB>>>(pXL0, pXL1, pXL3, bias, l,
                                      pXV, pAhV, pAlV, do_next);
        gat_con_kernel<<<gatCB, EB>>>(pXL2, bias, l,
                                      pXC, pAhC, pAlC, do_next);
    }

    zero_pool_kernel<<<GN, 256>>>();
    pool_kernel<<<gatVB, EB>>>(pXV, batch_var, NVN, pVP, pCNT);
    pool_kernel<<<gatCB, EB>>>(pXC, batch_con, NCN, pCP, pCNT + GN);
    finalize_kernel<<<GN, 256>>>(W_lin, b_lin, out);
}

// round 15
// speedup vs baseline: 2.3783x; 1.2372x over previous
#include <cuda_runtime.h>
#include <cuda_fp16.h>
#include <cstdint>
#include <cstddef>

#define NVN 50000
#define NCN 20000
#define HD  256
#define NLAYER 4
#define EVVN 500000
#define EVCN 300000
#define GN  64

#define ASTR 40
#define BK 32
#define NSTAGE 2
// halves: A h+l stages + B h stage
#define SMEM_HALVES (NSTAGE*128*ASTR*2 + NSTAGE*128*ASTR)
#define SMEM_BYTES  (SMEM_HALVES*2)

// ---------------- scratch ----------------
__device__ __align__(128) float g_XV0[NVN * HD];
__device__ __align__(128) float g_XC0[NCN * HD];
__device__ __align__(128) __half g_XL0[NVN * HD];
__device__ __align__(128) __half g_XL1[NVN * HD];
__device__ __align__(128) __half g_XL2[NVN * HD];
__device__ __align__(128) __half g_XL3[NCN * HD];

__device__ __align__(128) __half g_AhV[NVN * HD];
__device__ __align__(128) __half g_AlV[NVN * HD];
__device__ __align__(128) __half g_AhC[NCN * HD];
__device__ __align__(128) __half g_AlC[NCN * HD];
__device__ __align__(128) __half g_WhT[16 * HD * HD];  // [mat][n][k]

__device__ float g_AS0[2 * NVN], g_AD0[2 * NVN];
__device__ float g_AS1[2 * NVN], g_AD1[2 * NVN];
__device__ float g_AS2[2 * NVN], g_AD3[2 * NVN];
__device__ float g_AS3[2 * NCN], g_AD2[2 * NCN];

__device__ __align__(128) float g_WS[16 * HD];
__device__ __align__(128) float g_WD[16 * HD];

__device__ int g_RP0[NVN + 1], g_RP1[NVN + 1], g_RP3[NVN + 1], g_RP2[NCN + 1];
__device__ int g_CU0[NVN], g_CU1[NVN], g_CU3[NVN], g_CU2[NCN];
__device__ int g_CS0[EVVN], g_CS1[EVVN], g_CS3[EVCN], g_CS2[EVCN];

__device__ __align__(128) float g_VP[GN * HD];
__device__ __align__(128) float g_CP[GN * HD];
__device__ int   g_CNT[2 * GN];

// ---------------- helpers ----------------
__device__ __forceinline__ void red4(float* p, float4 v) {
    asm volatile("red.global.add.v4.f32 [%0], {%1,%2,%3,%4};"
                 :: "l"(p), "f"(v.x), "f"(v.y), "f"(v.z), "f"(v.w) : "memory");
}
__device__ __forceinline__ void h2split(float x, __half& h, __half& l) {
    h = __float2half_rn(x);
    l = __float2half_rn(x - __half2float(h));
}
__device__ __forceinline__ void ldsm4(uint32_t* r, const void* p) {
    uint32_t addr = (uint32_t)__cvta_generic_to_shared(p);
    asm volatile("ldmatrix.sync.aligned.m8n8.x4.shared.b16 {%0,%1,%2,%3}, [%4];"
                 : "=r"(r[0]), "=r"(r[1]), "=r"(r[2]), "=r"(r[3]) : "r"(addr));
}
__device__ __forceinline__ void ldsm2(uint32_t* r, const void* p) {
    uint32_t addr = (uint32_t)__cvta_generic_to_shared(p);
    asm volatile("ldmatrix.sync.aligned.m8n8.x2.shared.b16 {%0,%1}, [%2];"
                 : "=r"(r[0]), "=r"(r[1]) : "r"(addr));
}
__device__ __forceinline__ void mma_f16(float* c, const uint32_t* a, const uint32_t* b) {
    asm volatile(
        "mma.sync.aligned.m16n8k16.row.col.f32.f16.f16.f32 "
        "{%0,%1,%2,%3}, {%4,%5,%6,%7}, {%8,%9}, {%0,%1,%2,%3};"
        : "+f"(c[0]), "+f"(c[1]), "+f"(c[2]), "+f"(c[3])
        : "r"(a[0]), "r"(a[1]), "r"(a[2]), "r"(a[3]), "r"(b[0]), "r"(b[1]));
}
__device__ __forceinline__ void cpa16(void* dst, const void* src, bool valid) {
    uint32_t d = (uint32_t)__cvta_generic_to_shared(dst);
    int sz = valid ? 16 : 0;
    asm volatile("cp.async.ca.shared.global [%0], [%1], 16, %2;"
                 :: "r"(d), "l"(src), "r"(sz));
}
__device__ __forceinline__ float d4(float4 a, float4 b) {
    return a.x * b.x + a.y * b.y + a.z * b.z + a.w * b.w;
}

// ---------------- ws/wd precompute ----------------
__global__ void wsd_kernel(const float* __restrict__ Wsrc, const float* __restrict__ Wdst,
                           const float* __restrict__ as, const float* __restrict__ ad) {
    int b = blockIdx.x;
    int i = threadIdx.x;
    __shared__ float sas[HD], sad[HD];
    sas[i] = as[b * HD + i];
    sad[i] = ad[b * HD + i];
    __syncthreads();
    const float* Ws = Wsrc + (size_t)b * HD * HD + (size_t)i * HD;
    const float* Wd = Wdst + (size_t)b * HD * HD + (size_t)i * HD;
    float s = 0.f, d = 0.f;
    #pragma unroll 8
    for (int j = 0; j < HD; j++) { s += Ws[j] * sas[j]; d += Wd[j] * sad[j]; }
    g_WS[b * HD + i] = s;
    g_WD[b * HD + i] = d;
}

// ---------------- activation split ----------------
__global__ void split_kernel(const float* __restrict__ X, __half* __restrict__ Xh,
                             __half* __restrict__ Xl, int n4) {
    int i = blockIdx.x * blockDim.x + threadIdx.x;
    if (i >= n4) return;
    float4 v = ((const float4*)X)[i];
    __half h0, h1, h2, h3, l0, l1, l2, l3;
    h2split(v.x, h0, l0); h2split(v.y, h1, l1);
    h2split(v.z, h2, l2); h2split(v.w, h3, l3);
    ((__half2*)Xh)[i * 2 + 0] = __halves2half2(h0, h1);
    ((__half2*)Xh)[i * 2 + 1] = __halves2half2(h2, h3);
    ((__half2*)Xl)[i * 2 + 0] = __halves2half2(l0, l1);
    ((__half2*)Xl)[i * 2 + 1] = __halves2half2(l2, l3);
}

// ---------------- W transpose (hi only) ----------------
__global__ void wsplit_kernel(const float* __restrict__ W) {
    __shared__ float tile[32][33];
    int mat = blockIdx.z;
    int bk = blockIdx.x * 32, bn = blockIdx.y * 32;
    int tx = threadIdx.x, ty = threadIdx.y;
    const float* Wm = W + (size_t)mat * HD * HD;
    #pragma unroll
    for (int r = 0; r < 32; r += 8)
        tile[ty + r][tx] = Wm[(size_t)(bk + ty + r) * HD + bn + tx];
    __syncthreads();
    #pragma unroll
    for (int r = 0; r < 32; r += 8) {
        float x = tile[tx][ty + r];
        size_t o = (size_t)mat * HD * HD + (size_t)(bn + ty + r) * HD + bk + tx;
        g_WhT[o] = __float2half_rn(x);
    }
}

// ---------------- fp16x2 GEMM: (Ah+Al) x Wh, 128x128, 2-stage ----------
__global__ __launch_bounds__(256, 2) void gemm_fp16_kernel(
        const __half* __restrict__ AhV, const __half* __restrict__ AlV,
        const __half* __restrict__ AhC, const __half* __restrict__ AlC,
        const __half* __restrict__ WhT,
        __half* __restrict__ C0, __half* __restrict__ C1,
        __half* __restrict__ C2, __half* __restrict__ C3) {
    extern __shared__ __half smh[];
    __half* pAh = smh;
    __half* pAl = pAh + NSTAGE * 128 * ASTR;
    __half* pBh = pAl + NSTAGE * 128 * ASTR;

    const int mat = blockIdx.y >> 1;
    const int N = (mat == 3) ? NCN : NVN;
    const int row0 = blockIdx.x * 128;
    if (row0 >= N) return;
    const __half* Ah = (mat == 3) ? AhC : AhV;
    const __half* Al = (mat == 3) ? AlC : AlV;
    __half* C = (mat == 0) ? C0 : (mat == 1) ? C1 : (mat == 2) ? C2 : C3;
    const int col0 = (blockIdx.y & 1) * 128;
    const __half* W_h = WhT + (size_t)mat * HD * HD;

    const int tid = threadIdx.x;
    const int lane = tid & 31;
    const int wid = tid >> 5;
    const int wm = (wid & 3) * 32;
    const int wn = (wid >> 2) * 64;

    const int arow = tid >> 1;
    const int acol = (tid & 1) * 16;

    float acc[2][8][4];
    #pragma unroll
    for (int i = 0; i < 2; i++)
        #pragma unroll
        for (int j = 0; j < 8; j++)
            #pragma unroll
            for (int q = 0; q < 4; q++) acc[i][j][q] = 0.f;

    const int g = lane >> 2, t4 = lane & 3;
    const int lr = lane & 15;
    const int lk = (lane >> 4) * 8;
    const int br = lane & 7;
    const int bko = ((lane >> 3) & 1) * 8;

    auto load_stage = [&](int s, int k0) {
        bool v = (row0 + arow) < N;
        const __half* ah = v ? (Ah + (size_t)(row0 + arow) * HD + k0 + acol) : Ah;
        const __half* al = v ? (Al + (size_t)(row0 + arow) * HD + k0 + acol) : Al;
        __half* dh = pAh + s * 128 * ASTR + arow * ASTR + acol;
        __half* dl = pAl + s * 128 * ASTR + arow * ASTR + acol;
        cpa16(dh,     ah,     v);
        cpa16(dh + 8, ah + 8, v);
        cpa16(dl,     al,     v);
        cpa16(dl + 8, al + 8, v);
        __half* eh = pBh + s * 128 * ASTR + arow * ASTR + acol;
        const __half* wh = W_h + (size_t)(col0 + arow) * HD + k0 + acol;
        cpa16(eh,     wh,     true);
        cpa16(eh + 8, wh + 8, true);
        asm volatile("cp.async.commit_group;");
    };

    load_stage(0, 0);

    for (int kt = 0; kt < 8; kt++) {
        asm volatile("cp.async.wait_group 0;");
        __syncthreads();
        if (kt + 1 < 8) load_stage((kt + 1) & 1, (kt + 1) * BK);

        const int cur = kt & 1;
        const __half* cAh = pAh + cur * 128 * ASTR;
        const __half* cAl = pAl + cur * 128 * ASTR;
        const __half* cBh = pBh + cur * 128 * ASTR;

        #pragma unroll
        for (int ks = 0; ks < 2; ks++) {
            const int kb = ks * 16;
            uint32_t ah[2][4], al[2][4];
            #pragma unroll
            for (int i = 0; i < 2; i++) {
                ldsm4(ah[i], cAh + (size_t)(wm + i * 16 + lr) * ASTR + kb + lk);
                ldsm4(al[i], cAl + (size_t)(wm + i * 16 + lr) * ASTR + kb + lk);
            }
            #pragma unroll
            for (int j = 0; j < 8; j++) {
                uint32_t bh[2];
                ldsm2(bh, cBh + (size_t)(wn + j * 8 + br) * ASTR + kb + bko);
                #pragma unroll
                for (int i = 0; i < 2; i++) {
                    mma_f16(acc[i][j], ah[i], bh);
                    mma_f16(acc[i][j], al[i], bh);
                }
            }
        }
    }

    #pragma unroll
    for (int i = 0; i < 2; i++) {
        int r0 = row0 + wm + i * 16 + g;
        #pragma unroll
        for (int j = 0; j < 8; j++) {
            int c = col0 + wn + j * 8 + t4 * 2;
            if (r0 < N)
                *(__half2*)(C + (size_t)r0 * HD + c) =
                    __floats2half2_rn(acc[i][j][0], acc[i][j][1]);
            if (r0 + 8 < N)
                *(__half2*)(C + (size_t)(r0 + 8) * HD + c) =
                    __floats2half2_rn(acc[i][j][2], acc[i][j][3]);
        }
    }
}

// ---------------- standalone attention dots (layer 0 only) ----------------
__global__ void avec_var_kernel(const float* __restrict__ xv) {
    __shared__ float sv[6][HD];
    int t = threadIdx.x;
    sv[0][t] = g_WS[0 * HD + t];
    sv[1][t] = g_WD[0 * HD + t];
    sv[2][t] = g_WS[1 * HD + t];
    sv[3][t] = g_WD[1 * HD + t];
    sv[4][t] = g_WS[2 * HD + t];
    sv[5][t] = g_WD[3 * HD + t];
    __syncthreads();
    int w = (blockIdx.x * blockDim.x + t) >> 5;
    int lane = t & 31;
    if (w >= NVN) return;
    const float* row = xv + (size_t)w * HD;
    float s[6] = {0, 0, 0, 0, 0, 0};
    #pragma unroll
    for (int j0 = 0; j0 < HD; j0 += 32) {
        float x = row[j0 + lane];
        #pragma unroll
        for (int k = 0; k < 6; k++) s[k] += x * sv[k][j0 + lane];
    }
    #pragma unroll
    for (int k = 0; k < 6; k++)
        #pragma unroll
        for (int o = 16; o > 0; o >>= 1) s[k] += __shfl_xor_sync(0xffffffffu, s[k], o);
    if (lane == 0) {
        g_AS0[w] = s[0]; g_AD0[w] = s[1];
        g_AS1[w] = s[2]; g_AD1[w] = s[3];
        g_AS2[w] = s[4]; g_AD3[w] = s[5];
    }
}

__global__ void avec_con_kernel(const float* __restrict__ xc) {
    __shared__ float sv[2][HD];
    int t = threadIdx.x;
    sv[0][t] = g_WD[2 * HD + t];
    sv[1][t] = g_WS[3 * HD + t];
    __syncthreads();
    int w = (blockIdx.x * blockDim.x + t) >> 5;
    int lane = t & 31;
    if (w >= NCN) return;
    const float* row = xc + (size_t)w * HD;
    float s0 = 0.f, s1 = 0.f;
    #pragma unroll
    for (int j0 = 0; j0 < HD; j0 += 32) {
        float x = row[j0 + lane];
        s0 += x * sv[0][j0 + lane];
        s1 += x * sv[1][j0 + lane];
    }
    #pragma unroll
    for (int o = 16; o > 0; o >>= 1) {
        s0 += __shfl_xor_sync(0xffffffffu, s0, o);
        s1 += __shfl_xor_sync(0xffffffffu, s1, o);
    }
    if (lane == 0) { g_AD2[w] = s0; g_AS3[w] = s1; }
}

// ---------------- CSR build (merged kernels) ----------------
__global__ void zero_all_kernel() {
    int i = blockIdx.x * blockDim.x + threadIdx.x;
    if (i <= NVN) { g_RP0[i] = 0; g_RP1[i] = 0; g_RP3[i] = 0; }
    if (i <= NCN) g_RP2[i] = 0;
}
__global__ void hist_all_kernel(const int* __restrict__ dvv, const int* __restrict__ dvvr,
                                const int* __restrict__ dcv, const int* __restrict__ dvc) {
    int i = blockIdx.x * blockDim.x + threadIdx.x;
    if (i < EVVN) atomicAdd(&g_RP0[dvv[i]], 1);
    else if (i < 2 * EVVN) atomicAdd(&g_RP1[dvvr[i - EVVN]], 1);
    else if (i < 2 * EVVN + EVCN) atomicAdd(&g_RP3[dcv[i - 2 * EVVN]], 1);
    else if (i < 2 * EVVN + 2 * EVCN) atomicAdd(&g_RP2[dvc[i - 2 * EVVN - EVCN]], 1);
}
// 4 concurrent scans: blockIdx selects array
__global__ void scan_all_kernel() {
    __shared__ int swarp[32];
    __shared__ int stot;
    int which = blockIdx.x;
    int* rp     = (which == 0) ? g_RP0 : (which == 1) ? g_RP1 : (which == 2) ? g_RP3 : g_RP2;
    int* cursor = (which == 0) ? g_CU0 : (which == 1) ? g_CU1 : (which == 2) ? g_CU3 : g_CU2;
    int n = (which == 3) ? NCN : NVN;
    int t = threadIdx.x, w = t >> 5, lane = t & 31;
    int carry = 0;
    for (int base = 0; base < n; base += 1024) {
        int idx = base + t;
        int v = (idx < n) ? rp[idx] : 0;
        int x = v;
        #pragma unroll
        for (int o = 1; o < 32; o <<= 1) {
            int y = __shfl_up_sync(0xffffffffu, x, o);
            if (lane >= o) x += y;
        }
        if (lane == 31) swarp[w] = x;
        __syncthreads();
        if (w == 0) {
            int s = swarp[lane];
            int z = s;
            #pragma unroll
            for (int o = 1; o < 32; o <<= 1) {
                int y = __shfl_up_sync(0xffffffffu, z, o);
                if (lane >= o) z += y;
            }
            swarp[lane] = z - s;
            if (lane == 31) stot = z;
        }
        __syncthreads();
        int excl = carry + swarp[w] + (x - v);
        if (idx < n) { rp[idx] = excl; cursor[idx] = excl; }
        carry += stot;
        __syncthreads();
    }
    if (t == 0) rp[n] = carry;
}
__global__ void scatter_all_kernel(const int* __restrict__ e_vv, const int* __restrict__ e_vvr,
                                   const int* __restrict__ e_cv, const int* __restrict__ e_vc) {
    int i = blockIdx.x * blockDim.x + threadIdx.x;
    if (i < EVVN) {
        int pos = atomicAdd(&g_CU0[e_vv[EVVN + i]], 1);
        g_CS0[pos] = e_vv[i];
    } else if (i < 2 * EVVN) {
        int j = i - EVVN;
        int pos = atomicAdd(&g_CU1[e_vvr[EVVN + j]], 1);
        g_CS1[pos] = e_vvr[j];
    } else if (i < 2 * EVVN + EVCN) {
        int j = i - 2 * EVVN;
        int pos = atomicAdd(&g_CU3[e_cv[EVCN + j]], 1);
        g_CS3[pos] = e_cv[j];
    } else if (i < 2 * EVVN + 2 * EVCN) {
        int j = i - 2 * EVVN - EVCN;
        int pos = atomicAdd(&g_CU2[e_vc[EVCN + j]], 1);
        g_CS2[pos] = e_vc[j];
    }
}

// ---------------- fused GAT (fp16 XL, lane owns 8 contiguous elems) ----------
__device__ __forceinline__ void gat_accum(
        int d, int lane,
        const int* __restrict__ rp, const int* __restrict__ cs,
        const float* __restrict__ AS, const float* __restrict__ AD,
        const __half* __restrict__ XL,
        float4& acc0, float4& acc1) {
    int off = rp[d];
    int deg = rp[d + 1] - off;
    if (deg <= 0) return;
    float adv = AD[d];
    float m = -1e30f;
    for (int j = lane; j < deg; j += 32) {
        int s = cs[off + j];
        float e = AS[s] + adv;
        e = (e >= 0.f) ? e : 0.2f * e;
        m = fmaxf(m, e);
    }
    #pragma unroll
    for (int o = 16; o > 0; o >>= 1) m = fmaxf(m, __shfl_xor_sync(0xffffffffu, m, o));
    float den = 0.f;
    for (int j = lane; j < deg; j += 32) {
        int s = cs[off + j];
        float e = AS[s] + adv;
        e = (e >= 0.f) ? e : 0.2f * e;
        den += __expf(e - m);
    }
    #pragma unroll
    for (int o = 16; o > 0; o >>= 1) den += __shfl_xor_sync(0xffffffffu, den, o);
    float invden = 1.f / (den + 1e-16f);
    #pragma unroll 4
    for (int j = 0; j < deg; j++) {
        int s = cs[off + j];
        float e = AS[s] + adv;
        e = (e >= 0.f) ? e : 0.2f * e;
        float wgt = __expf(e - m) * invden;
        const uint4 raw = ((const uint4*)(XL + (size_t)s * HD))[lane];
        __half2 p0 = *(const __half2*)&raw.x;
        __half2 p1 = *(const __half2*)&raw.y;
        __half2 p2 = *(const __half2*)&raw.z;
        __half2 p3 = *(const __half2*)&raw.w;
        float2 f0 = __half22float2(p0), f1 = __half22float2(p1);
        float2 f2 = __half22float2(p2), f3 = __half22float2(p3);
        acc0.x += wgt * f0.x; acc0.y += wgt * f0.y;
        acc0.z += wgt * f1.x; acc0.w += wgt * f1.y;
        acc1.x += wgt * f2.x; acc1.y += wgt * f2.y;
        acc1.z += wgt * f3.x; acc1.w += wgt * f3.y;
    }
}

__device__ __forceinline__ void split_store(__half* outh, __half* outl, int w, int lane,
                                            float4 acc0, float4 acc1) {
    __half h0, h1, h2, h3, l0, l1, l2, l3;
    __half2* oh = (__half2*)(outh + (size_t)w * HD) + lane * 4;
    __half2* ol = (__half2*)(outl + (size_t)w * HD) + lane * 4;
    h2split(acc0.x, h0, l0); h2split(acc0.y, h1, l1);
    h2split(acc0.z, h2, l2); h2split(acc0.w, h3, l3);
    oh[0] = __halves2half2(h0, h1);
    oh[1] = __halves2half2(h2, h3);
    ol[0] = __halves2half2(l0, l1);
    ol[1] = __halves2half2(l2, l3);
    h2split(acc1.x, h0, l0); h2split(acc1.y, h1, l1);
    h2split(acc1.z, h2, l2); h2split(acc1.w, h3, l3);
    oh[2] = __halves2half2(h0, h1);
    oh[3] = __halves2half2(h2, h3);
    ol[2] = __halves2half2(l0, l1);
    ol[3] = __halves2half2(l2, l3);
}

// merged var GAT
__global__ void gat_var_kernel(const __half* __restrict__ XL0, const __half* __restrict__ XL1,
                               const __half* __restrict__ XL3,
                               const float* __restrict__ bias, int l,
                               float* __restrict__ out,
                               __half* __restrict__ outh, __half* __restrict__ outl,
                               int do_next) {
    int w = (blockIdx.x * blockDim.x + threadIdx.x) >> 5;
    int lane = threadIdx.x & 31;
    if (w >= NVN) return;
    int rv = (l & 1) * NVN, rc = (l & 1) * NCN;
    float4 acc0, acc1;
    {
        const float4* b0 = (const float4*)(bias + (size_t)(4 * l + 0) * HD) + lane * 2;
        const float4* b1 = (const float4*)(bias + (size_t)(4 * l + 1) * HD) + lane * 2;
        const float4* b3 = (const float4*)(bias + (size_t)(4 * l + 3) * HD) + lane * 2;
        float4 x0 = b0[0], y0 = b1[0], z0 = b3[0];
        float4 x1 = b0[1], y1 = b1[1], z1 = b3[1];
        acc0 = make_float4(x0.x + y0.x + z0.x, x0.y + y0.y + z0.y,
                           x0.z + y0.z + z0.z, x0.w + y0.w + z0.w);
        acc1 = make_float4(x1.x + y1.x + z1.x, x1.y + y1.y + z1.y,
                           x1.z + y1.z + z1.z, x1.w + y1.w + z1.w);
    }
    gat_accum(w, lane, g_RP0, g_CS0, g_AS0 + rv, g_AD0 + rv, XL0, acc0, acc1);
    gat_accum(w, lane, g_RP1, g_CS1, g_AS1 + rv, g_AD1 + rv, XL1, acc0, acc1);
    gat_accum(w, lane, g_RP3, g_CS3, g_AS3 + rc, g_AD3 + rv, XL3, acc0, acc1);
    if (!do_next) {
        float4* ob = (float4*)(out + (size_t)w * HD) + lane * 2;
        ob[0] = acc0;
        ob[1] = acc1;
        return;
    }
    split_store(outh, outl, w, lane, acc0, acc1);
    int L = l + 1;
    int wv = ((l + 1) & 1) * NVN;
    float s[6];
    const int vidx[6] = {0, 0, 1, 1, 2, 3};
    #pragma unroll
    for (int k = 0; k < 6; k++) {
        const float* vecb = (k == 1 || k == 3 || k == 5) ? g_WD : g_WS;
        const float4* vp = (const float4*)(vecb + (size_t)(4 * L + vidx[k]) * HD) + lane * 2;
        s[k] = d4(acc0, vp[0]) + d4(acc1, vp[1]);
    }
    #pragma unroll
    for (int k = 0; k < 6; k++)
        #pragma unroll
        for (int o = 16; o > 0; o >>= 1) s[k] += __shfl_xor_sync(0xffffffffu, s[k], o);
    if (lane == 0) {
        g_AS0[wv + w] = s[0]; g_AD0[wv + w] = s[1];
        g_AS1[wv + w] = s[2]; g_AD1[wv + w] = s[3];
        g_AS2[wv + w] = s[4]; g_AD3[wv + w] = s[5];
    }
}

__global__ void gat_con_kernel(const __half* __restrict__ XL2,
                               const float* __restrict__ bias, int l,
                               float* __restrict__ out,
                               __half* __restrict__ outh, __half* __restrict__ outl,
                               int do_next) {
    int w = (blockIdx.x * blockDim.x + threadIdx.x) >> 5;
    int lane = threadIdx.x & 31;
    if (w >= NCN) return;
    int rc = (l & 1) * NCN;
    float4 acc0, acc1;
    const float4* b2 = (const float4*)(bias + (size_t)(4 * l + 2) * HD) + lane * 2;
    acc0 = b2[0];
    acc1 = b2[1];
    gat_accum(w, lane, g_RP2, g_CS2, g_AS2 + (l & 1) * NVN, g_AD2 + rc, XL2, acc0, acc1);
    if (!do_next) {
        float4* ob = (float4*)(out + (size_t)w * HD) + lane * 2;
        ob[0] = acc0;
        ob[1] = acc1;
        return;
    }
    split_store(outh, outl, w, lane, acc0, acc1);
    int L = l + 1;
    int wc = ((l + 1) & 1) * NCN;
    const float4* v0 = (const float4*)(g_WD + (size_t)(4 * L + 2) * HD) + lane * 2;
    const float4* v1 = (const float4*)(g_WS + (size_t)(4 * L + 3) * HD) + lane * 2;
    float s0 = d4(acc0, v0[0]) + d4(acc1, v0[1]);
    float s1 = d4(acc0, v1[0]) + d4(acc1, v1[1]);
    #pragma unroll
    for (int o = 16; o > 0; o >>= 1) {
        s0 += __shfl_xor_sync(0xffffffffu, s0, o);
        s1 += __shfl_xor_sync(0xffffffffu, s1, o);
    }
    if (lane == 0) { g_AD2[wc + w] = s0; g_AS3[wc + w] = s1; }
}

// ---------------- pooling + head ----------------
__global__ void zero_pool_kernel() {
    int i = blockIdx.x * 256 + threadIdx.x;
    g_VP[i] = 0.f;
    g_CP[i] = 0.f;
    if (i < 2 * GN) g_CNT[i] = 0;
}

__global__ void pool_kernel(const float* __restrict__ X, const int* __restrict__ batch,
                            int N, float* __restrict__ S, int* __restrict__ cnt) {
    int w = (blockIdx.x * blockDim.x + threadIdx.x) >> 5;
    int lane = threadIdx.x & 31;
    if (w >= N) return;
    int g = batch[w];
    if (lane == 0) atomicAdd(&cnt[g], 1);
    const float4* xr = (const float4*)(X + (size_t)w * HD);
    float* sb = S + (size_t)g * HD;
    #pragma unroll
    for (int j = 0; j < 2; j++) {
        int idx = lane + 32 * j;
        red4(sb + 4 * idx, xr[idx]);
    }
}

__global__ void finalize_kernel(const float* __restrict__ Wlin, const float* __restrict__ blin,
                                float* __restrict__ out) {
    int g = blockIdx.x, t = threadIdx.x;
    float cv = (float)max(g_CNT[g], 1);
    float cc = (float)max(g_CNT[GN + g], 1);
    float a = g_VP[g * HD + t] / cv;
    float c = g_CP[g * HD + t] / cc;
    float p0 = a * Wlin[t * 2 + 0] + c * Wlin[(HD + t) * 2 + 0];
    float p1 = a * Wlin[t * 2 + 1] + c * Wlin[(HD + t) * 2 + 1];
    __shared__ float s0[256], s1[256];
    s0[t] = p0; s1[t] = p1;
    __syncthreads();
    for (int o = 128; o > 0; o >>= 1) {
        if (t < o) { s0[t] += s0[t + o]; s1[t] += s1[t + o]; }
        __syncthreads();
    }
    if (t == 0) {
        float z0 = s0[0] + blin[0], z1 = s1[0] + blin[1];
        float m = fmaxf(z0, z1);
        float e0 = expf(z0 - m), e1 = expf(z1 - m);
        float inv = 1.f / (e0 + e1);
        out[2 * g + 0] = e0 * inv;
        out[2 * g + 1] = e1 * inv;
    }
}

// ---------------- host ----------------
extern "C" void kernel_launch(void* const* d_in, const int* in_sizes, int n_in,
                              void* d_out, int out_size) {
    const float* x_var   = (const float*)d_in[0];
    const float* x_con   = (const float*)d_in[1];
    const float* W_src   = (const float*)d_in[2];
    const float* W_dst   = (const float*)d_in[3];
    const float* att_src = (const float*)d_in[4];
    const float* att_dst = (const float*)d_in[5];
    const float* bias    = (const float*)d_in[6];
    const float* W_lin   = (const float*)d_in[7];
    const float* b_lin   = (const float*)d_in[8];
    const int* e_vv      = (const int*)d_in[9];
    const int* e_vv_rev  = (const int*)d_in[10];
    const int* e_vc      = (const int*)d_in[11];
    const int* e_cv      = (const int*)d_in[12];
    const int* batch_var = (const int*)d_in[13];
    const int* batch_con = (const int*)d_in[14];
    float* out = (float*)d_out;

    float *pXV, *pXC, *pVP, *pCP;
    __half *pXL0, *pXL1, *pXL2, *pXL3;
    __half *pAhV, *pAlV, *pAhC, *pAlC, *pWhT;
    int* pCNT;
    cudaGetSymbolAddress((void**)&pXV, g_XV0);
    cudaGetSymbolAddress((void**)&pXC, g_XC0);
    cudaGetSymbolAddress((void**)&pXL0, g_XL0);
    cudaGetSymbolAddress((void**)&pXL1, g_XL1);
    cudaGetSymbolAddress((void**)&pXL2, g_XL2);
    cudaGetSymbolAddress((void**)&pXL3, g_XL3);
    cudaGetSymbolAddress((void**)&pAhV, g_AhV);
    cudaGetSymbolAddress((void**)&pAlV, g_AlV);
    cudaGetSymbolAddress((void**)&pAhC, g_AhC);
    cudaGetSymbolAddress((void**)&pAlC, g_AlC);
    cudaGetSymbolAddress((void**)&pWhT, g_WhT);
    cudaGetSymbolAddress((void**)&pVP, g_VP);
    cudaGetSymbolAddress((void**)&pCP, g_CP);
    cudaGetSymbolAddress((void**)&pCNT, g_CNT);

    cudaFuncSetAttribute(gemm_fp16_kernel,
                         cudaFuncAttributeMaxDynamicSharedMemorySize, SMEM_BYTES);

    const int EB = 256;
    dim3 gemmGrid((NVN + 127) / 128, 8);
    const int ETOT = 2 * EVVN + 2 * EVCN;

    split_kernel<<<(NVN * HD / 4 + EB - 1) / EB, EB>>>(x_var, pAhV, pAlV, NVN * HD / 4);
    split_kernel<<<(NCN * HD / 4 + EB - 1) / EB, EB>>>(x_con, pAhC, pAlC, NCN * HD / 4);
    wsplit_kernel<<<dim3(8, 8, 16), dim3(32, 8)>>>(W_src);

    gemm_fp16_kernel<<<gemmGrid, 256, SMEM_BYTES>>>(
        pAhV, pAlV, pAhC, pAlC, pWhT, pXL0, pXL1, pXL2, pXL3);

    wsd_kernel<<<16, 256>>>(W_src, W_dst, att_src, att_dst);
    avec_var_kernel<<<(NVN * 32 + EB - 1) / EB, EB>>>(x_var);
    avec_con_kernel<<<(NCN * 32 + EB - 1) / EB, EB>>>(x_con);

    zero_all_kernel<<<(NVN + 1 + EB - 1) / EB, EB>>>();
    hist_all_kernel<<<(ETOT + EB - 1) / EB, EB>>>(e_vv + EVVN, e_vv_rev + EVVN,
                                                  e_cv + EVCN, e_vc + EVCN);
    scan_all_kernel<<<4, 1024>>>();
    scatter_all_kernel<<<(ETOT + EB - 1) / EB, EB>>>(e_vv, e_vv_rev, e_cv, e_vc);

    int gatVB = (NVN * 32 + EB - 1) / EB;
    int gatCB = (NCN * 32 + EB - 1) / EB;

    for (int l = 0; l < NLAYER; l++) {
        int do_next = (l + 1 < NLAYER) ? 1 : 0;

        if (l > 0) {
            gemm_fp16_kernel<<<gemmGrid, 256, SMEM_BYTES>>>(
                pAhV, pAlV, pAhC, pAlC,
                pWhT + (size_t)(4 * l) * HD * HD,
                pXL0, pXL1, pXL2, pXL3);
        }

        gat_var_kernel<<<gatVB, EB>>>(pXL0, pXL1, pXL3, bias, l,
                                      pXV, pAhV, pAlV, do_next);
        gat_con_kernel<<<gatCB, EB>>>(pXL2, bias, l,
                                      pXC, pAhC, pAlC, do_next);
    }

    zero_pool_kernel<<<GN, 256>>>();
    pool_kernel<<<gatVB, EB>>>(pXV, batch_var, NVN, pVP, pCNT);
    pool_kernel<<<gatCB, EB>>>(pXC, batch_con, NCN, pCP, pCNT + GN);
    finalize_kernel<<<GN, 256>>>(W_lin, b_lin, out);
}

// round 16
// speedup vs baseline: 2.8384x; 1.1935x over previous
#include <cuda_runtime.h>
#include <cuda_fp16.h>
#include <cstdint>
#include <cstddef>

#define NVN 50000
#define NCN 20000
#define HD  256
#define NLAYER 4
#define EVVN 500000
#define EVCN 300000
#define GN  64

#define ASTR 40
#define BK 32
#define NSTAGE 2
// halves: A h stages + B h stages
#define SMEM_HALVES (NSTAGE*128*ASTR + NSTAGE*128*ASTR)
#define SMEM_BYTES  (SMEM_HALVES*2)

// ---------------- scratch ----------------
__device__ __align__(128) float g_XV0[NVN * HD];
__device__ __align__(128) float g_XC0[NCN * HD];
__device__ __align__(128) __half g_XL0[NVN * HD];
__device__ __align__(128) __half g_XL1[NVN * HD];
__device__ __align__(128) __half g_XL2[NVN * HD];
__device__ __align__(128) __half g_XL3[NCN * HD];

__device__ __align__(128) __half g_AhV[NVN * HD];
__device__ __align__(128) __half g_AhC[NCN * HD];
__device__ __align__(128) __half g_WhT[16 * HD * HD];  // [mat][n][k]

__device__ float g_AS0[2 * NVN], g_AD0[2 * NVN];
__device__ float g_AS1[2 * NVN], g_AD1[2 * NVN];
__device__ float g_AS2[2 * NVN], g_AD3[2 * NVN];
__device__ float g_AS3[2 * NCN], g_AD2[2 * NCN];

__device__ __align__(128) float g_WS[16 * HD];
__device__ __align__(128) float g_WD[16 * HD];

__device__ int g_RP0[NVN + 1], g_RP1[NVN + 1], g_RP3[NVN + 1], g_RP2[NCN + 1];
__device__ int g_CU0[NVN], g_CU1[NVN], g_CU3[NVN], g_CU2[NCN];
__device__ int g_CS0[EVVN], g_CS1[EVVN], g_CS3[EVCN], g_CS2[EVCN];

__device__ __align__(128) float g_VP[GN * HD];
__device__ __align__(128) float g_CP[GN * HD];
__device__ int   g_CNT[2 * GN];

// ---------------- helpers ----------------
__device__ __forceinline__ void red4(float* p, float4 v) {
    asm volatile("red.global.add.v4.f32 [%0], {%1,%2,%3,%4};"
                 :: "l"(p), "f"(v.x), "f"(v.y), "f"(v.z), "f"(v.w) : "memory");
}
__device__ __forceinline__ void ldsm4(uint32_t* r, const void* p) {
    uint32_t addr = (uint32_t)__cvta_generic_to_shared(p);
    asm volatile("ldmatrix.sync.aligned.m8n8.x4.shared.b16 {%0,%1,%2,%3}, [%4];"
                 : "=r"(r[0]), "=r"(r[1]), "=r"(r[2]), "=r"(r[3]) : "r"(addr));
}
__device__ __forceinline__ void ldsm2(uint32_t* r, const void* p) {
    uint32_t addr = (uint32_t)__cvta_generic_to_shared(p);
    asm volatile("ldmatrix.sync.aligned.m8n8.x2.shared.b16 {%0,%1}, [%2];"
                 : "=r"(r[0]), "=r"(r[1]) : "r"(addr));
}
__device__ __forceinline__ void mma_f16(float* c, const uint32_t* a, const uint32_t* b) {
    asm volatile(
        "mma.sync.aligned.m16n8k16.row.col.f32.f16.f16.f32 "
        "{%0,%1,%2,%3}, {%4,%5,%6,%7}, {%8,%9}, {%0,%1,%2,%3};"
        : "+f"(c[0]), "+f"(c[1]), "+f"(c[2]), "+f"(c[3])
        : "r"(a[0]), "r"(a[1]), "r"(a[2]), "r"(a[3]), "r"(b[0]), "r"(b[1]));
}
__device__ __forceinline__ void cpa16(void* dst, const void* src, bool valid) {
    uint32_t d = (uint32_t)__cvta_generic_to_shared(dst);
    int sz = valid ? 16 : 0;
    asm volatile("cp.async.ca.shared.global [%0], [%1], 16, %2;"
                 :: "r"(d), "l"(src), "r"(sz));
}
__device__ __forceinline__ float d4(float4 a, float4 b) {
    return a.x * b.x + a.y * b.y + a.z * b.z + a.w * b.w;
}

// ---------------- ws/wd precompute ----------------
__global__ void wsd_kernel(const float* __restrict__ Wsrc, const float* __restrict__ Wdst,
                           const float* __restrict__ as, const float* __restrict__ ad) {
    int b = blockIdx.x;
    int i = threadIdx.x;
    __shared__ float sas[HD], sad[HD];
    sas[i] = as[b * HD + i];
    sad[i] = ad[b * HD + i];
    __syncthreads();
    const float* Ws = Wsrc + (size_t)b * HD * HD + (size_t)i * HD;
    const float* Wd = Wdst + (size_t)b * HD * HD + (size_t)i * HD;
    float s = 0.f, d = 0.f;
    #pragma unroll 8
    for (int j = 0; j < HD; j++) { s += Ws[j] * sas[j]; d += Wd[j] * sad[j]; }
    g_WS[b * HD + i] = s;
    g_WD[b * HD + i] = d;
}

// ---------------- fp32 -> fp16 convert ----------------
__global__ void convert_kernel(const float* __restrict__ X, __half* __restrict__ Xh, int n4) {
    int i = blockIdx.x * blockDim.x + threadIdx.x;
    if (i >= n4) return;
    float4 v = ((const float4*)X)[i];
    ((__half2*)Xh)[i * 2 + 0] = __floats2half2_rn(v.x, v.y);
    ((__half2*)Xh)[i * 2 + 1] = __floats2half2_rn(v.z, v.w);
}

// ---------------- W transpose (fp16) ----------------
__global__ void wsplit_kernel(const float* __restrict__ W) {
    __shared__ float tile[32][33];
    int mat = blockIdx.z;
    int bk = blockIdx.x * 32, bn = blockIdx.y * 32;
    int tx = threadIdx.x, ty = threadIdx.y;
    const float* Wm = W + (size_t)mat * HD * HD;
    #pragma unroll
    for (int r = 0; r < 32; r += 8)
        tile[ty + r][tx] = Wm[(size_t)(bk + ty + r) * HD + bn + tx];
    __syncthreads();
    #pragma unroll
    for (int r = 0; r < 32; r += 8) {
        float x = tile[tx][ty + r];
        size_t o = (size_t)mat * HD * HD + (size_t)(bn + ty + r) * HD + bk + tx;
        g_WhT[o] = __float2half_rn(x);
    }
}

// ---------------- fp16 GEMM: Ah x Wh, 128x128, 2-stage ----------
__global__ __launch_bounds__(256, 2) void gemm_fp16_kernel(
        const __half* __restrict__ AhV, const __half* __restrict__ AhC,
        const __half* __restrict__ WhT,
        __half* __restrict__ C0, __half* __restrict__ C1,
        __half* __restrict__ C2, __half* __restrict__ C3) {
    extern __shared__ __half smh[];
    __half* pAh = smh;
    __half* pBh = pAh + NSTAGE * 128 * ASTR;

    const int mat = blockIdx.y >> 1;
    const int N = (mat == 3) ? NCN : NVN;
    const int row0 = blockIdx.x * 128;
    if (row0 >= N) return;
    const __half* Ah = (mat == 3) ? AhC : AhV;
    __half* C = (mat == 0) ? C0 : (mat == 1) ? C1 : (mat == 2) ? C2 : C3;
    const int col0 = (blockIdx.y & 1) * 128;
    const __half* W_h = WhT + (size_t)mat * HD * HD;

    const int tid = threadIdx.x;
    const int lane = tid & 31;
    const int wid = tid >> 5;
    const int wm = (wid & 3) * 32;
    const int wn = (wid >> 2) * 64;

    const int arow = tid >> 1;
    const int acol = (tid & 1) * 16;

    float acc[2][8][4];
    #pragma unroll
    for (int i = 0; i < 2; i++)
        #pragma unroll
        for (int j = 0; j < 8; j++)
            #pragma unroll
            for (int q = 0; q < 4; q++) acc[i][j][q] = 0.f;

    const int g = lane >> 2, t4 = lane & 3;
    const int lr = lane & 15;
    const int lk = (lane >> 4) * 8;
    const int br = lane & 7;
    const int bko = ((lane >> 3) & 1) * 8;

    auto load_stage = [&](int s, int k0) {
        bool v = (row0 + arow) < N;
        const __half* ah = v ? (Ah + (size_t)(row0 + arow) * HD + k0 + acol) : Ah;
        __half* dh = pAh + s * 128 * ASTR + arow * ASTR + acol;
        cpa16(dh,     ah,     v);
        cpa16(dh + 8, ah + 8, v);
        __half* eh = pBh + s * 128 * ASTR + arow * ASTR + acol;
        const __half* wh = W_h + (size_t)(col0 + arow) * HD + k0 + acol;
        cpa16(eh,     wh,     true);
        cpa16(eh + 8, wh + 8, true);
        asm volatile("cp.async.commit_group;");
    };

    load_stage(0, 0);

    for (int kt = 0; kt < 8; kt++) {
        asm volatile("cp.async.wait_group 0;");
        __syncthreads();
        if (kt + 1 < 8) load_stage((kt + 1) & 1, (kt + 1) * BK);

        const int cur = kt & 1;
        const __half* cAh = pAh + cur * 128 * ASTR;
        const __half* cBh = pBh + cur * 128 * ASTR;

        #pragma unroll
        for (int ks = 0; ks < 2; ks++) {
            const int kb = ks * 16;
            uint32_t ah[2][4];
            #pragma unroll
            for (int i = 0; i < 2; i++)
                ldsm4(ah[i], cAh + (size_t)(wm + i * 16 + lr) * ASTR + kb + lk);
            #pragma unroll
            for (int j = 0; j < 8; j++) {
                uint32_t bh[2];
                ldsm2(bh, cBh + (size_t)(wn + j * 8 + br) * ASTR + kb + bko);
                #pragma unroll
                for (int i = 0; i < 2; i++)
                    mma_f16(acc[i][j], ah[i], bh);
            }
        }
    }

    #pragma unroll
    for (int i = 0; i < 2; i++) {
        int r0 = row0 + wm + i * 16 + g;
        #pragma unroll
        for (int j = 0; j < 8; j++) {
            int c = col0 + wn + j * 8 + t4 * 2;
            if (r0 < N)
                *(__half2*)(C + (size_t)r0 * HD + c) =
                    __floats2half2_rn(acc[i][j][0], acc[i][j][1]);
            if (r0 + 8 < N)
                *(__half2*)(C + (size_t)(r0 + 8) * HD + c) =
                    __floats2half2_rn(acc[i][j][2], acc[i][j][3]);
        }
    }
}

// ---------------- standalone attention dots (layer 0 only) ----------------
__global__ void avec_var_kernel(const float* __restrict__ xv) {
    __shared__ float sv[6][HD];
    int t = threadIdx.x;
    sv[0][t] = g_WS[0 * HD + t];
    sv[1][t] = g_WD[0 * HD + t];
    sv[2][t] = g_WS[1 * HD + t];
    sv[3][t] = g_WD[1 * HD + t];
    sv[4][t] = g_WS[2 * HD + t];
    sv[5][t] = g_WD[3 * HD + t];
    __syncthreads();
    int w = (blockIdx.x * blockDim.x + t) >> 5;
    int lane = t & 31;
    if (w >= NVN) return;
    const float* row = xv + (size_t)w * HD;
    float s[6] = {0, 0, 0, 0, 0, 0};
    #pragma unroll
    for (int j0 = 0; j0 < HD; j0 += 32) {
        float x = row[j0 + lane];
        #pragma unroll
        for (int k = 0; k < 6; k++) s[k] += x * sv[k][j0 + lane];
    }
    #pragma unroll
    for (int k = 0; k < 6; k++)
        #pragma unroll
        for (int o = 16; o > 0; o >>= 1) s[k] += __shfl_xor_sync(0xffffffffu, s[k], o);
    if (lane == 0) {
        g_AS0[w] = s[0]; g_AD0[w] = s[1];
        g_AS1[w] = s[2]; g_AD1[w] = s[3];
        g_AS2[w] = s[4]; g_AD3[w] = s[5];
    }
}

__global__ void avec_con_kernel(const float* __restrict__ xc) {
    __shared__ float sv[2][HD];
    int t = threadIdx.x;
    sv[0][t] = g_WD[2 * HD + t];
    sv[1][t] = g_WS[3 * HD + t];
    __syncthreads();
    int w = (blockIdx.x * blockDim.x + t) >> 5;
    int lane = t & 31;
    if (w >= NCN) return;
    const float* row = xc + (size_t)w * HD;
    float s0 = 0.f, s1 = 0.f;
    #pragma unroll
    for (int j0 = 0; j0 < HD; j0 += 32) {
        float x = row[j0 + lane];
        s0 += x * sv[0][j0 + lane];
        s1 += x * sv[1][j0 + lane];
    }
    #pragma unroll
    for (int o = 16; o > 0; o >>= 1) {
        s0 += __shfl_xor_sync(0xffffffffu, s0, o);
        s1 += __shfl_xor_sync(0xffffffffu, s1, o);
    }
    if (lane == 0) { g_AD2[w] = s0; g_AS3[w] = s1; }
}

// ---------------- CSR build (merged kernels) ----------------
__global__ void zero_all_kernel() {
    int i = blockIdx.x * blockDim.x + threadIdx.x;
    if (i <= NVN) { g_RP0[i] = 0; g_RP1[i] = 0; g_RP3[i] = 0; }
    if (i <= NCN) g_RP2[i] = 0;
}
__global__ void hist_all_kernel(const int* __restrict__ dvv, const int* __restrict__ dvvr,
                                const int* __restrict__ dcv, const int* __restrict__ dvc) {
    int i = blockIdx.x * blockDim.x + threadIdx.x;
    if (i < EVVN) atomicAdd(&g_RP0[dvv[i]], 1);
    else if (i < 2 * EVVN) atomicAdd(&g_RP1[dvvr[i - EVVN]], 1);
    else if (i < 2 * EVVN + EVCN) atomicAdd(&g_RP3[dcv[i - 2 * EVVN]], 1);
    else if (i < 2 * EVVN + 2 * EVCN) atomicAdd(&g_RP2[dvc[i - 2 * EVVN - EVCN]], 1);
}
__global__ void scan_all_kernel() {
    __shared__ int swarp[32];
    __shared__ int stot;
    int which = blockIdx.x;
    int* rp     = (which == 0) ? g_RP0 : (which == 1) ? g_RP1 : (which == 2) ? g_RP3 : g_RP2;
    int* cursor = (which == 0) ? g_CU0 : (which == 1) ? g_CU1 : (which == 2) ? g_CU3 : g_CU2;
    int n = (which == 3) ? NCN : NVN;
    int t = threadIdx.x, w = t >> 5, lane = t & 31;
    int carry = 0;
    for (int base = 0; base < n; base += 1024) {
        int idx = base + t;
        int v = (idx < n) ? rp[idx] : 0;
        int x = v;
        #pragma unroll
        for (int o = 1; o < 32; o <<= 1) {
            int y = __shfl_up_sync(0xffffffffu, x, o);
            if (lane >= o) x += y;
        }
        if (lane == 31) swarp[w] = x;
        __syncthreads();
        if (w == 0) {
            int s = swarp[lane];
            int z = s;
            #pragma unroll
            for (int o = 1; o < 32; o <<= 1) {
                int y = __shfl_up_sync(0xffffffffu, z, o);
                if (lane >= o) z += y;
            }
            swarp[lane] = z - s;
            if (lane == 31) stot = z;
        }
        __syncthreads();
        int excl = carry + swarp[w] + (x - v);
        if (idx < n) { rp[idx] = excl; cursor[idx] = excl; }
        carry += stot;
        __syncthreads();
    }
    if (t == 0) rp[n] = carry;
}
__global__ void scatter_all_kernel(const int* __restrict__ e_vv, const int* __restrict__ e_vvr,
                                   const int* __restrict__ e_cv, const int* __restrict__ e_vc) {
    int i = blockIdx.x * blockDim.x + threadIdx.x;
    if (i < EVVN) {
        int pos = atomicAdd(&g_CU0[e_vv[EVVN + i]], 1);
        g_CS0[pos] = e_vv[i];
    } else if (i < 2 * EVVN) {
        int j = i - EVVN;
        int pos = atomicAdd(&g_CU1[e_vvr[EVVN + j]], 1);
        g_CS1[pos] = e_vvr[j];
    } else if (i < 2 * EVVN + EVCN) {
        int j = i - 2 * EVVN;
        int pos = atomicAdd(&g_CU3[e_cv[EVCN + j]], 1);
        g_CS3[pos] = e_cv[j];
    } else if (i < 2 * EVVN + 2 * EVCN) {
        int j = i - 2 * EVVN - EVCN;
        int pos = atomicAdd(&g_CU2[e_vc[EVCN + j]], 1);
        g_CS2[pos] = e_vc[j];
    }
}

// ---------------- fused GAT (fp16 XL, lane owns 8 contiguous elems) ----------
__device__ __forceinline__ void gat_accum(
        int d, int lane,
        const int* __restrict__ rp, const int* __restrict__ cs,
        const float* __restrict__ AS, const float* __restrict__ AD,
        const __half* __restrict__ XL,
        float4& acc0, float4& acc1) {
    int off = rp[d];
    int deg = rp[d + 1] - off;
    if (deg <= 0) return;
    float adv = AD[d];
    float m = -1e30f;
    for (int j = lane; j < deg; j += 32) {
        int s = cs[off + j];
        float e = AS[s] + adv;
        e = (e >= 0.f) ? e : 0.2f * e;
        m = fmaxf(m, e);
    }
    #pragma unroll
    for (int o = 16; o > 0; o >>= 1) m = fmaxf(m, __shfl_xor_sync(0xffffffffu, m, o));
    float den = 0.f;
    for (int j = lane; j < deg; j += 32) {
        int s = cs[off + j];
        float e = AS[s] + adv;
        e = (e >= 0.f) ? e : 0.2f * e;
        den += __expf(e - m);
    }
    #pragma unroll
    for (int o = 16; o > 0; o >>= 1) den += __shfl_xor_sync(0xffffffffu, den, o);
    float invden = 1.f / (den + 1e-16f);
    #pragma unroll 4
    for (int j = 0; j < deg; j++) {
        int s = cs[off + j];
        float e = AS[s] + adv;
        e = (e >= 0.f) ? e : 0.2f * e;
        float wgt = __expf(e - m) * invden;
        const uint4 raw = ((const uint4*)(XL + (size_t)s * HD))[lane];
        __half2 p0 = *(const __half2*)&raw.x;
        __half2 p1 = *(const __half2*)&raw.y;
        __half2 p2 = *(const __half2*)&raw.z;
        __half2 p3 = *(const __half2*)&raw.w;
        float2 f0 = __half22float2(p0), f1 = __half22float2(p1);
        float2 f2 = __half22float2(p2), f3 = __half22float2(p3);
        acc0.x += wgt * f0.x; acc0.y += wgt * f0.y;
        acc0.z += wgt * f1.x; acc0.w += wgt * f1.y;
        acc1.x += wgt * f2.x; acc1.y += wgt * f2.y;
        acc1.z += wgt * f3.x; acc1.w += wgt * f3.y;
    }
}

__device__ __forceinline__ void h_store(__half* outh, int w, int lane,
                                        float4 acc0, float4 acc1) {
    __half2* oh = (__half2*)(outh + (size_t)w * HD) + lane * 4;
    oh[0] = __floats2half2_rn(acc0.x, acc0.y);
    oh[1] = __floats2half2_rn(acc0.z, acc0.w);
    oh[2] = __floats2half2_rn(acc1.x, acc1.y);
    oh[3] = __floats2half2_rn(acc1.z, acc1.w);
}

// merged var+con GAT: warps [0, NVN) -> var, [NVN, NVN+NCN) -> con
__global__ void gat_all_kernel(const __half* __restrict__ XL0, const __half* __restrict__ XL1,
                               const __half* __restrict__ XL2, const __half* __restrict__ XL3,
                               const float* __restrict__ bias, int l,
                               float* __restrict__ outv, float* __restrict__ outc,
                               __half* __restrict__ outhV, __half* __restrict__ outhC,
                               int do_next) {
    int gw = (blockIdx.x * blockDim.x + threadIdx.x) >> 5;
    int lane = threadIdx.x & 31;
    int rv = (l & 1) * NVN, rc = (l & 1) * NCN;
    int L = l + 1;
    if (gw < NVN) {
        int w = gw;
        float4 acc0, acc1;
        {
            const float4* b0 = (const float4*)(bias + (size_t)(4 * l + 0) * HD) + lane * 2;
            const float4* b1 = (const float4*)(bias + (size_t)(4 * l + 1) * HD) + lane * 2;
            const float4* b3 = (const float4*)(bias + (size_t)(4 * l + 3) * HD) + lane * 2;
            float4 x0 = b0[0], y0 = b1[0], z0 = b3[0];
            float4 x1 = b0[1], y1 = b1[1], z1 = b3[1];
            acc0 = make_float4(x0.x + y0.x + z0.x, x0.y + y0.y + z0.y,
                               x0.z + y0.z + z0.z, x0.w + y0.w + z0.w);
            acc1 = make_float4(x1.x + y1.x + z1.x, x1.y + y1.y + z1.y,
                               x1.z + y1.z + z1.z, x1.w + y1.w + z1.w);
        }
        gat_accum(w, lane, g_RP0, g_CS0, g_AS0 + rv, g_AD0 + rv, XL0, acc0, acc1);
        gat_accum(w, lane, g_RP1, g_CS1, g_AS1 + rv, g_AD1 + rv, XL1, acc0, acc1);
        gat_accum(w, lane, g_RP3, g_CS3, g_AS3 + rc, g_AD3 + rv, XL3, acc0, acc1);
        if (!do_next) {
            float4* ob = (float4*)(outv + (size_t)w * HD) + lane * 2;
            ob[0] = acc0;
            ob[1] = acc1;
            return;
        }
        h_store(outhV, w, lane, acc0, acc1);
        int wv = ((l + 1) & 1) * NVN;
        float s[6];
        const int vidx[6] = {0, 0, 1, 1, 2, 3};
        #pragma unroll
        for (int k = 0; k < 6; k++) {
            const float* vecb = (k == 1 || k == 3 || k == 5) ? g_WD : g_WS;
            const float4* vp = (const float4*)(vecb + (size_t)(4 * L + vidx[k]) * HD) + lane * 2;
            s[k] = d4(acc0, vp[0]) + d4(acc1, vp[1]);
        }
        #pragma unroll
        for (int k = 0; k < 6; k++)
            #pragma unroll
            for (int o = 16; o > 0; o >>= 1) s[k] += __shfl_xor_sync(0xffffffffu, s[k], o);
        if (lane == 0) {
            g_AS0[wv + w] = s[0]; g_AD0[wv + w] = s[1];
            g_AS1[wv + w] = s[2]; g_AD1[wv + w] = s[3];
            g_AS2[wv + w] = s[4]; g_AD3[wv + w] = s[5];
        }
    } else if (gw < NVN + NCN) {
        int w = gw - NVN;
        float4 acc0, acc1;
        const float4* b2 = (const float4*)(bias + (size_t)(4 * l + 2) * HD) + lane * 2;
        acc0 = b2[0];
        acc1 = b2[1];
        gat_accum(w, lane, g_RP2, g_CS2, g_AS2 + rv, g_AD2 + rc, XL2, acc0, acc1);
        if (!do_next) {
            float4* ob = (float4*)(outc + (size_t)w * HD) + lane * 2;
            ob[0] = acc0;
            ob[1] = acc1;
            return;
        }
        h_store(outhC, w, lane, acc0, acc1);
        int wc = ((l + 1) & 1) * NCN;
        const float4* v0 = (const float4*)(g_WD + (size_t)(4 * L + 2) * HD) + lane * 2;
        const float4* v1 = (const float4*)(g_WS + (size_t)(4 * L + 3) * HD) + lane * 2;
        float s0 = d4(acc0, v0[0]) + d4(acc1, v0[1]);
        float s1 = d4(acc0, v1[0]) + d4(acc1, v1[1]);
        #pragma unroll
        for (int o = 16; o > 0; o >>= 1) {
            s0 += __shfl_xor_sync(0xffffffffu, s0, o);
            s1 += __shfl_xor_sync(0xffffffffu, s1, o);
        }
        if (lane == 0) { g_AD2[wc + w] = s0; g_AS3[wc + w] = s1; }
    }
}

// ---------------- pooling + head ----------------
__global__ void zero_pool_kernel() {
    int i = blockIdx.x * 256 + threadIdx.x;
    g_VP[i] = 0.f;
    g_CP[i] = 0.f;
    if (i < 2 * GN) g_CNT[i] = 0;
}

__global__ void pool_kernel(const float* __restrict__ X, const int* __restrict__ batch,
                            int N, float* __restrict__ S, int* __restrict__ cnt) {
    int w = (blockIdx.x * blockDim.x + threadIdx.x) >> 5;
    int lane = threadIdx.x & 31;
    if (w >= N) return;
    int g = batch[w];
    if (lane == 0) atomicAdd(&cnt[g], 1);
    const float4* xr = (const float4*)(X + (size_t)w * HD);
    float* sb = S + (size_t)g * HD;
    #pragma unroll
    for (int j = 0; j < 2; j++) {
        int idx = lane + 32 * j;
        red4(sb + 4 * idx, xr[idx]);
    }
}

__global__ void finalize_kernel(const float* __restrict__ Wlin, const float* __restrict__ blin,
                                float* __restrict__ out) {
    int g = blockIdx.x, t = threadIdx.x;
    float cv = (float)max(g_CNT[g], 1);
    float cc = (float)max(g_CNT[GN + g], 1);
    float a = g_VP[g * HD + t] / cv;
    float c = g_CP[g * HD + t] / cc;
    float p0 = a * Wlin[t * 2 + 0] + c * Wlin[(HD + t) * 2 + 0];
    float p1 = a * Wlin[t * 2 + 1] + c * Wlin[(HD + t) * 2 + 1];
    __shared__ float s0[256], s1[256];
    s0[t] = p0; s1[t] = p1;
    __syncthreads();
    for (int o = 128; o > 0; o >>= 1) {
        if (t < o) { s0[t] += s0[t + o]; s1[t] += s1[t + o]; }
        __syncthreads();
    }
    if (t == 0) {
        float z0 = s0[0] + blin[0], z1 = s1[0] + blin[1];
        float m = fmaxf(z0, z1);
        float e0 = expf(z0 - m), e1 = expf(z1 - m);
        float inv = 1.f / (e0 + e1);
        out[2 * g + 0] = e0 * inv;
        out[2 * g + 1] = e1 * inv;
    }
}

// ---------------- host ----------------
extern "C" void kernel_launch(void* const* d_in, const int* in_sizes, int n_in,
                              void* d_out, int out_size) {
    const float* x_var   = (const float*)d_in[0];
    const float* x_con   = (const float*)d_in[1];
    const float* W_src   = (const float*)d_in[2];
    const float* W_dst   = (const float*)d_in[3];
    const float* att_src = (const float*)d_in[4];
    const float* att_dst = (const float*)d_in[5];
    const float* bias    = (const float*)d_in[6];
    const float* W_lin   = (const float*)d_in[7];
    const float* b_lin   = (const float*)d_in[8];
    const int* e_vv      = (const int*)d_in[9];
    const int* e_vv_rev  = (const int*)d_in[10];
    const int* e_vc      = (const int*)d_in[11];
    const int* e_cv      = (const int*)d_in[12];
    const int* batch_var = (const int*)d_in[13];
    const int* batch_con = (const int*)d_in[14];
    float* out = (float*)d_out;

    float *pXV, *pXC, *pVP, *pCP;
    __half *pXL0, *pXL1, *pXL2, *pXL3;
    __half *pAhV, *pAhC, *pWhT;
    int* pCNT;
    cudaGetSymbolAddress((void**)&pXV, g_XV0);
    cudaGetSymbolAddress((void**)&pXC, g_XC0);
    cudaGetSymbolAddress((void**)&pXL0, g_XL0);
    cudaGetSymbolAddress((void**)&pXL1, g_XL1);
    cudaGetSymbolAddress((void**)&pXL2, g_XL2);
    cudaGetSymbolAddress((void**)&pXL3, g_XL3);
    cudaGetSymbolAddress((void**)&pAhV, g_AhV);
    cudaGetSymbolAddress((void**)&pAhC, g_AhC);
    cudaGetSymbolAddress((void**)&pWhT, g_WhT);
    cudaGetSymbolAddress((void**)&pVP, g_VP);
    cudaGetSymbolAddress((void**)&pCP, g_CP);
    cudaGetSymbolAddress((void**)&pCNT, g_CNT);

    cudaFuncSetAttribute(gemm_fp16_kernel,
                         cudaFuncAttributeMaxDynamicSharedMemorySize, SMEM_BYTES);

    const int EB = 256;
    dim3 gemmGrid((NVN + 127) / 128, 8);
    const int ETOT = 2 * EVVN + 2 * EVCN;

    convert_kernel<<<(NVN * HD / 4 + EB - 1) / EB, EB>>>(x_var, pAhV, NVN * HD / 4);
    convert_kernel<<<(NCN * HD / 4 + EB - 1) / EB, EB>>>(x_con, pAhC, NCN * HD / 4);
    wsplit_kernel<<<dim3(8, 8, 16), dim3(32, 8)>>>(W_src);

    gemm_fp16_kernel<<<gemmGrid, 256, SMEM_BYTES>>>(
        pAhV, pAhC, pWhT, pXL0, pXL1, pXL2, pXL3);

    wsd_kernel<<<16, 256>>>(W_src, W_dst, att_src, att_dst);
    avec_var_kernel<<<(NVN * 32 + EB - 1) / EB, EB>>>(x_var);
    avec_con_kernel<<<(NCN * 32 + EB - 1) / EB, EB>>>(x_con);

    zero_all_kernel<<<(NVN + 1 + EB - 1) / EB, EB>>>();
    hist_all_kernel<<<(ETOT + EB - 1) / EB, EB>>>(e_vv + EVVN, e_vv_rev + EVVN,
                                                  e_cv + EVCN, e_vc + EVCN);
    scan_all_kernel<<<4, 1024>>>();
    scatter_all_kernel<<<(ETOT + EB - 1) / EB, EB>>>(e_vv, e_vv_rev, e_cv, e_vc);

    int gatAB = ((NVN + NCN) * 32 + EB - 1) / EB;
    int gatVB = (NVN * 32 + EB - 1) / EB;
    int gatCB = (NCN * 32 + EB - 1) / EB;

    for (int l = 0; l < NLAYER; l++) {
        int do_next = (l + 1 < NLAYER) ? 1 : 0;

        if (l > 0) {
            gemm_fp16_kernel<<<gemmGrid, 256, SMEM_BYTES>>>(
                pAhV, pAhC, pWhT + (size_t)(4 * l) * HD * HD,
                pXL0, pXL1, pXL2, pXL3);
        }

        gat_all_kernel<<<gatAB, EB>>>(pXL0, pXL1, pXL2, pXL3, bias, l,
                                      pXV, pXC, pAhV, pAhC, do_next);
    }

    zero_pool_kernel<<<GN, 256>>>();
    pool_kernel<<<gatVB, EB>>>(pXV, batch_var, NVN, pVP, pCNT);
    pool_kernel<<<gatCB, EB>>>(pXC, batch_con, NCN, pCP, pCNT + GN);
    finalize_kernel<<<GN, 256>>>(W_lin, b_lin, out);
}

// round 17
// speedup vs baseline: 2.9486x; 1.0388x over previous
#include <cuda_runtime.h>
#include <cuda_fp16.h>
#include <cstdint>
#include <cstddef>

#define NVN 50000
#define NCN 20000
#define HD  256
#define NLAYER 4
#define EVVN 500000
#define EVCN 300000
#define GN  64

#define ASTR 40
#define BK 32
#define NSTAGE 3
#define SMEM_HALVES (NSTAGE*128*ASTR + NSTAGE*128*ASTR)
#define SMEM_BYTES  (SMEM_HALVES*2)

// ---------------- scratch ----------------
__device__ __align__(128) __half g_XL0[NVN * HD];
__device__ __align__(128) __half g_XL1[NVN * HD];
__device__ __align__(128) __half g_XL2[NVN * HD];
__device__ __align__(128) __half g_XL3[NCN * HD];

__device__ __align__(128) __half g_AhV[NVN * HD];
__device__ __align__(128) __half g_AhC[NCN * HD];
__device__ __align__(128) __half g_WhT[16 * HD * HD];  // [mat][n][k]

__device__ float g_AS0[2 * NVN], g_AD0[2 * NVN];
__device__ float g_AS1[2 * NVN], g_AD1[2 * NVN];
__device__ float g_AS2[2 * NVN], g_AD3[2 * NVN];
__device__ float g_AS3[2 * NCN], g_AD2[2 * NCN];

__device__ __align__(128) float g_WS[16 * HD];
__device__ __align__(128) float g_WD[16 * HD];

__device__ int g_RP0[NVN + 1], g_RP1[NVN + 1], g_RP3[NVN + 1], g_RP2[NCN + 1];
__device__ int g_CU0[NVN], g_CU1[NVN], g_CU3[NVN], g_CU2[NCN];
__device__ int g_CS0[EVVN], g_CS1[EVVN], g_CS3[EVCN], g_CS2[EVCN];

__device__ __align__(128) float g_VP[GN * HD];
__device__ __align__(128) float g_CP[GN * HD];
__device__ int   g_CNT[2 * GN];

// ---------------- helpers ----------------
__device__ __forceinline__ void red4(float* p, float4 v) {
    asm volatile("red.global.add.v4.f32 [%0], {%1,%2,%3,%4};"
                 :: "l"(p), "f"(v.x), "f"(v.y), "f"(v.z), "f"(v.w) : "memory");
}
__device__ __forceinline__ void ldsm4(uint32_t* r, const void* p) {
    uint32_t addr = (uint32_t)__cvta_generic_to_shared(p);
    asm volatile("ldmatrix.sync.aligned.m8n8.x4.shared.b16 {%0,%1,%2,%3}, [%4];"
                 : "=r"(r[0]), "=r"(r[1]), "=r"(r[2]), "=r"(r[3]) : "r"(addr));
}
__device__ __forceinline__ void ldsm2(uint32_t* r, const void* p) {
    uint32_t addr = (uint32_t)__cvta_generic_to_shared(p);
    asm volatile("ldmatrix.sync.aligned.m8n8.x2.shared.b16 {%0,%1}, [%2];"
                 : "=r"(r[0]), "=r"(r[1]) : "r"(addr));
}
__device__ __forceinline__ void mma_f16(float* c, const uint32_t* a, const uint32_t* b) {
    asm volatile(
        "mma.sync.aligned.m16n8k16.row.col.f32.f16.f16.f32 "
        "{%0,%1,%2,%3}, {%4,%5,%6,%7}, {%8,%9}, {%0,%1,%2,%3};"
        : "+f"(c[0]), "+f"(c[1]), "+f"(c[2]), "+f"(c[3])
        : "r"(a[0]), "r"(a[1]), "r"(a[2]), "r"(a[3]), "r"(b[0]), "r"(b[1]));
}
__device__ __forceinline__ void cpa16(void* dst, const void* src, bool valid) {
    uint32_t d = (uint32_t)__cvta_generic_to_shared(dst);
    int sz = valid ? 16 : 0;
    asm volatile("cp.async.ca.shared.global [%0], [%1], 16, %2;"
                 :: "r"(d), "l"(src), "r"(sz));
}
__device__ __forceinline__ float d4(float4 a, float4 b) {
    return a.x * b.x + a.y * b.y + a.z * b.z + a.w * b.w;
}

// ---------------- ws/wd precompute (parallelized: grid (16,4) x 64thr) --------
__global__ void wsd_kernel(const float* __restrict__ Wsrc, const float* __restrict__ Wdst,
                           const float* __restrict__ as, const float* __restrict__ ad) {
    int b = blockIdx.x;                       // 0..15 mat
    int i = blockIdx.y * 64 + threadIdx.x;    // row
    __shared__ float sas[HD], sad[HD];
    for (int j = threadIdx.x; j < HD; j += 64) {
        sas[j] = as[b * HD + j];
        sad[j] = ad[b * HD + j];
    }
    __syncthreads();
    const float* Ws = Wsrc + (size_t)b * HD * HD + (size_t)i * HD;
    const float* Wd = Wdst + (size_t)b * HD * HD + (size_t)i * HD;
    float s = 0.f, d = 0.f;
    #pragma unroll 8
    for (int j = 0; j < HD; j++) { s += Ws[j] * sas[j]; d += Wd[j] * sad[j]; }
    g_WS[b * HD + i] = s;
    g_WD[b * HD + i] = d;
}

// ---------------- fp32 -> fp16 convert ----------------
__global__ void convert_kernel(const float* __restrict__ X, __half* __restrict__ Xh, int n4) {
    int i = blockIdx.x * blockDim.x + threadIdx.x;
    if (i >= n4) return;
    float4 v = ((const float4*)X)[i];
    ((__half2*)Xh)[i * 2 + 0] = __floats2half2_rn(v.x, v.y);
    ((__half2*)Xh)[i * 2 + 1] = __floats2half2_rn(v.z, v.w);
}

// ---------------- W transpose (fp16) ----------------
__global__ void wsplit_kernel(const float* __restrict__ W) {
    __shared__ float tile[32][33];
    int mat = blockIdx.z;
    int bk = blockIdx.x * 32, bn = blockIdx.y * 32;
    int tx = threadIdx.x, ty = threadIdx.y;
    const float* Wm = W + (size_t)mat * HD * HD;
    #pragma unroll
    for (int r = 0; r < 32; r += 8)
        tile[ty + r][tx] = Wm[(size_t)(bk + ty + r) * HD + bn + tx];
    __syncthreads();
    #pragma unroll
    for (int r = 0; r < 32; r += 8) {
        float x = tile[tx][ty + r];
        size_t o = (size_t)mat * HD * HD + (size_t)(bn + ty + r) * HD + bk + tx;
        g_WhT[o] = __float2half_rn(x);
    }
}

// ---------------- fp16 GEMM: Ah x Wh, 128x128, 3-stage ----------
__global__ __launch_bounds__(256, 2) void gemm_fp16_kernel(
        const __half* __restrict__ AhV, const __half* __restrict__ AhC,
        const __half* __restrict__ WhT,
        __half* __restrict__ C0, __half* __restrict__ C1,
        __half* __restrict__ C2, __half* __restrict__ C3) {
    extern __shared__ __half smh[];
    __half* pAh = smh;
    __half* pBh = pAh + NSTAGE * 128 * ASTR;

    const int mat = blockIdx.y >> 1;
    const int N = (mat == 3) ? NCN : NVN;
    const int row0 = blockIdx.x * 128;
    if (row0 >= N) return;
    const __half* Ah = (mat == 3) ? AhC : AhV;
    __half* C = (mat == 0) ? C0 : (mat == 1) ? C1 : (mat == 2) ? C2 : C3;
    const int col0 = (blockIdx.y & 1) * 128;
    const __half* W_h = WhT + (size_t)mat * HD * HD;

    const int tid = threadIdx.x;
    const int lane = tid & 31;
    const int wid = tid >> 5;
    const int wm = (wid & 3) * 32;
    const int wn = (wid >> 2) * 64;

    const int arow = tid >> 1;
    const int acol = (tid & 1) * 16;

    float acc[2][8][4];
    #pragma unroll
    for (int i = 0; i < 2; i++)
        #pragma unroll
        for (int j = 0; j < 8; j++)
            #pragma unroll
            for (int q = 0; q < 4; q++) acc[i][j][q] = 0.f;

    const int g = lane >> 2, t4 = lane & 3;
    const int lr = lane & 15;
    const int lk = (lane >> 4) * 8;
    const int br = lane & 7;
    const int bko = ((lane >> 3) & 1) * 8;

    auto load_stage = [&](int s, int k0) {
        bool v = (row0 + arow) < N;
        const __half* ah = v ? (Ah + (size_t)(row0 + arow) * HD + k0 + acol) : Ah;
        __half* dh = pAh + s * 128 * ASTR + arow * ASTR + acol;
        cpa16(dh,     ah,     v);
        cpa16(dh + 8, ah + 8, v);
        __half* eh = pBh + s * 128 * ASTR + arow * ASTR + acol;
        const __half* wh = W_h + (size_t)(col0 + arow) * HD + k0 + acol;
        cpa16(eh,     wh,     true);
        cpa16(eh + 8, wh + 8, true);
        asm volatile("cp.async.commit_group;");
    };

    load_stage(0, 0);
    load_stage(1, BK);

    for (int kt = 0; kt < 8; kt++) {
        if (kt + 1 < 8) {
            asm volatile("cp.async.wait_group 1;");
        } else {
            asm volatile("cp.async.wait_group 0;");
        }
        __syncthreads();
        if (kt + 2 < 8) load_stage((kt + 2) % NSTAGE, (kt + 2) * BK);

        const int cur = kt % NSTAGE;
        const __half* cAh = pAh + cur * 128 * ASTR;
        const __half* cBh = pBh + cur * 128 * ASTR;

        #pragma unroll
        for (int ks = 0; ks < 2; ks++) {
            const int kb = ks * 16;
            uint32_t ah[2][4];
            #pragma unroll
            for (int i = 0; i < 2; i++)
                ldsm4(ah[i], cAh + (size_t)(wm + i * 16 + lr) * ASTR + kb + lk);
            #pragma unroll
            for (int j = 0; j < 8; j++) {
                uint32_t bh[2];
                ldsm2(bh, cBh + (size_t)(wn + j * 8 + br) * ASTR + kb + bko);
                #pragma unroll
                for (int i = 0; i < 2; i++)
                    mma_f16(acc[i][j], ah[i], bh);
            }
        }
    }

    #pragma unroll
    for (int i = 0; i < 2; i++) {
        int r0 = row0 + wm + i * 16 + g;
        #pragma unroll
        for (int j = 0; j < 8; j++) {
            int c = col0 + wn + j * 8 + t4 * 2;
            if (r0 < N)
                *(__half2*)(C + (size_t)r0 * HD + c) =
                    __floats2half2_rn(acc[i][j][0], acc[i][j][1]);
            if (r0 + 8 < N)
                *(__half2*)(C + (size_t)(r0 + 8) * HD + c) =
                    __floats2half2_rn(acc[i][j][2], acc[i][j][3]);
        }
    }
}

// ---------------- standalone attention dots (layer 0 only) ----------------
__global__ void avec_var_kernel(const float* __restrict__ xv) {
    __shared__ float sv[6][HD];
    int t = threadIdx.x;
    sv[0][t] = g_WS[0 * HD + t];
    sv[1][t] = g_WD[0 * HD + t];
    sv[2][t] = g_WS[1 * HD + t];
    sv[3][t] = g_WD[1 * HD + t];
    sv[4][t] = g_WS[2 * HD + t];
    sv[5][t] = g_WD[3 * HD + t];
    __syncthreads();
    int w = (blockIdx.x * blockDim.x + t) >> 5;
    int lane = t & 31;
    if (w >= NVN) return;
    const float* row = xv + (size_t)w * HD;
    float s[6] = {0, 0, 0, 0, 0, 0};
    #pragma unroll
    for (int j0 = 0; j0 < HD; j0 += 32) {
        float x = row[j0 + lane];
        #pragma unroll
        for (int k = 0; k < 6; k++) s[k] += x * sv[k][j0 + lane];
    }
    #pragma unroll
    for (int k = 0; k < 6; k++)
        #pragma unroll
        for (int o = 16; o > 0; o >>= 1) s[k] += __shfl_xor_sync(0xffffffffu, s[k], o);
    if (lane == 0) {
        g_AS0[w] = s[0]; g_AD0[w] = s[1];
        g_AS1[w] = s[2]; g_AD1[w] = s[3];
        g_AS2[w] = s[4]; g_AD3[w] = s[5];
    }
}

__global__ void avec_con_kernel(const float* __restrict__ xc) {
    __shared__ float sv[2][HD];
    int t = threadIdx.x;
    sv[0][t] = g_WD[2 * HD + t];
    sv[1][t] = g_WS[3 * HD + t];
    __syncthreads();
    int w = (blockIdx.x * blockDim.x + t) >> 5;
    int lane = t & 31;
    if (w >= NCN) return;
    const float* row = xc + (size_t)w * HD;
    float s0 = 0.f, s1 = 0.f;
    #pragma unroll
    for (int j0 = 0; j0 < HD; j0 += 32) {
        float x = row[j0 + lane];
        s0 += x * sv[0][j0 + lane];
        s1 += x * sv[1][j0 + lane];
    }
    #pragma unroll
    for (int o = 16; o > 0; o >>= 1) {
        s0 += __shfl_xor_sync(0xffffffffu, s0, o);
        s1 += __shfl_xor_sync(0xffffffffu, s1, o);
    }
    if (lane == 0) { g_AD2[w] = s0; g_AS3[w] = s1; }
}

// ---------------- CSR build (merged kernels) ----------------
__global__ void zero_all_kernel() {
    int i = blockIdx.x * blockDim.x + threadIdx.x;
    if (i <= NVN) { g_RP0[i] = 0; g_RP1[i] = 0; g_RP3[i] = 0; }
    if (i <= NCN) g_RP2[i] = 0;
    if (i < GN * HD) { g_VP[i] = 0.f; g_CP[i] = 0.f; }
    if (i < 2 * GN) g_CNT[i] = 0;
}
__global__ void hist_all_kernel(const int* __restrict__ dvv, const int* __restrict__ dvvr,
                                const int* __restrict__ dcv, const int* __restrict__ dvc) {
    int i = blockIdx.x * blockDim.x + threadIdx.x;
    if (i < EVVN) atomicAdd(&g_RP0[dvv[i]], 1);
    else if (i < 2 * EVVN) atomicAdd(&g_RP1[dvvr[i - EVVN]], 1);
    else if (i < 2 * EVVN + EVCN) atomicAdd(&g_RP3[dcv[i - 2 * EVVN]], 1);
    else if (i < 2 * EVVN + 2 * EVCN) atomicAdd(&g_RP2[dvc[i - 2 * EVVN - EVCN]], 1);
}
__global__ void scan_all_kernel() {
    __shared__ int swarp[32];
    __shared__ int stot;
    int which = blockIdx.x;
    int* rp     = (which == 0) ? g_RP0 : (which == 1) ? g_RP1 : (which == 2) ? g_RP3 : g_RP2;
    int* cursor = (which == 0) ? g_CU0 : (which == 1) ? g_CU1 : (which == 2) ? g_CU3 : g_CU2;
    int n = (which == 3) ? NCN : NVN;
    int t = threadIdx.x, w = t >> 5, lane = t & 31;
    int carry = 0;
    for (int base = 0; base < n; base += 1024) {
        int idx = base + t;
        int v = (idx < n) ? rp[idx] : 0;
        int x = v;
        #pragma unroll
        for (int o = 1; o < 32; o <<= 1) {
            int y = __shfl_up_sync(0xffffffffu, x, o);
            if (lane >= o) x += y;
        }
        if (lane == 31) swarp[w] = x;
        __syncthreads();
        if (w == 0) {
            int s = swarp[lane];
            int z = s;
            #pragma unroll
            for (int o = 1; o < 32; o <<= 1) {
                int y = __shfl_up_sync(0xffffffffu, z, o);
                if (lane >= o) z += y;
            }
            swarp[lane] = z - s;
            if (lane == 31) stot = z;
        }
        __syncthreads();
        int excl = carry + swarp[w] + (x - v);
        if (idx < n) { rp[idx] = excl; cursor[idx] = excl; }
        carry += stot;
        __syncthreads();
    }
    if (t == 0) rp[n] = carry;
}
__global__ void scatter_all_kernel(const int* __restrict__ e_vv, const int* __restrict__ e_vvr,
                                   const int* __restrict__ e_cv, const int* __restrict__ e_vc) {
    int i = blockIdx.x * blockDim.x + threadIdx.x;
    if (i < EVVN) {
        int pos = atomicAdd(&g_CU0[e_vv[EVVN + i]], 1);
        g_CS0[pos] = e_vv[i];
    } else if (i < 2 * EVVN) {
        int j = i - EVVN;
        int pos = atomicAdd(&g_CU1[e_vvr[EVVN + j]], 1);
        g_CS1[pos] = e_vvr[j];
    } else if (i < 2 * EVVN + EVCN) {
        int j = i - 2 * EVVN;
        int pos = atomicAdd(&g_CU3[e_cv[EVCN + j]], 1);
        g_CS3[pos] = e_cv[j];
    } else if (i < 2 * EVVN + 2 * EVCN) {
        int j = i - 2 * EVVN - EVCN;
        int pos = atomicAdd(&g_CU2[e_vc[EVCN + j]], 1);
        g_CS2[pos] = e_vc[j];
    }
}

// ---------------- fused GAT (fp16 XL, lane owns 8 contiguous elems) ----------
__device__ __forceinline__ void gat_accum(
        int d, int lane,
        const int* __restrict__ rp, const int* __restrict__ cs,
        const float* __restrict__ AS, const float* __restrict__ AD,
        const __half* __restrict__ XL,
        float4& acc0, float4& acc1) {
    int off = rp[d];
    int deg = rp[d + 1] - off;
    if (deg <= 0) return;
    float adv = AD[d];
    float m = -1e30f;
    for (int j = lane; j < deg; j += 32) {
        int s = cs[off + j];
        float e = AS[s] + adv;
        e = (e >= 0.f) ? e : 0.2f * e;
        m = fmaxf(m, e);
    }
    #pragma unroll
    for (int o = 16; o > 0; o >>= 1) m = fmaxf(m, __shfl_xor_sync(0xffffffffu, m, o));
    float den = 0.f;
    for (int j = lane; j < deg; j += 32) {
        int s = cs[off + j];
        float e = AS[s] + adv;
        e = (e >= 0.f) ? e : 0.2f * e;
        den += __expf(e - m);
    }
    #pragma unroll
    for (int o = 16; o > 0; o >>= 1) den += __shfl_xor_sync(0xffffffffu, den, o);
    float invden = 1.f / (den + 1e-16f);
    #pragma unroll 4
    for (int j = 0; j < deg; j++) {
        int s = cs[off + j];
        float e = AS[s] + adv;
        e = (e >= 0.f) ? e : 0.2f * e;
        float wgt = __expf(e - m) * invden;
        const uint4 raw = ((const uint4*)(XL + (size_t)s * HD))[lane];
        __half2 p0 = *(const __half2*)&raw.x;
        __half2 p1 = *(const __half2*)&raw.y;
        __half2 p2 = *(const __half2*)&raw.z;
        __half2 p3 = *(const __half2*)&raw.w;
        float2 f0 = __half22float2(p0), f1 = __half22float2(p1);
        float2 f2 = __half22float2(p2), f3 = __half22float2(p3);
        acc0.x += wgt * f0.x; acc0.y += wgt * f0.y;
        acc0.z += wgt * f1.x; acc0.w += wgt * f1.y;
        acc1.x += wgt * f2.x; acc1.y += wgt * f2.y;
        acc1.z += wgt * f3.x; acc1.w += wgt * f3.y;
    }
}

__device__ __forceinline__ void h_store(__half* outh, int w, int lane,
                                        float4 acc0, float4 acc1) {
    __half2* oh = (__half2*)(outh + (size_t)w * HD) + lane * 4;
    oh[0] = __floats2half2_rn(acc0.x, acc0.y);
    oh[1] = __floats2half2_rn(acc0.z, acc0.w);
    oh[2] = __floats2half2_rn(acc1.x, acc1.y);
    oh[3] = __floats2half2_rn(acc1.z, acc1.w);
}

// merged var+con GAT; last layer fuses mean-pool accumulation
__global__ void gat_all_kernel(const __half* __restrict__ XL0, const __half* __restrict__ XL1,
                               const __half* __restrict__ XL2, const __half* __restrict__ XL3,
                               const float* __restrict__ bias, int l,
                               __half* __restrict__ outhV, __half* __restrict__ outhC,
                               const int* __restrict__ batch_var,
                               const int* __restrict__ batch_con,
                               int do_next) {
    int gw = (blockIdx.x * blockDim.x + threadIdx.x) >> 5;
    int lane = threadIdx.x & 31;
    int rv = (l & 1) * NVN, rc = (l & 1) * NCN;
    int L = l + 1;
    if (gw < NVN) {
        int w = gw;
        float4 acc0, acc1;
        {
            const float4* b0 = (const float4*)(bias + (size_t)(4 * l + 0) * HD) + lane * 2;
            const float4* b1 = (const float4*)(bias + (size_t)(4 * l + 1) * HD) + lane * 2;
            const float4* b3 = (const float4*)(bias + (size_t)(4 * l + 3) * HD) + lane * 2;
            float4 x0 = b0[0], y0 = b1[0], z0 = b3[0];
            float4 x1 = b0[1], y1 = b1[1], z1 = b3[1];
            acc0 = make_float4(x0.x + y0.x + z0.x, x0.y + y0.y + z0.y,
                               x0.z + y0.z + z0.z, x0.w + y0.w + z0.w);
            acc1 = make_float4(x1.x + y1.x + z1.x, x1.y + y1.y + z1.y,
                               x1.z + y1.z + z1.z, x1.w + y1.w + z1.w);
        }
        gat_accum(w, lane, g_RP0, g_CS0, g_AS0 + rv, g_AD0 + rv, XL0, acc0, acc1);
        gat_accum(w, lane, g_RP1, g_CS1, g_AS1 + rv, g_AD1 + rv, XL1, acc0, acc1);
        gat_accum(w, lane, g_RP3, g_CS3, g_AS3 + rc, g_AD3 + rv, XL3, acc0, acc1);
        if (!do_next) {
            int gb = batch_var[w];
            if (lane == 0) atomicAdd(&g_CNT[gb], 1);
            float* sb = g_VP + (size_t)gb * HD + lane * 8;
            red4(sb, acc0);
            red4(sb + 4, acc1);
            return;
        }
        h_store(outhV, w, lane, acc0, acc1);
        int wv = ((l + 1) & 1) * NVN;
        float s[6];
        const int vidx[6] = {0, 0, 1, 1, 2, 3};
        #pragma unroll
        for (int k = 0; k < 6; k++) {
            const float* vecb = (k == 1 || k == 3 || k == 5) ? g_WD : g_WS;
            const float4* vp = (const float4*)(vecb + (size_t)(4 * L + vidx[k]) * HD) + lane * 2;
            s[k] = d4(acc0, vp[0]) + d4(acc1, vp[1]);
        }
        #pragma unroll
        for (int k = 0; k < 6; k++)
            #pragma unroll
            for (int o = 16; o > 0; o >>= 1) s[k] += __shfl_xor_sync(0xffffffffu, s[k], o);
        if (lane == 0) {
            g_AS0[wv + w] = s[0]; g_AD0[wv + w] = s[1];
            g_AS1[wv + w] = s[2]; g_AD1[wv + w] = s[3];
            g_AS2[wv + w] = s[4]; g_AD3[wv + w] = s[5];
        }
    } else if (gw < NVN + NCN) {
        int w = gw - NVN;
        float4 acc0, acc1;
        const float4* b2 = (const float4*)(bias + (size_t)(4 * l + 2) * HD) + lane * 2;
        acc0 = b2[0];
        acc1 = b2[1];
        gat_accum(w, lane, g_RP2, g_CS2, g_AS2 + rv, g_AD2 + rc, XL2, acc0, acc1);
        if (!do_next) {
            int gb = batch_con[w];
            if (lane == 0) atomicAdd(&g_CNT[GN + gb], 1);
            float* sb = g_CP + (size_t)gb * HD + lane * 8;
            red4(sb, acc0);
            red4(sb + 4, acc1);
            return;
        }
        h_store(outhC, w, lane, acc0, acc1);
        int wc = ((l + 1) & 1) * NCN;
        const float4* v0 = (const float4*)(g_WD + (size_t)(4 * L + 2) * HD) + lane * 2;
        const float4* v1 = (const float4*)(g_WS + (size_t)(4 * L + 3) * HD) + lane * 2;
        float s0 = d4(acc0, v0[0]) + d4(acc1, v0[1]);
        float s1 = d4(acc0, v1[0]) + d4(acc1, v1[1]);
        #pragma unroll
        for (int o = 16; o > 0; o >>= 1) {
            s0 += __shfl_xor_sync(0xffffffffu, s0, o);
            s1 += __shfl_xor_sync(0xffffffffu, s1, o);
        }
        if (lane == 0) { g_AD2[wc + w] = s0; g_AS3[wc + w] = s1; }
    }
}

// ---------------- head ----------------
__global__ void finalize_kernel(const float* __restrict__ Wlin, const float* __restrict__ blin,
                                float* __restrict__ out) {
    int g = blockIdx.x, t = threadIdx.x;
    float cv = (float)max(g_CNT[g], 1);
    float cc = (float)max(g_CNT[GN + g], 1);
    float a = g_VP[g * HD + t] / cv;
    float c = g_CP[g * HD + t] / cc;
    float p0 = a * Wlin[t * 2 + 0] + c * Wlin[(HD + t) * 2 + 0];
    float p1 = a * Wlin[t * 2 + 1] + c * Wlin[(HD + t) * 2 + 1];
    __shared__ float s0[256], s1[256];
    s0[t] = p0; s1[t] = p1;
    __syncthreads();
    for (int o = 128; o > 0; o >>= 1) {
        if (t < o) { s0[t] += s0[t + o]; s1[t] += s1[t + o]; }
        __syncthreads();
    }
    if (t == 0) {
        float z0 = s0[0] + blin[0], z1 = s1[0] + blin[1];
        float m = fmaxf(z0, z1);
        float e0 = expf(z0 - m), e1 = expf(z1 - m);
        float inv = 1.f / (e0 + e1);
        out[2 * g + 0] = e0 * inv;
        out[2 * g + 1] = e1 * inv;
    }
}

// ---------------- host ----------------
extern "C" void kernel_launch(void* const* d_in, const int* in_sizes, int n_in,
                              void* d_out, int out_size) {
    const float* x_var   = (const float*)d_in[0];
    const float* x_con   = (const float*)d_in[1];
    const float* W_src   = (const float*)d_in[2];
    const float* W_dst   = (const float*)d_in[3];
    const float* att_src = (const float*)d_in[4];
    const float* att_dst = (const float*)d_in[5];
    const float* bias    = (const float*)d_in[6];
    const float* W_lin   = (const float*)d_in[7];
    const float* b_lin   = (const float*)d_in[8];
    const int* e_vv      = (const int*)d_in[9];
    const int* e_vv_rev  = (const int*)d_in[10];
    const int* e_vc      = (const int*)d_in[11];
    const int* e_cv      = (const int*)d_in[12];
    const int* batch_var = (const int*)d_in[13];
    const int* batch_con = (const int*)d_in[14];
    float* out = (float*)d_out;

    __half *pXL0, *pXL1, *pXL2, *pXL3;
    __half *pAhV, *pAhC, *pWhT;
    cudaGetSymbolAddress((void**)&pXL0, g_XL0);
    cudaGetSymbolAddress((void**)&pXL1, g_XL1);
    cudaGetSymbolAddress((void**)&pXL2, g_XL2);
    cudaGetSymbolAddress((void**)&pXL3, g_XL3);
    cudaGetSymbolAddress((void**)&pAhV, g_AhV);
    cudaGetSymbolAddress((void**)&pAhC, g_AhC);
    cudaGetSymbolAddress((void**)&pWhT, g_WhT);

    cudaFuncSetAttribute(gemm_fp16_kernel,
                         cudaFuncAttributeMaxDynamicSharedMemorySize, SMEM_BYTES);

    const int EB = 256;
    dim3 gemmGrid((NVN + 127) / 128, 8);
    const int ETOT = 2 * EVVN + 2 * EVCN;

    convert_kernel<<<(NVN * HD / 4 + EB - 1) / EB, EB>>>(x_var, pAhV, NVN * HD / 4);
    convert_kernel<<<(NCN * HD / 4 + EB - 1) / EB, EB>>>(x_con, pAhC, NCN * HD / 4);
    wsplit_kernel<<<dim3(8, 8, 16), dim3(32, 8)>>>(W_src);

    gemm_fp16_kernel<<<gemmGrid, 256, SMEM_BYTES>>>(
        pAhV, pAhC, pWhT, pXL0, pXL1, pXL2, pXL3);

    wsd_kernel<<<dim3(16, 4), 64>>>(W_src, W_dst, att_src, att_dst);
    avec_var_kernel<<<(NVN * 32 + EB - 1) / EB, EB>>>(x_var);
    avec_con_kernel<<<(NCN * 32 + EB - 1) / EB, EB>>>(x_con);

    zero_all_kernel<<<(NVN + 1 + EB - 1) / EB, EB>>>();
    hist_all_kernel<<<(ETOT + EB - 1) / EB, EB>>>(e_vv + EVVN, e_vv_rev + EVVN,
                                                  e_cv + EVCN, e_vc + EVCN);
    scan_all_kernel<<<4, 1024>>>();
    scatter_all_kernel<<<(ETOT + EB - 1) / EB, EB>>>(e_vv, e_vv_rev, e_cv, e_vc);

    int gatAB = ((NVN + NCN) * 32 + EB - 1) / EB;

    for (int l = 0; l < NLAYER; l++) {
        int do_next = (l + 1 < NLAYER) ? 1 : 0;

        if (l > 0) {
            gemm_fp16_kernel<<<gemmGrid, 256, SMEM_BYTES>>>(
                pAhV, pAhC, pWhT + (size_t)(4 * l) * HD * HD,
                pXL0, pXL1, pXL2, pXL3);
        }

        gat_all_kernel<<<gatAB, EB>>>(pXL0, pXL1, pXL2, pXL3, bias, l,
                                      pAhV, pAhC, batch_var, batch_con, do_next);
    }

    finalize_kernel<<<GN, 256>>>(W_lin, b_lin, out);
}